// round 10
// baseline (speedup 1.0000x reference)
#include <cuda_runtime.h>
#include <cuda_bf16.h>
#include <cstdint>

#define N_NODES 50000
#define N_EDGES 800000
#define N_GRAPH 500
#define DIM     128
#define EDIM    7
#define LAYERS  5
#define NCLASS  10
#define BN_EPS  1e-5f
#define NROWS_PAD 50048   // NTILES*128

// ---------------- scratch ----------------
__device__ float g_x  [N_NODES * DIM];
__device__ float g_pool[N_GRAPH * DIM];
__device__ float g_gcnt[N_GRAPH];

// bf16 hi/lo planes of (x + agg): edge-kernel output, MLP A input
__device__ __nv_bfloat16 g_Ah[(size_t)NROWS_PAD * DIM];
__device__ __nv_bfloat16 g_Al[(size_t)NROWS_PAD * DIM];

// CSR scratch
__device__ int   g_deg [N_NODES];
__device__ int   g_off [N_NODES + 1];
__device__ int   g_fill[N_NODES];
__device__ int   g_esrc[N_EDGES];
__device__ float g_eattr[(size_t)N_EDGES * 8];   // attr in CSR order (padded to 8)

// transposed + bf16-split weight images, row-major [o][k] (10 mats: l*2 + {W1,W2})
__device__ __nv_bfloat16 g_Wh[10 * 16384];
__device__ __nv_bfloat16 g_Wl[10 * 16384];

// ================= helpers =================
__device__ __forceinline__ uint32_t smem_u32(const void* p) {
    uint32_t a;
    asm("{ .reg .u64 t; cvta.to.shared.u64 t, %1; cvt.u32.u64 %0, t; }" : "=r"(a) : "l"(p));
    return a;
}
__device__ __forceinline__ void ldm4(uint32_t* r, uint32_t addr) {
    asm volatile("ldmatrix.sync.aligned.m8n8.x4.shared.b16 {%0,%1,%2,%3}, [%4];"
                 : "=r"(r[0]), "=r"(r[1]), "=r"(r[2]), "=r"(r[3]) : "r"(addr));
}
__device__ __forceinline__ void mma_bf16(float* c, const uint32_t* a, uint32_t b0, uint32_t b1) {
    asm volatile("mma.sync.aligned.m16n8k16.row.col.f32.bf16.bf16.f32 "
                 "{%0,%1,%2,%3}, {%4,%5,%6,%7}, {%8,%9}, {%0,%1,%2,%3};"
                 : "+f"(c[0]), "+f"(c[1]), "+f"(c[2]), "+f"(c[3])
                 : "r"(a[0]), "r"(a[1]), "r"(a[2]), "r"(a[3]), "r"(b0), "r"(b1));
}
__device__ __forceinline__ void cp16(uint32_t smem_dst, const void* gsrc) {
    asm volatile("cp.async.cg.shared.global [%0], [%1], 16;" :: "r"(smem_dst), "l"(gsrc));
}

// split fp32x4 -> bf16 hi/lo and store 8B to each plane
__device__ __forceinline__ void store_split(__nv_bfloat16* Ah, __nv_bfloat16* Al,
                                            size_t idx, float4 acc) {
    __nv_bfloat162 h01 = __float22bfloat162_rn(make_float2(acc.x, acc.y));
    __nv_bfloat162 h23 = __float22bfloat162_rn(make_float2(acc.z, acc.w));
    float2 f01 = __bfloat1622float2(h01);
    float2 f23 = __bfloat1622float2(h23);
    __nv_bfloat162 l01 = __float22bfloat162_rn(make_float2(acc.x - f01.x, acc.y - f01.y));
    __nv_bfloat162 l23 = __float22bfloat162_rn(make_float2(acc.z - f23.x, acc.w - f23.y));
    uint2 hp = make_uint2(*reinterpret_cast<uint32_t*>(&h01), *reinterpret_cast<uint32_t*>(&h23));
    uint2 lp = make_uint2(*reinterpret_cast<uint32_t*>(&l01), *reinterpret_cast<uint32_t*>(&l23));
    *reinterpret_cast<uint2*>(Ah + idx) = hp;
    *reinterpret_cast<uint2*>(Al + idx) = lp;
}

// ---------------- weight prep: transpose + bf16 hi/lo split ----------------
__global__ void k_prep_w(const float* __restrict__ W1, const float* __restrict__ W2) {
    int idx = blockIdx.x * blockDim.x + threadIdx.x;
    if (idx >= 10 * 16384) return;
    int mat = idx >> 14;
    int r = idx & 16383;
    int o = r >> 7, k = r & 127;
    int l = mat >> 1;
    const float* W = (mat & 1) ? (W2 + l * 16384) : (W1 + l * 16384);
    float x = W[k * 128 + o];
    __nv_bfloat16 h = __float2bfloat16(x);
    __nv_bfloat16 lo = __float2bfloat16(x - __bfloat162float(h));
    g_Wh[mat * 16384 + o * 128 + k] = h;
    g_Wl[mat * 16384 + o * 128 + k] = lo;
}

// ---------------- CSR build ----------------
__global__ void k_hist(const int* __restrict__ ei) {
    int e = blockIdx.x * blockDim.x + threadIdx.x;
    if (e < N_EDGES) atomicAdd(&g_deg[ei[N_EDGES + e]], 1);
}

// single-block scan: 1024 threads, chunked, exclusive prefix of g_deg -> g_off/g_fill
__global__ void __launch_bounds__(1024) k_scan() {
    __shared__ int sw[32];
    __shared__ int sCarry;
    int tid = threadIdx.x, lane = tid & 31, wid = tid >> 5;
    if (tid == 0) sCarry = 0;
    __syncthreads();
    for (int base = 0; base < N_NODES; base += 1024) {
        int i = base + tid;
        int v = (i < N_NODES) ? g_deg[i] : 0;
        int x = v;
#pragma unroll
        for (int d = 1; d < 32; d <<= 1) {
            int t = __shfl_up_sync(0xffffffffu, x, d);
            if (lane >= d) x += t;
        }
        if (lane == 31) sw[wid] = x;
        __syncthreads();
        if (wid == 0) {
            int y = sw[lane];
#pragma unroll
            for (int d = 1; d < 32; d <<= 1) {
                int t = __shfl_up_sync(0xffffffffu, y, d);
                if (lane >= d) y += t;
            }
            sw[lane] = y;
        }
        __syncthreads();
        int carry = sCarry;
        int excl = carry + (wid ? sw[wid - 1] : 0) + x - v;
        if (i < N_NODES) { g_off[i] = excl; g_fill[i] = excl; }
        if (i == N_NODES - 1) g_off[N_NODES] = excl + v;
        __syncthreads();
        if (tid == 0) sCarry = carry + sw[31];
        __syncthreads();
    }
}

__global__ void k_scatter(const int* __restrict__ ei, const float* __restrict__ attr) {
    int e = blockIdx.x * blockDim.x + threadIdx.x;
    if (e < N_EDGES) {
        int dst = ei[N_EDGES + e];
        int p = atomicAdd(&g_fill[dst], 1);
        g_esrc[p] = ei[e];
        float* d = g_eattr + (size_t)p * 8;
#pragma unroll
        for (int i = 0; i < 7; i++) d[i] = attr[e * 7 + i];
    }
}

// ---------------- edge aggregation, 4-way pipelined (layers 1..4) ----------------
// writes (x[dst] + sum msg) as bf16 hi/lo planes
__global__ void __launch_bounds__(256) k_edge_csr(
    const float* __restrict__ eW, const float* __restrict__ eb)
{
    __shared__ float4 sW[EDIM * 32];
    __shared__ float4 sB[32];
    int tid = threadIdx.x;
    if (tid < EDIM * 32) sW[tid] = reinterpret_cast<const float4*>(eW)[tid];
    if (tid < 32)        sB[tid] = reinterpret_cast<const float4*>(eb)[tid];
    __syncthreads();

    int warp = tid >> 5, lane = tid & 31;
    int dst = blockIdx.x * 8 + warp;
    if (dst >= N_NODES) return;

    const float4* X4 = reinterpret_cast<const float4*>(g_x);
    float4 acc = X4[(size_t)dst * 32 + lane];
    float4 b = sB[lane];
    int j = g_off[dst], end = g_off[dst + 1];

    for (; j + 4 <= end; j += 4) {
        float av = g_eattr[(size_t)j * 8 + lane];   // 4 edges x 8 attrs, coalesced
        int s0 = g_esrc[j + 0], s1 = g_esrc[j + 1];
        int s2 = g_esrc[j + 2], s3 = g_esrc[j + 3];
        float4 x0 = X4[(size_t)s0 * 32 + lane];
        float4 x1 = X4[(size_t)s1 * 32 + lane];
        float4 x2 = X4[(size_t)s2 * 32 + lane];
        float4 x3 = X4[(size_t)s3 * 32 + lane];
        float4 e0 = b, e1 = b, e2 = b, e3 = b;
#pragma unroll
        for (int q = 0; q < EDIM; q++) {
            float4 w = sW[q * 32 + lane];
            float a0 = __shfl_sync(0xffffffffu, av, q);
            float a1 = __shfl_sync(0xffffffffu, av, 8 + q);
            float a2 = __shfl_sync(0xffffffffu, av, 16 + q);
            float a3 = __shfl_sync(0xffffffffu, av, 24 + q);
            e0.x += a0 * w.x; e0.y += a0 * w.y; e0.z += a0 * w.z; e0.w += a0 * w.w;
            e1.x += a1 * w.x; e1.y += a1 * w.y; e1.z += a1 * w.z; e1.w += a1 * w.w;
            e2.x += a2 * w.x; e2.y += a2 * w.y; e2.z += a2 * w.z; e2.w += a2 * w.w;
            e3.x += a3 * w.x; e3.y += a3 * w.y; e3.z += a3 * w.z; e3.w += a3 * w.w;
        }
        acc.x += fmaxf(x0.x + e0.x, 0.f) + fmaxf(x1.x + e1.x, 0.f)
               + fmaxf(x2.x + e2.x, 0.f) + fmaxf(x3.x + e3.x, 0.f);
        acc.y += fmaxf(x0.y + e0.y, 0.f) + fmaxf(x1.y + e1.y, 0.f)
               + fmaxf(x2.y + e2.y, 0.f) + fmaxf(x3.y + e3.y, 0.f);
        acc.z += fmaxf(x0.z + e0.z, 0.f) + fmaxf(x1.z + e1.z, 0.f)
               + fmaxf(x2.z + e2.z, 0.f) + fmaxf(x3.z + e3.z, 0.f);
        acc.w += fmaxf(x0.w + e0.w, 0.f) + fmaxf(x1.w + e1.w, 0.f)
               + fmaxf(x2.w + e2.w, 0.f) + fmaxf(x3.w + e3.w, 0.f);
    }
    for (; j < end; j++) {
        int src = g_esrc[j];
        float v = (lane < EDIM) ? g_eattr[(size_t)j * 8 + lane] : 0.0f;
        float4 e = b;
#pragma unroll
        for (int q = 0; q < EDIM; q++) {
            float a = __shfl_sync(0xffffffffu, v, q);
            float4 w = sW[q * 32 + lane];
            e.x += a * w.x; e.y += a * w.y; e.z += a * w.z; e.w += a * w.w;
        }
        float4 xv = X4[(size_t)src * 32 + lane];
        acc.x += fmaxf(xv.x + e.x, 0.0f);
        acc.y += fmaxf(xv.y + e.y, 0.0f);
        acc.z += fmaxf(xv.z + e.z, 0.0f);
        acc.w += fmaxf(xv.w + e.w, 0.0f);
    }
    store_split(g_Ah, g_Al, (size_t)dst * 128 + lane * 4, acc);
}

// ---------------- layer-0 edge: x[src] == node_emb for all nodes (no gather) ----------------
__global__ void __launch_bounds__(256) k_edge_l0(
    const float* __restrict__ node_emb,
    const float* __restrict__ eW, const float* __restrict__ eb)
{
    __shared__ float4 sW[EDIM * 32];
    __shared__ float4 sB[32];
    __shared__ float4 sE[32];
    int tid = threadIdx.x;
    if (tid < EDIM * 32) sW[tid] = reinterpret_cast<const float4*>(eW)[tid];
    if (tid < 32)        sB[tid] = reinterpret_cast<const float4*>(eb)[tid];
    if (tid >= 32 && tid < 64)
        sE[tid - 32] = reinterpret_cast<const float4*>(node_emb)[tid - 32];
    __syncthreads();

    int warp = tid >> 5, lane = tid & 31;
    int dst = blockIdx.x * 8 + warp;
    if (dst >= N_NODES) return;

    float4 em = sE[lane];
    float4 acc = em;
    float4 b = sB[lane];
    b.x += em.x; b.y += em.y; b.z += em.z; b.w += em.w;
    int j = g_off[dst], end = g_off[dst + 1];

    for (; j + 4 <= end; j += 4) {
        float av = g_eattr[(size_t)j * 8 + lane];
        float4 e0 = b, e1 = b, e2 = b, e3 = b;
#pragma unroll
        for (int q = 0; q < EDIM; q++) {
            float4 w = sW[q * 32 + lane];
            float a0 = __shfl_sync(0xffffffffu, av, q);
            float a1 = __shfl_sync(0xffffffffu, av, 8 + q);
            float a2 = __shfl_sync(0xffffffffu, av, 16 + q);
            float a3 = __shfl_sync(0xffffffffu, av, 24 + q);
            e0.x += a0 * w.x; e0.y += a0 * w.y; e0.z += a0 * w.z; e0.w += a0 * w.w;
            e1.x += a1 * w.x; e1.y += a1 * w.y; e1.z += a1 * w.z; e1.w += a1 * w.w;
            e2.x += a2 * w.x; e2.y += a2 * w.y; e2.z += a2 * w.z; e2.w += a2 * w.w;
            e3.x += a3 * w.x; e3.y += a3 * w.y; e3.z += a3 * w.z; e3.w += a3 * w.w;
        }
        acc.x += fmaxf(e0.x, 0.f) + fmaxf(e1.x, 0.f) + fmaxf(e2.x, 0.f) + fmaxf(e3.x, 0.f);
        acc.y += fmaxf(e0.y, 0.f) + fmaxf(e1.y, 0.f) + fmaxf(e2.y, 0.f) + fmaxf(e3.y, 0.f);
        acc.z += fmaxf(e0.z, 0.f) + fmaxf(e1.z, 0.f) + fmaxf(e2.z, 0.f) + fmaxf(e3.z, 0.f);
        acc.w += fmaxf(e0.w, 0.f) + fmaxf(e1.w, 0.f) + fmaxf(e2.w, 0.f) + fmaxf(e3.w, 0.f);
    }
    for (; j < end; j++) {
        float v = (lane < EDIM) ? g_eattr[(size_t)j * 8 + lane] : 0.0f;
        float4 e = b;
#pragma unroll
        for (int q = 0; q < EDIM; q++) {
            float a = __shfl_sync(0xffffffffu, v, q);
            float4 w = sW[q * 32 + lane];
            e.x += a * w.x; e.y += a * w.y; e.z += a * w.z; e.w += a * w.w;
        }
        acc.x += fmaxf(e.x, 0.0f);
        acc.y += fmaxf(e.y, 0.0f);
        acc.z += fmaxf(e.z, 0.0f);
        acc.w += fmaxf(e.w, 0.0f);
    }
    store_split(g_Ah, g_Al, (size_t)dst * 128 + lane * 4, acc);
}

// ---------------- fused per-layer MLP ----------------
#define PAD 136
#define WIMG (128 * PAD)
#define FUSED_SMEM (6 * WIMG * 2 + 2048)

__device__ __forceinline__ void gemm_128(float (&acc)[2][8][4],
    uint32_t adrAh, uint32_t adrAl, uint32_t adrBh, uint32_t adrBl)
{
#pragma unroll
    for (int mt = 0; mt < 2; mt++)
#pragma unroll
        for (int nt = 0; nt < 8; nt++)
#pragma unroll
            for (int q = 0; q < 4; q++) acc[mt][nt][q] = 0.0f;

#pragma unroll
    for (int ks = 0; ks < 8; ks++) {
        uint32_t k2 = ks * 32;
        uint32_t ah[2][4], al[2][4], bh[4][4], bl[4][4];
        ldm4(ah[0], adrAh + k2);
        ldm4(ah[1], adrAh + 16 * PAD * 2 + k2);
        ldm4(al[0], adrAl + k2);
        ldm4(al[1], adrAl + 16 * PAD * 2 + k2);
#pragma unroll
        for (int p = 0; p < 4; p++) {
            ldm4(bh[p], adrBh + p * 16 * PAD * 2 + k2);
            ldm4(bl[p], adrBl + p * 16 * PAD * 2 + k2);
        }
#pragma unroll
        for (int mt = 0; mt < 2; mt++)
#pragma unroll
            for (int nt = 0; nt < 8; nt++) {
                int p = nt >> 1, q = nt & 1;
                mma_bf16(acc[mt][nt], ah[mt], bh[p][q], bh[p][q + 2]);
                mma_bf16(acc[mt][nt], al[mt], bh[p][q], bh[p][q + 2]);
                mma_bf16(acc[mt][nt], ah[mt], bl[p][q], bl[p][q + 2]);
            }
    }
}

__global__ void __launch_bounds__(256, 1) k_mlp_fused(
    const __nv_bfloat16* __restrict__ Ah, const __nv_bfloat16* __restrict__ Al,
    float* __restrict__ out,
    const __nv_bfloat16* __restrict__ W1h, const __nv_bfloat16* __restrict__ W1l,
    const __nv_bfloat16* __restrict__ W2h, const __nv_bfloat16* __restrict__ W2l,
    const float* __restrict__ b1,
    const float* __restrict__ g1, const float* __restrict__ bb1,
    const float* __restrict__ m1, const float* __restrict__ v1,
    const float* __restrict__ b2,
    const float* __restrict__ g2, const float* __restrict__ bb2,
    const float* __restrict__ m2, const float* __restrict__ v2)
{
    extern __shared__ char sm[];
    __nv_bfloat16* sW1h = reinterpret_cast<__nv_bfloat16*>(sm);
    __nv_bfloat16* sW1l = sW1h + WIMG;
    __nv_bfloat16* sW2h = sW1l + WIMG;
    __nv_bfloat16* sW2l = sW2h + WIMG;
    __nv_bfloat16* sAh  = sW2l + WIMG;
    __nv_bfloat16* sAl  = sAh + WIMG;
    float* S1 = reinterpret_cast<float*>(sAl + WIMG);
    float* T1 = S1 + 128;
    float* S2 = T1 + 128;
    float* T2 = S2 + 128;

    int tid = threadIdx.x, wid = tid >> 5, lane = tid & 31;

    for (int i = tid; i < 2048; i += 256) {
        int o = i >> 4, kc = (i & 15) * 8;
        *reinterpret_cast<uint4*>(sW1h + o * PAD + kc) = reinterpret_cast<const uint4*>(W1h)[i];
        *reinterpret_cast<uint4*>(sW1l + o * PAD + kc) = reinterpret_cast<const uint4*>(W1l)[i];
        *reinterpret_cast<uint4*>(sW2h + o * PAD + kc) = reinterpret_cast<const uint4*>(W2h)[i];
        *reinterpret_cast<uint4*>(sW2l + o * PAD + kc) = reinterpret_cast<const uint4*>(W2l)[i];
    }
    if (tid < 128) {
        float s1 = g1[tid] * rsqrtf(v1[tid] + BN_EPS);
        S1[tid] = s1;
        T1[tid] = (b1[tid] - m1[tid]) * s1 + bb1[tid];
        float s2 = g2[tid] * rsqrtf(v2[tid] + BN_EPS);
        S2[tid] = s2;
        T2[tid] = (b2[tid] - m2[tid]) * s2 + bb2[tid];
    }

    int wm = wid & 3, wn = wid >> 2;
    uint32_t aOff = ((uint32_t)(wm * 32 + (lane & 15)) * PAD + (lane >> 4) * 8) * 2;
    uint32_t bOff = ((uint32_t)(wn * 64 + (lane & 7) + ((lane >> 3) & 1) * 8) * PAD + (lane >> 4) * 8) * 2;
    uint32_t adrAh  = smem_u32(sAh)  + aOff;
    uint32_t adrAl  = smem_u32(sAl)  + aOff;
    uint32_t adrB1h = smem_u32(sW1h) + bOff;
    uint32_t adrB1l = smem_u32(sW1l) + bOff;
    uint32_t adrB2h = smem_u32(sW2h) + bOff;
    uint32_t adrB2l = smem_u32(sW2l) + bOff;

    uint32_t sAh_u = smem_u32(sAh);
    uint32_t sAl_u = smem_u32(sAl);

    const int NTILES = (N_NODES + 127) / 128;   // 391

    for (int t = blockIdx.x; t < NTILES; t += gridDim.x) {
        int base = t * 128;
        __syncthreads();   // everyone done with previous tile's sA

        // ---- A: cp.async relayout of bf16 planes into padded smem ----
        // rows >= N_NODES carry garbage; their outputs are discarded at the store.
        for (int i = tid; i < 2048; i += 256) {
            int row = i >> 4, seg = (i & 15) * 8;
            uint32_t d = (uint32_t)((row * PAD + seg) * 2);
            size_t s = (size_t)(base + row) * 128 + seg;
            cp16(sAh_u + d, Ah + s);
            cp16(sAl_u + d, Al + s);
        }
        asm volatile("cp.async.commit_group;" ::: "memory");
        asm volatile("cp.async.wait_group 0;" ::: "memory");
        __syncthreads();

        // ---- GEMM1 ----
        float acc[2][8][4];
        gemm_128(acc, adrAh, adrAl, adrB1h, adrB1l);
        __syncthreads();   // all warps done reading sA

        // ---- epilogue1: BN1 + ReLU -> bf16 split back into sA ----
#pragma unroll
        for (int mt = 0; mt < 2; mt++) {
            int r0 = wm * 32 + mt * 16 + (lane >> 2);
#pragma unroll
            for (int nt = 0; nt < 8; nt++) {
                int col = wn * 64 + nt * 8 + (lane & 3) * 2;
                float Sa = S1[col], Sb2 = S1[col + 1];
                float Ta = T1[col], Tb = T1[col + 1];
                float y0 = fmaxf(acc[mt][nt][0] * Sa + Ta, 0.0f);
                float y1 = fmaxf(acc[mt][nt][1] * Sb2 + Tb, 0.0f);
                float y2 = fmaxf(acc[mt][nt][2] * Sa + Ta, 0.0f);
                float y3 = fmaxf(acc[mt][nt][3] * Sb2 + Tb, 0.0f);
                __nv_bfloat162 h0 = __float22bfloat162_rn(make_float2(y0, y1));
                __nv_bfloat162 h1 = __float22bfloat162_rn(make_float2(y2, y3));
                float2 f0 = __bfloat1622float2(h0);
                float2 f1 = __bfloat1622float2(h1);
                __nv_bfloat162 l0 = __float22bfloat162_rn(make_float2(y0 - f0.x, y1 - f0.y));
                __nv_bfloat162 l1 = __float22bfloat162_rn(make_float2(y2 - f1.x, y3 - f1.y));
                *reinterpret_cast<uint32_t*>(sAh + r0 * PAD + col) = *reinterpret_cast<uint32_t*>(&h0);
                *reinterpret_cast<uint32_t*>(sAl + r0 * PAD + col) = *reinterpret_cast<uint32_t*>(&l0);
                *reinterpret_cast<uint32_t*>(sAh + (r0 + 8) * PAD + col) = *reinterpret_cast<uint32_t*>(&h1);
                *reinterpret_cast<uint32_t*>(sAl + (r0 + 8) * PAD + col) = *reinterpret_cast<uint32_t*>(&l1);
            }
        }
        __syncthreads();

        // ---- GEMM2 ----
        gemm_128(acc, adrAh, adrAl, adrB2h, adrB2l);

        // ---- epilogue2: BN2 + ReLU -> global fp32 x ----
#pragma unroll
        for (int mt = 0; mt < 2; mt++) {
            int r0 = base + wm * 32 + mt * 16 + (lane >> 2);
#pragma unroll
            for (int nt = 0; nt < 8; nt++) {
                int col = wn * 64 + nt * 8 + (lane & 3) * 2;
                float Sa = S2[col], Sb2 = S2[col + 1];
                float Ta = T2[col], Tb = T2[col + 1];
                if (r0 < N_NODES) {
                    float2 v;
                    v.x = fmaxf(acc[mt][nt][0] * Sa + Ta, 0.0f);
                    v.y = fmaxf(acc[mt][nt][1] * Sb2 + Tb, 0.0f);
                    *reinterpret_cast<float2*>(out + (size_t)r0 * 128 + col) = v;
                }
                if (r0 + 8 < N_NODES) {
                    float2 v;
                    v.x = fmaxf(acc[mt][nt][2] * Sa + Ta, 0.0f);
                    v.y = fmaxf(acc[mt][nt][3] * Sb2 + Tb, 0.0f);
                    *reinterpret_cast<float2*>(out + (size_t)(r0 + 8) * 128 + col) = v;
                }
            }
        }
    }
}

// ---------------- pooling ----------------
__global__ void k_pool(const int* __restrict__ batch) {
    int gw = (blockIdx.x * blockDim.x + threadIdx.x) >> 5;
    int lane = threadIdx.x & 31;
    if (gw >= N_NODES) return;
    int c = batch[gw];
    float4 v = reinterpret_cast<const float4*>(g_x)[(size_t)gw * 32 + lane];
    atomicAdd(reinterpret_cast<float4*>(g_pool) + c * 32 + lane, v);
    if (lane == 0) atomicAdd(&g_gcnt[c], 1.0f);
}

// ---------------- head ----------------
__global__ void k_head(const float* __restrict__ W1, const float* __restrict__ b1,
                       const float* __restrict__ W2, const float* __restrict__ b2,
                       float* __restrict__ out)
{
    __shared__ float sg[DIM];
    __shared__ float sh[DIM];
    int c = blockIdx.x;
    int t = threadIdx.x;
    float cnt = fmaxf(g_gcnt[c], 1.0f);
    sg[t] = g_pool[c * DIM + t] / cnt;
    __syncthreads();
    float acc = b1[t];
#pragma unroll 8
    for (int k = 0; k < DIM; k++) acc += sg[k] * W1[k * DIM + t];
    sh[t] = fmaxf(acc, 0.0f);
    __syncthreads();
    if (t < NCLASS) {
        float o2 = b2[t];
#pragma unroll 8
        for (int k = 0; k < DIM; k++) o2 += sh[k] * W2[k * NCLASS + t];
        out[c * NCLASS + t] = o2;
    }
}

// ---------------- launch ----------------
extern "C" void kernel_launch(void* const* d_in, const int* in_sizes, int n_in,
                              void* d_out, int out_size)
{
    const float* edge_attr = (const float*)d_in[0];
    const int*   edge_index= (const int*)  d_in[1];
    const int*   batch     = (const int*)  d_in[2];
    const float* node_emb  = (const float*)d_in[3];
    const float* edge_W    = (const float*)d_in[4];
    const float* edge_b    = (const float*)d_in[5];
    const float* mlp_W1    = (const float*)d_in[6];
    const float* mlp_b1    = (const float*)d_in[7];
    const float* bn1_g     = (const float*)d_in[8];
    const float* bn1_b     = (const float*)d_in[9];
    const float* bn1_m     = (const float*)d_in[10];
    const float* bn1_v     = (const float*)d_in[11];
    const float* mlp_W2    = (const float*)d_in[12];
    const float* mlp_b2    = (const float*)d_in[13];
    const float* bn2_g     = (const float*)d_in[14];
    const float* bn2_b     = (const float*)d_in[15];
    const float* bn2_m     = (const float*)d_in[16];
    const float* bn2_v     = (const float*)d_in[17];
    const float* head_W1   = (const float*)d_in[18];
    const float* head_b1   = (const float*)d_in[19];
    const float* head_W2   = (const float*)d_in[20];
    const float* head_b2   = (const float*)d_in[21];
    float* out = (float*)d_out;

    cudaFuncSetAttribute(k_mlp_fused, cudaFuncAttributeMaxDynamicSharedMemorySize, FUSED_SMEM);

    float *px, *ppool, *pgcnt;
    int *pdeg;
    __nv_bfloat16 *pwh, *pwl, *pah, *pal;
    cudaGetSymbolAddress((void**)&px,    g_x);
    cudaGetSymbolAddress((void**)&ppool, g_pool);
    cudaGetSymbolAddress((void**)&pgcnt, g_gcnt);
    cudaGetSymbolAddress((void**)&pdeg,  g_deg);
    cudaGetSymbolAddress((void**)&pwh,   g_Wh);
    cudaGetSymbolAddress((void**)&pwl,   g_Wl);
    cudaGetSymbolAddress((void**)&pah,   g_Ah);
    cudaGetSymbolAddress((void**)&pal,   g_Al);

    // zeroing via async memsets (graph-capturable)
    cudaMemsetAsync(pdeg,  0, N_NODES * sizeof(int));
    cudaMemsetAsync(ppool, 0, N_GRAPH * DIM * sizeof(float));
    cudaMemsetAsync(pgcnt, 0, N_GRAPH * sizeof(float));

    // weight prep + CSR build (deterministic each replay)
    k_prep_w<<<(10 * 16384 + 255) / 256, 256>>>(mlp_W1, mlp_W2);
    k_hist<<<(N_EDGES + 255) / 256, 256>>>(edge_index);
    k_scan<<<1, 1024>>>();
    k_scatter<<<(N_EDGES + 255) / 256, 256>>>(edge_index, edge_attr);

    const int TC_GRID = 148;
    for (int l = 0; l < LAYERS; l++) {
        if (l == 0)
            k_edge_l0<<<(N_NODES + 7) / 8, 256>>>(node_emb, edge_W, edge_b);
        else
            k_edge_csr<<<(N_NODES + 7) / 8, 256>>>(edge_W + l * EDIM * DIM, edge_b + l * DIM);
        int m1 = l * 2, m2 = l * 2 + 1;
        k_mlp_fused<<<TC_GRID, 256, FUSED_SMEM>>>(
            pah, pal, px,
            pwh + m1 * 16384, pwl + m1 * 16384,
            pwh + m2 * 16384, pwl + m2 * 16384,
            mlp_b1 + l * DIM, bn1_g + l * DIM, bn1_b + l * DIM, bn1_m + l * DIM, bn1_v + l * DIM,
            mlp_b2 + l * DIM, bn2_g + l * DIM, bn2_b + l * DIM, bn2_m + l * DIM, bn2_v + l * DIM);
    }

    k_pool<<<(N_NODES * 32 + 255) / 256, 256>>>(batch);
    k_head<<<N_GRAPH, DIM>>>(head_W1, head_b1, head_W2, head_b2, out);
}

// round 13
// speedup vs baseline: 1.0721x; 1.0721x over previous
#include <cuda_runtime.h>
#include <cuda_bf16.h>
#include <cstdint>

#define N_NODES 50000
#define N_EDGES 800000
#define N_GRAPH 500
#define DIM     128
#define EDIM    7
#define LAYERS  5
#define NCLASS  10
#define BN_EPS  1e-5f
#define NROWS_PAD 50048   // NTILES*128

// ---------------- scratch ----------------
__device__ float g_x  [N_NODES * DIM];
__device__ float g_pool[N_GRAPH * DIM];
__device__ float g_gcnt[N_GRAPH];

// bf16 hi/lo planes of (x + agg): edge-kernel output, MLP A input
__device__ __nv_bfloat16 g_Ah[(size_t)NROWS_PAD * DIM];
__device__ __nv_bfloat16 g_Al[(size_t)NROWS_PAD * DIM];

// CSR scratch
__device__ int   g_deg [N_NODES];
__device__ int   g_off [N_NODES + 1];
__device__ int   g_bsum[256];
__device__ int   g_fill[N_NODES];
__device__ int   g_eid [N_EDGES];
__device__ int   g_esrc[N_EDGES];
__device__ float g_eattr[(size_t)N_EDGES * 8];   // attr in CSR order (padded to 8)

// transposed + bf16-split weight images, row-major [o][k] (10 mats: l*2 + {W1,W2})
__device__ __nv_bfloat16 g_Wh[10 * 16384];
__device__ __nv_bfloat16 g_Wl[10 * 16384];

// ================= helpers =================
__device__ __forceinline__ uint32_t smem_u32(const void* p) {
    uint32_t a;
    asm("{ .reg .u64 t; cvta.to.shared.u64 t, %1; cvt.u32.u64 %0, t; }" : "=r"(a) : "l"(p));
    return a;
}
__device__ __forceinline__ void ldm4(uint32_t* r, uint32_t addr) {
    asm volatile("ldmatrix.sync.aligned.m8n8.x4.shared.b16 {%0,%1,%2,%3}, [%4];"
                 : "=r"(r[0]), "=r"(r[1]), "=r"(r[2]), "=r"(r[3]) : "r"(addr));
}
__device__ __forceinline__ void mma_bf16(float* c, const uint32_t* a, uint32_t b0, uint32_t b1) {
    asm volatile("mma.sync.aligned.m16n8k16.row.col.f32.bf16.bf16.f32 "
                 "{%0,%1,%2,%3}, {%4,%5,%6,%7}, {%8,%9}, {%0,%1,%2,%3};"
                 : "+f"(c[0]), "+f"(c[1]), "+f"(c[2]), "+f"(c[3])
                 : "r"(a[0]), "r"(a[1]), "r"(a[2]), "r"(a[3]), "r"(b0), "r"(b1));
}
__device__ __forceinline__ void cp16(uint32_t smem_dst, const void* gsrc) {
    asm volatile("cp.async.cg.shared.global [%0], [%1], 16;" :: "r"(smem_dst), "l"(gsrc));
}

// split fp32x4 -> bf16 hi/lo and store 8B to each plane
__device__ __forceinline__ void store_split(__nv_bfloat16* Ah, __nv_bfloat16* Al,
                                            size_t idx, float4 acc) {
    __nv_bfloat162 h01 = __float22bfloat162_rn(make_float2(acc.x, acc.y));
    __nv_bfloat162 h23 = __float22bfloat162_rn(make_float2(acc.z, acc.w));
    float2 f01 = __bfloat1622float2(h01);
    float2 f23 = __bfloat1622float2(h23);
    __nv_bfloat162 l01 = __float22bfloat162_rn(make_float2(acc.x - f01.x, acc.y - f01.y));
    __nv_bfloat162 l23 = __float22bfloat162_rn(make_float2(acc.z - f23.x, acc.w - f23.y));
    uint2 hp = make_uint2(*reinterpret_cast<uint32_t*>(&h01), *reinterpret_cast<uint32_t*>(&h23));
    uint2 lp = make_uint2(*reinterpret_cast<uint32_t*>(&l01), *reinterpret_cast<uint32_t*>(&l23));
    *reinterpret_cast<uint2*>(Ah + idx) = hp;
    *reinterpret_cast<uint2*>(Al + idx) = lp;
}

// ---------------- weight prep: transpose + bf16 hi/lo split ----------------
__global__ void k_prep_w(const float* __restrict__ W1, const float* __restrict__ W2) {
    int idx = blockIdx.x * blockDim.x + threadIdx.x;
    if (idx >= 10 * 16384) return;
    int mat = idx >> 14;
    int r = idx & 16383;
    int o = r >> 7, k = r & 127;
    int l = mat >> 1;
    const float* W = (mat & 1) ? (W2 + l * 16384) : (W1 + l * 16384);
    float x = W[k * 128 + o];
    __nv_bfloat16 h = __float2bfloat16(x);
    __nv_bfloat16 lo = __float2bfloat16(x - __bfloat162float(h));
    g_Wh[mat * 16384 + o * 128 + k] = h;
    g_Wl[mat * 16384 + o * 128 + k] = lo;
}

// ---------------- CSR build ----------------
__global__ void k_hist(const int* __restrict__ ei) {
    int e = blockIdx.x * blockDim.x + threadIdx.x;
    if (e < N_EDGES) atomicAdd(&g_deg[ei[N_EDGES + e]], 1);
}
#define SCAN_BLOCKS ((N_NODES + 255) / 256)   // 196
__global__ void k_blocksum() {
    __shared__ int s[256];
    int i = blockIdx.x * 256 + threadIdx.x;
    s[threadIdx.x] = (i < N_NODES) ? g_deg[i] : 0;
    __syncthreads();
    for (int d = 128; d > 0; d >>= 1) {
        if (threadIdx.x < d) s[threadIdx.x] += s[threadIdx.x + d];
        __syncthreads();
    }
    if (threadIdx.x == 0) g_bsum[blockIdx.x] = s[0];
}
__global__ void k_scan_bsum() {
    __shared__ int s[256];
    int v = (threadIdx.x < SCAN_BLOCKS) ? g_bsum[threadIdx.x] : 0;
    s[threadIdx.x] = v;
    __syncthreads();
    for (int d = 1; d < 256; d <<= 1) {
        int t = (threadIdx.x >= d) ? s[threadIdx.x - d] : 0;
        __syncthreads();
        s[threadIdx.x] += t;
        __syncthreads();
    }
    if (threadIdx.x < SCAN_BLOCKS) g_bsum[threadIdx.x] = s[threadIdx.x] - v;  // exclusive
}
__global__ void k_scan_final() {
    __shared__ int s[256];
    int i = blockIdx.x * 256 + threadIdx.x;
    int v = (i < N_NODES) ? g_deg[i] : 0;
    s[threadIdx.x] = v;
    __syncthreads();
    for (int d = 1; d < 256; d <<= 1) {
        int t = (threadIdx.x >= d) ? s[threadIdx.x - d] : 0;
        __syncthreads();
        s[threadIdx.x] += t;
        __syncthreads();
    }
    int excl = s[threadIdx.x] - v + g_bsum[blockIdx.x];
    if (i < N_NODES) { g_off[i] = excl; g_fill[i] = excl; }
    if (i == N_NODES - 1) g_off[N_NODES] = excl + v;
}

// phase 1: atomic slot assignment, single 4B random store
__global__ void k_scatter_idx(const int* __restrict__ ei) {
    int e = blockIdx.x * blockDim.x + threadIdx.x;
    if (e < N_EDGES) {
        int dst = ei[N_EDGES + e];
        int p = atomicAdd(&g_fill[dst], 1);
        g_eid[p] = e;
    }
}
// phase 2: coalesced CSR-order writes; random reads served from L2
__global__ void k_gather_attr(const int* __restrict__ ei, const float* __restrict__ attr) {
    int j = blockIdx.x * blockDim.x + threadIdx.x;
    if (j >= N_EDGES) return;
    int e = g_eid[j];                       // coalesced read
    g_esrc[j] = ei[e];                      // random 4B read, coalesced write
    const float* a = attr + (size_t)e * 7;  // random 28B read (L2)
    float4 v0 = make_float4(a[0], a[1], a[2], a[3]);
    float4 v1 = make_float4(a[4], a[5], a[6], 0.0f);
    float4* d = reinterpret_cast<float4*>(g_eattr + (size_t)j * 8);
    d[0] = v0;                              // coalesced 32B write
    d[1] = v1;
}

// ---------------- edge aggregation, 4-way pipelined (layers 1..4) ----------------
// writes (x[dst] + sum msg) as bf16 hi/lo planes
__global__ void __launch_bounds__(256) k_edge_csr(
    const float* __restrict__ eW, const float* __restrict__ eb)
{
    __shared__ float4 sW[EDIM * 32];
    __shared__ float4 sB[32];
    int tid = threadIdx.x;
    if (tid < EDIM * 32) sW[tid] = reinterpret_cast<const float4*>(eW)[tid];
    if (tid < 32)        sB[tid] = reinterpret_cast<const float4*>(eb)[tid];
    __syncthreads();

    int warp = tid >> 5, lane = tid & 31;
    int dst = blockIdx.x * 8 + warp;
    if (dst >= N_NODES) return;

    const float4* X4 = reinterpret_cast<const float4*>(g_x);
    float4 acc = X4[(size_t)dst * 32 + lane];
    float4 b = sB[lane];
    int j = g_off[dst], end = g_off[dst + 1];

    for (; j + 4 <= end; j += 4) {
        float av = g_eattr[(size_t)j * 8 + lane];   // 4 edges x 8 attrs, coalesced
        int s0 = g_esrc[j + 0], s1 = g_esrc[j + 1];
        int s2 = g_esrc[j + 2], s3 = g_esrc[j + 3];
        float4 x0 = X4[(size_t)s0 * 32 + lane];
        float4 x1 = X4[(size_t)s1 * 32 + lane];
        float4 x2 = X4[(size_t)s2 * 32 + lane];
        float4 x3 = X4[(size_t)s3 * 32 + lane];
        float4 e0 = b, e1 = b, e2 = b, e3 = b;
#pragma unroll
        for (int q = 0; q < EDIM; q++) {
            float4 w = sW[q * 32 + lane];
            float a0 = __shfl_sync(0xffffffffu, av, q);
            float a1 = __shfl_sync(0xffffffffu, av, 8 + q);
            float a2 = __shfl_sync(0xffffffffu, av, 16 + q);
            float a3 = __shfl_sync(0xffffffffu, av, 24 + q);
            e0.x += a0 * w.x; e0.y += a0 * w.y; e0.z += a0 * w.z; e0.w += a0 * w.w;
            e1.x += a1 * w.x; e1.y += a1 * w.y; e1.z += a1 * w.z; e1.w += a1 * w.w;
            e2.x += a2 * w.x; e2.y += a2 * w.y; e2.z += a2 * w.z; e2.w += a2 * w.w;
            e3.x += a3 * w.x; e3.y += a3 * w.y; e3.z += a3 * w.z; e3.w += a3 * w.w;
        }
        acc.x += fmaxf(x0.x + e0.x, 0.f) + fmaxf(x1.x + e1.x, 0.f)
               + fmaxf(x2.x + e2.x, 0.f) + fmaxf(x3.x + e3.x, 0.f);
        acc.y += fmaxf(x0.y + e0.y, 0.f) + fmaxf(x1.y + e1.y, 0.f)
               + fmaxf(x2.y + e2.y, 0.f) + fmaxf(x3.y + e3.y, 0.f);
        acc.z += fmaxf(x0.z + e0.z, 0.f) + fmaxf(x1.z + e1.z, 0.f)
               + fmaxf(x2.z + e2.z, 0.f) + fmaxf(x3.z + e3.z, 0.f);
        acc.w += fmaxf(x0.w + e0.w, 0.f) + fmaxf(x1.w + e1.w, 0.f)
               + fmaxf(x2.w + e2.w, 0.f) + fmaxf(x3.w + e3.w, 0.f);
    }
    for (; j < end; j++) {
        int src = g_esrc[j];
        float v = (lane < EDIM) ? g_eattr[(size_t)j * 8 + lane] : 0.0f;
        float4 e = b;
#pragma unroll
        for (int q = 0; q < EDIM; q++) {
            float a = __shfl_sync(0xffffffffu, v, q);
            float4 w = sW[q * 32 + lane];
            e.x += a * w.x; e.y += a * w.y; e.z += a * w.z; e.w += a * w.w;
        }
        float4 xv = X4[(size_t)src * 32 + lane];
        acc.x += fmaxf(xv.x + e.x, 0.0f);
        acc.y += fmaxf(xv.y + e.y, 0.0f);
        acc.z += fmaxf(xv.z + e.z, 0.0f);
        acc.w += fmaxf(xv.w + e.w, 0.0f);
    }
    store_split(g_Ah, g_Al, (size_t)dst * 128 + lane * 4, acc);
}

// ---------------- layer-0 edge: x[src] == node_emb for all nodes (no gather) ----------------
__global__ void __launch_bounds__(256) k_edge_l0(
    const float* __restrict__ node_emb,
    const float* __restrict__ eW, const float* __restrict__ eb)
{
    __shared__ float4 sW[EDIM * 32];
    __shared__ float4 sB[32];
    __shared__ float4 sE[32];
    int tid = threadIdx.x;
    if (tid < EDIM * 32) sW[tid] = reinterpret_cast<const float4*>(eW)[tid];
    if (tid < 32)        sB[tid] = reinterpret_cast<const float4*>(eb)[tid];
    if (tid >= 32 && tid < 64)
        sE[tid - 32] = reinterpret_cast<const float4*>(node_emb)[tid - 32];
    __syncthreads();

    int warp = tid >> 5, lane = tid & 31;
    int dst = blockIdx.x * 8 + warp;
    if (dst >= N_NODES) return;

    float4 em = sE[lane];
    float4 acc = em;
    float4 b = sB[lane];
    b.x += em.x; b.y += em.y; b.z += em.z; b.w += em.w;
    int j = g_off[dst], end = g_off[dst + 1];

    for (; j + 4 <= end; j += 4) {
        float av = g_eattr[(size_t)j * 8 + lane];
        float4 e0 = b, e1 = b, e2 = b, e3 = b;
#pragma unroll
        for (int q = 0; q < EDIM; q++) {
            float4 w = sW[q * 32 + lane];
            float a0 = __shfl_sync(0xffffffffu, av, q);
            float a1 = __shfl_sync(0xffffffffu, av, 8 + q);
            float a2 = __shfl_sync(0xffffffffu, av, 16 + q);
            float a3 = __shfl_sync(0xffffffffu, av, 24 + q);
            e0.x += a0 * w.x; e0.y += a0 * w.y; e0.z += a0 * w.z; e0.w += a0 * w.w;
            e1.x += a1 * w.x; e1.y += a1 * w.y; e1.z += a1 * w.z; e1.w += a1 * w.w;
            e2.x += a2 * w.x; e2.y += a2 * w.y; e2.z += a2 * w.z; e2.w += a2 * w.w;
            e3.x += a3 * w.x; e3.y += a3 * w.y; e3.z += a3 * w.z; e3.w += a3 * w.w;
        }
        acc.x += fmaxf(e0.x, 0.f) + fmaxf(e1.x, 0.f) + fmaxf(e2.x, 0.f) + fmaxf(e3.x, 0.f);
        acc.y += fmaxf(e0.y, 0.f) + fmaxf(e1.y, 0.f) + fmaxf(e2.y, 0.f) + fmaxf(e3.y, 0.f);
        acc.z += fmaxf(e0.z, 0.f) + fmaxf(e1.z, 0.f) + fmaxf(e2.z, 0.f) + fmaxf(e3.z, 0.f);
        acc.w += fmaxf(e0.w, 0.f) + fmaxf(e1.w, 0.f) + fmaxf(e2.w, 0.f) + fmaxf(e3.w, 0.f);
    }
    for (; j < end; j++) {
        float v = (lane < EDIM) ? g_eattr[(size_t)j * 8 + lane] : 0.0f;
        float4 e = b;
#pragma unroll
        for (int q = 0; q < EDIM; q++) {
            float a = __shfl_sync(0xffffffffu, v, q);
            float4 w = sW[q * 32 + lane];
            e.x += a * w.x; e.y += a * w.y; e.z += a * w.z; e.w += a * w.w;
        }
        acc.x += fmaxf(e.x, 0.0f);
        acc.y += fmaxf(e.y, 0.0f);
        acc.z += fmaxf(e.z, 0.0f);
        acc.w += fmaxf(e.w, 0.0f);
    }
    store_split(g_Ah, g_Al, (size_t)dst * 128 + lane * 4, acc);
}

// ---------------- fused per-layer MLP ----------------
#define PAD 136
#define WIMG (128 * PAD)
#define FUSED_SMEM (6 * WIMG * 2 + 2048)

__device__ __forceinline__ void gemm_128(float (&acc)[2][8][4],
    uint32_t adrAh, uint32_t adrAl, uint32_t adrBh, uint32_t adrBl)
{
#pragma unroll
    for (int mt = 0; mt < 2; mt++)
#pragma unroll
        for (int nt = 0; nt < 8; nt++)
#pragma unroll
            for (int q = 0; q < 4; q++) acc[mt][nt][q] = 0.0f;

#pragma unroll
    for (int ks = 0; ks < 8; ks++) {
        uint32_t k2 = ks * 32;
        uint32_t ah[2][4], al[2][4], bh[4][4], bl[4][4];
        ldm4(ah[0], adrAh + k2);
        ldm4(ah[1], adrAh + 16 * PAD * 2 + k2);
        ldm4(al[0], adrAl + k2);
        ldm4(al[1], adrAl + 16 * PAD * 2 + k2);
#pragma unroll
        for (int p = 0; p < 4; p++) {
            ldm4(bh[p], adrBh + p * 16 * PAD * 2 + k2);
            ldm4(bl[p], adrBl + p * 16 * PAD * 2 + k2);
        }
#pragma unroll
        for (int mt = 0; mt < 2; mt++)
#pragma unroll
            for (int nt = 0; nt < 8; nt++) {
                int p = nt >> 1, q = nt & 1;
                mma_bf16(acc[mt][nt], ah[mt], bh[p][q], bh[p][q + 2]);
                mma_bf16(acc[mt][nt], al[mt], bh[p][q], bh[p][q + 2]);
                mma_bf16(acc[mt][nt], ah[mt], bl[p][q], bl[p][q + 2]);
            }
    }
}

__global__ void __launch_bounds__(256, 1) k_mlp_fused(
    const __nv_bfloat16* __restrict__ Ah, const __nv_bfloat16* __restrict__ Al,
    float* __restrict__ out,
    const __nv_bfloat16* __restrict__ W1h, const __nv_bfloat16* __restrict__ W1l,
    const __nv_bfloat16* __restrict__ W2h, const __nv_bfloat16* __restrict__ W2l,
    const float* __restrict__ b1,
    const float* __restrict__ g1, const float* __restrict__ bb1,
    const float* __restrict__ m1, const float* __restrict__ v1,
    const float* __restrict__ b2,
    const float* __restrict__ g2, const float* __restrict__ bb2,
    const float* __restrict__ m2, const float* __restrict__ v2)
{
    extern __shared__ char sm[];
    __nv_bfloat16* sW1h = reinterpret_cast<__nv_bfloat16*>(sm);
    __nv_bfloat16* sW1l = sW1h + WIMG;
    __nv_bfloat16* sW2h = sW1l + WIMG;
    __nv_bfloat16* sW2l = sW2h + WIMG;
    __nv_bfloat16* sAh  = sW2l + WIMG;
    __nv_bfloat16* sAl  = sAh + WIMG;
    float* S1 = reinterpret_cast<float*>(sAl + WIMG);
    float* T1 = S1 + 128;
    float* S2 = T1 + 128;
    float* T2 = S2 + 128;

    int tid = threadIdx.x, wid = tid >> 5, lane = tid & 31;

    for (int i = tid; i < 2048; i += 256) {
        int o = i >> 4, kc = (i & 15) * 8;
        *reinterpret_cast<uint4*>(sW1h + o * PAD + kc) = reinterpret_cast<const uint4*>(W1h)[i];
        *reinterpret_cast<uint4*>(sW1l + o * PAD + kc) = reinterpret_cast<const uint4*>(W1l)[i];
        *reinterpret_cast<uint4*>(sW2h + o * PAD + kc) = reinterpret_cast<const uint4*>(W2h)[i];
        *reinterpret_cast<uint4*>(sW2l + o * PAD + kc) = reinterpret_cast<const uint4*>(W2l)[i];
    }
    if (tid < 128) {
        float s1 = g1[tid] * rsqrtf(v1[tid] + BN_EPS);
        S1[tid] = s1;
        T1[tid] = (b1[tid] - m1[tid]) * s1 + bb1[tid];
        float s2 = g2[tid] * rsqrtf(v2[tid] + BN_EPS);
        S2[tid] = s2;
        T2[tid] = (b2[tid] - m2[tid]) * s2 + bb2[tid];
    }

    int wm = wid & 3, wn = wid >> 2;
    uint32_t aOff = ((uint32_t)(wm * 32 + (lane & 15)) * PAD + (lane >> 4) * 8) * 2;
    uint32_t bOff = ((uint32_t)(wn * 64 + (lane & 7) + ((lane >> 3) & 1) * 8) * PAD + (lane >> 4) * 8) * 2;
    uint32_t adrAh  = smem_u32(sAh)  + aOff;
    uint32_t adrAl  = smem_u32(sAl)  + aOff;
    uint32_t adrB1h = smem_u32(sW1h) + bOff;
    uint32_t adrB1l = smem_u32(sW1l) + bOff;
    uint32_t adrB2h = smem_u32(sW2h) + bOff;
    uint32_t adrB2l = smem_u32(sW2l) + bOff;

    uint32_t sAh_u = smem_u32(sAh);
    uint32_t sAl_u = smem_u32(sAl);

    const int NTILES = (N_NODES + 127) / 128;   // 391

    for (int t = blockIdx.x; t < NTILES; t += gridDim.x) {
        int base = t * 128;
        __syncthreads();   // everyone done with previous tile's sA

        // ---- A: cp.async relayout of bf16 planes into padded smem ----
        for (int i = tid; i < 2048; i += 256) {
            int row = i >> 4, seg = (i & 15) * 8;
            uint32_t d = (uint32_t)((row * PAD + seg) * 2);
            size_t s = (size_t)(base + row) * 128 + seg;
            cp16(sAh_u + d, Ah + s);
            cp16(sAl_u + d, Al + s);
        }
        asm volatile("cp.async.commit_group;" ::: "memory");
        asm volatile("cp.async.wait_group 0;" ::: "memory");
        __syncthreads();

        // ---- GEMM1 ----
        float acc[2][8][4];
        gemm_128(acc, adrAh, adrAl, adrB1h, adrB1l);
        __syncthreads();   // all warps done reading sA

        // ---- epilogue1: BN1 + ReLU -> bf16 split back into sA ----
#pragma unroll
        for (int mt = 0; mt < 2; mt++) {
            int r0 = wm * 32 + mt * 16 + (lane >> 2);
#pragma unroll
            for (int nt = 0; nt < 8; nt++) {
                int col = wn * 64 + nt * 8 + (lane & 3) * 2;
                float Sa = S1[col], Sb2 = S1[col + 1];
                float Ta = T1[col], Tb = T1[col + 1];
                float y0 = fmaxf(acc[mt][nt][0] * Sa + Ta, 0.0f);
                float y1 = fmaxf(acc[mt][nt][1] * Sb2 + Tb, 0.0f);
                float y2 = fmaxf(acc[mt][nt][2] * Sa + Ta, 0.0f);
                float y3 = fmaxf(acc[mt][nt][3] * Sb2 + Tb, 0.0f);
                __nv_bfloat162 h0 = __float22bfloat162_rn(make_float2(y0, y1));
                __nv_bfloat162 h1 = __float22bfloat162_rn(make_float2(y2, y3));
                float2 f0 = __bfloat1622float2(h0);
                float2 f1 = __bfloat1622float2(h1);
                __nv_bfloat162 l0 = __float22bfloat162_rn(make_float2(y0 - f0.x, y1 - f0.y));
                __nv_bfloat162 l1 = __float22bfloat162_rn(make_float2(y2 - f1.x, y3 - f1.y));
                *reinterpret_cast<uint32_t*>(sAh + r0 * PAD + col) = *reinterpret_cast<uint32_t*>(&h0);
                *reinterpret_cast<uint32_t*>(sAl + r0 * PAD + col) = *reinterpret_cast<uint32_t*>(&l0);
                *reinterpret_cast<uint32_t*>(sAh + (r0 + 8) * PAD + col) = *reinterpret_cast<uint32_t*>(&h1);
                *reinterpret_cast<uint32_t*>(sAl + (r0 + 8) * PAD + col) = *reinterpret_cast<uint32_t*>(&l1);
            }
        }
        __syncthreads();

        // ---- GEMM2 ----
        gemm_128(acc, adrAh, adrAl, adrB2h, adrB2l);

        // ---- epilogue2: BN2 + ReLU -> global fp32 x ----
#pragma unroll
        for (int mt = 0; mt < 2; mt++) {
            int r0 = base + wm * 32 + mt * 16 + (lane >> 2);
#pragma unroll
            for (int nt = 0; nt < 8; nt++) {
                int col = wn * 64 + nt * 8 + (lane & 3) * 2;
                float Sa = S2[col], Sb2 = S2[col + 1];
                float Ta = T2[col], Tb = T2[col + 1];
                if (r0 < N_NODES) {
                    float2 v;
                    v.x = fmaxf(acc[mt][nt][0] * Sa + Ta, 0.0f);
                    v.y = fmaxf(acc[mt][nt][1] * Sb2 + Tb, 0.0f);
                    *reinterpret_cast<float2*>(out + (size_t)r0 * 128 + col) = v;
                }
                if (r0 + 8 < N_NODES) {
                    float2 v;
                    v.x = fmaxf(acc[mt][nt][2] * Sa + Ta, 0.0f);
                    v.y = fmaxf(acc[mt][nt][3] * Sb2 + Tb, 0.0f);
                    *reinterpret_cast<float2*>(out + (size_t)(r0 + 8) * 128 + col) = v;
                }
            }
        }
    }
}

// ---------------- pooling ----------------
__global__ void k_pool(const int* __restrict__ batch) {
    int gw = (blockIdx.x * blockDim.x + threadIdx.x) >> 5;
    int lane = threadIdx.x & 31;
    if (gw >= N_NODES) return;
    int c = batch[gw];
    float4 v = reinterpret_cast<const float4*>(g_x)[(size_t)gw * 32 + lane];
    atomicAdd(reinterpret_cast<float4*>(g_pool) + c * 32 + lane, v);
    if (lane == 0) atomicAdd(&g_gcnt[c], 1.0f);
}

// ---------------- head ----------------
__global__ void k_head(const float* __restrict__ W1, const float* __restrict__ b1,
                       const float* __restrict__ W2, const float* __restrict__ b2,
                       float* __restrict__ out)
{
    __shared__ float sg[DIM];
    __shared__ float sh[DIM];
    int c = blockIdx.x;
    int t = threadIdx.x;
    float cnt = fmaxf(g_gcnt[c], 1.0f);
    sg[t] = g_pool[c * DIM + t] / cnt;
    __syncthreads();
    float acc = b1[t];
#pragma unroll 8
    for (int k = 0; k < DIM; k++) acc += sg[k] * W1[k * DIM + t];
    sh[t] = fmaxf(acc, 0.0f);
    __syncthreads();
    if (t < NCLASS) {
        float o2 = b2[t];
#pragma unroll 8
        for (int k = 0; k < DIM; k++) o2 += sh[k] * W2[k * NCLASS + t];
        out[c * NCLASS + t] = o2;
    }
}

// ---------------- launch ----------------
extern "C" void kernel_launch(void* const* d_in, const int* in_sizes, int n_in,
                              void* d_out, int out_size)
{
    const float* edge_attr = (const float*)d_in[0];
    const int*   edge_index= (const int*)  d_in[1];
    const int*   batch     = (const int*)  d_in[2];
    const float* node_emb  = (const float*)d_in[3];
    const float* edge_W    = (const float*)d_in[4];
    const float* edge_b    = (const float*)d_in[5];
    const float* mlp_W1    = (const float*)d_in[6];
    const float* mlp_b1    = (const float*)d_in[7];
    const float* bn1_g     = (const float*)d_in[8];
    const float* bn1_b     = (const float*)d_in[9];
    const float* bn1_m     = (const float*)d_in[10];
    const float* bn1_v     = (const float*)d_in[11];
    const float* mlp_W2    = (const float*)d_in[12];
    const float* mlp_b2    = (const float*)d_in[13];
    const float* bn2_g     = (const float*)d_in[14];
    const float* bn2_b     = (const float*)d_in[15];
    const float* bn2_m     = (const float*)d_in[16];
    const float* bn2_v     = (const float*)d_in[17];
    const float* head_W1   = (const float*)d_in[18];
    const float* head_b1   = (const float*)d_in[19];
    const float* head_W2   = (const float*)d_in[20];
    const float* head_b2   = (const float*)d_in[21];
    float* out = (float*)d_out;

    cudaFuncSetAttribute(k_mlp_fused, cudaFuncAttributeMaxDynamicSharedMemorySize, FUSED_SMEM);

    float *px, *ppool, *pgcnt;
    int *pdeg;
    __nv_bfloat16 *pwh, *pwl, *pah, *pal;
    cudaGetSymbolAddress((void**)&px,    g_x);
    cudaGetSymbolAddress((void**)&ppool, g_pool);
    cudaGetSymbolAddress((void**)&pgcnt, g_gcnt);
    cudaGetSymbolAddress((void**)&pdeg,  g_deg);
    cudaGetSymbolAddress((void**)&pwh,   g_Wh);
    cudaGetSymbolAddress((void**)&pwl,   g_Wl);
    cudaGetSymbolAddress((void**)&pah,   g_Ah);
    cudaGetSymbolAddress((void**)&pal,   g_Al);

    // zeroing via async memsets (graph-capturable)
    cudaMemsetAsync(pdeg,  0, N_NODES * sizeof(int));
    cudaMemsetAsync(ppool, 0, N_GRAPH * DIM * sizeof(float));
    cudaMemsetAsync(pgcnt, 0, N_GRAPH * sizeof(float));

    // weight prep + CSR build (deterministic each replay)
    k_prep_w<<<(10 * 16384 + 255) / 256, 256>>>(mlp_W1, mlp_W2);
    k_hist<<<(N_EDGES + 255) / 256, 256>>>(edge_index);
    k_blocksum<<<SCAN_BLOCKS, 256>>>();
    k_scan_bsum<<<1, 256>>>();
    k_scan_final<<<SCAN_BLOCKS, 256>>>();
    k_scatter_idx<<<(N_EDGES + 255) / 256, 256>>>(edge_index);
    k_gather_attr<<<(N_EDGES + 255) / 256, 256>>>(edge_index, edge_attr);

    const int TC_GRID = 148;
    for (int l = 0; l < LAYERS; l++) {
        if (l == 0)
            k_edge_l0<<<(N_NODES + 7) / 8, 256>>>(node_emb, edge_W, edge_b);
        else
            k_edge_csr<<<(N_NODES + 7) / 8, 256>>>(edge_W + l * EDIM * DIM, edge_b + l * DIM);
        int m1 = l * 2, m2 = l * 2 + 1;
        k_mlp_fused<<<TC_GRID, 256, FUSED_SMEM>>>(
            pah, pal, px,
            pwh + m1 * 16384, pwl + m1 * 16384,
            pwh + m2 * 16384, pwl + m2 * 16384,
            mlp_b1 + l * DIM, bn1_g + l * DIM, bn1_b + l * DIM, bn1_m + l * DIM, bn1_v + l * DIM,
            mlp_b2 + l * DIM, bn2_g + l * DIM, bn2_b + l * DIM, bn2_m + l * DIM, bn2_v + l * DIM);
    }

    k_pool<<<(N_NODES * 32 + 255) / 256, 256>>>(batch);
    k_head<<<N_GRAPH, DIM>>>(head_W1, head_b1, head_W2, head_b2, out);
}

// round 14
// speedup vs baseline: 1.0849x; 1.0120x over previous
#include <cuda_runtime.h>
#include <cuda_bf16.h>
#include <cstdint>

#define N_NODES 50000
#define N_EDGES 800000
#define N_GRAPH 500
#define DIM     128
#define EDIM    7
#define LAYERS  5
#define NCLASS  10
#define BN_EPS  1e-5f
#define NROWS_PAD 50048   // NTILES*128

typedef unsigned long long u64;

// ---------------- scratch ----------------
__device__ float g_x  [N_NODES * DIM];
__device__ float g_pool[N_GRAPH * DIM];
__device__ float g_gcnt[N_GRAPH];

// bf16 hi/lo planes of (x + agg): edge-kernel output, MLP A input
__device__ __nv_bfloat16 g_Ah[(size_t)NROWS_PAD * DIM];
__device__ __nv_bfloat16 g_Al[(size_t)NROWS_PAD * DIM];

// CSR scratch
__device__ int   g_deg [N_NODES];
__device__ int   g_off [N_NODES + 1];
__device__ int   g_bsum[256];
__device__ int   g_fill[N_NODES];
__device__ int   g_eid [N_EDGES];
__device__ int   g_esrc[N_EDGES];
__device__ float g_eattr[(size_t)N_EDGES * 8];   // attr in CSR order (padded to 8)

// transposed + bf16-split weight images, row-major [o][k] (10 mats: l*2 + {W1,W2})
__device__ __nv_bfloat16 g_Wh[10 * 16384];
__device__ __nv_bfloat16 g_Wl[10 * 16384];

// ================= helpers =================
__device__ __forceinline__ uint32_t smem_u32(const void* p) {
    uint32_t a;
    asm("{ .reg .u64 t; cvta.to.shared.u64 t, %1; cvt.u32.u64 %0, t; }" : "=r"(a) : "l"(p));
    return a;
}
__device__ __forceinline__ void ldm4(uint32_t* r, uint32_t addr) {
    asm volatile("ldmatrix.sync.aligned.m8n8.x4.shared.b16 {%0,%1,%2,%3}, [%4];"
                 : "=r"(r[0]), "=r"(r[1]), "=r"(r[2]), "=r"(r[3]) : "r"(addr));
}
__device__ __forceinline__ void mma_bf16(float* c, const uint32_t* a, uint32_t b0, uint32_t b1) {
    asm volatile("mma.sync.aligned.m16n8k16.row.col.f32.bf16.bf16.f32 "
                 "{%0,%1,%2,%3}, {%4,%5,%6,%7}, {%8,%9}, {%0,%1,%2,%3};"
                 : "+f"(c[0]), "+f"(c[1]), "+f"(c[2]), "+f"(c[3])
                 : "r"(a[0]), "r"(a[1]), "r"(a[2]), "r"(a[3]), "r"(b0), "r"(b1));
}
__device__ __forceinline__ void cp16(uint32_t smem_dst, const void* gsrc) {
    asm volatile("cp.async.cg.shared.global [%0], [%1], 16;" :: "r"(smem_dst), "l"(gsrc));
}

// ---- packed f32x2 (Blackwell FFMA2 path; base sm_100+ PTX, no 'a' suffix) ----
__device__ __forceinline__ u64 fma2(u64 a, u64 b, u64 c) {
    u64 d;
    asm("fma.rn.f32x2 %0, %1, %2, %3;" : "=l"(d) : "l"(a), "l"(b), "l"(c));
    return d;
}
__device__ __forceinline__ u64 add2(u64 a, u64 b) {
    u64 d;
    asm("add.rn.f32x2 %0, %1, %2;" : "=l"(d) : "l"(a), "l"(b));
    return d;
}
__device__ __forceinline__ u64 packdup(float a) {
    u64 d;
    uint32_t u = __float_as_uint(a);
    asm("mov.b64 %0, {%1, %1};" : "=l"(d) : "r"(u));
    return d;
}
__device__ __forceinline__ u64 pack2(float a, float b) {
    u64 d;
    uint32_t ua = __float_as_uint(a), ub = __float_as_uint(b);
    asm("mov.b64 %0, {%1, %2};" : "=l"(d) : "r"(ua), "r"(ub));
    return d;
}
__device__ __forceinline__ float2 unpack2(u64 v) {
    uint32_t x, y;
    asm("mov.b64 {%0, %1}, %2;" : "=r"(x), "=r"(y) : "l"(v));
    return make_float2(__uint_as_float(x), __uint_as_float(y));
}

// split fp32x4 -> bf16 hi/lo and store 8B to each plane
__device__ __forceinline__ void store_split(__nv_bfloat16* Ah, __nv_bfloat16* Al,
                                            size_t idx, float4 acc) {
    __nv_bfloat162 h01 = __float22bfloat162_rn(make_float2(acc.x, acc.y));
    __nv_bfloat162 h23 = __float22bfloat162_rn(make_float2(acc.z, acc.w));
    float2 f01 = __bfloat1622float2(h01);
    float2 f23 = __bfloat1622float2(h23);
    __nv_bfloat162 l01 = __float22bfloat162_rn(make_float2(acc.x - f01.x, acc.y - f01.y));
    __nv_bfloat162 l23 = __float22bfloat162_rn(make_float2(acc.z - f23.x, acc.w - f23.y));
    uint2 hp = make_uint2(*reinterpret_cast<uint32_t*>(&h01), *reinterpret_cast<uint32_t*>(&h23));
    uint2 lp = make_uint2(*reinterpret_cast<uint32_t*>(&l01), *reinterpret_cast<uint32_t*>(&l23));
    *reinterpret_cast<uint2*>(Ah + idx) = hp;
    *reinterpret_cast<uint2*>(Al + idx) = lp;
}

// ---------------- weight prep: transpose + bf16 hi/lo split ----------------
__global__ void k_prep_w(const float* __restrict__ W1, const float* __restrict__ W2) {
    int idx = blockIdx.x * blockDim.x + threadIdx.x;
    if (idx >= 10 * 16384) return;
    int mat = idx >> 14;
    int r = idx & 16383;
    int o = r >> 7, k = r & 127;
    int l = mat >> 1;
    const float* W = (mat & 1) ? (W2 + l * 16384) : (W1 + l * 16384);
    float x = W[k * 128 + o];
    __nv_bfloat16 h = __float2bfloat16(x);
    __nv_bfloat16 lo = __float2bfloat16(x - __bfloat162float(h));
    g_Wh[mat * 16384 + o * 128 + k] = h;
    g_Wl[mat * 16384 + o * 128 + k] = lo;
}

// ---------------- graph sizes: batch is sorted -> binary search ----------------
__global__ void k_gcnt(const int* __restrict__ batch) {
    int c = blockIdx.x * blockDim.x + threadIdx.x;
    if (c >= N_GRAPH) return;
    int lo = 0, hi = N_NODES;
    while (lo < hi) { int m = (lo + hi) >> 1; if (batch[m] < c) lo = m + 1; else hi = m; }
    int lo2 = lo, hi2 = N_NODES;
    while (lo2 < hi2) { int m = (lo2 + hi2) >> 1; if (batch[m] < c + 1) lo2 = m + 1; else hi2 = m; }
    g_gcnt[c] = (float)(lo2 - lo);
}

// ---------------- CSR build ----------------
__global__ void k_hist(const int* __restrict__ ei) {
    int e = blockIdx.x * blockDim.x + threadIdx.x;
    if (e < N_EDGES) atomicAdd(&g_deg[ei[N_EDGES + e]], 1);
}
#define SCAN_BLOCKS ((N_NODES + 255) / 256)   // 196
__global__ void k_blocksum() {
    __shared__ int s[256];
    int i = blockIdx.x * 256 + threadIdx.x;
    s[threadIdx.x] = (i < N_NODES) ? g_deg[i] : 0;
    __syncthreads();
    for (int d = 128; d > 0; d >>= 1) {
        if (threadIdx.x < d) s[threadIdx.x] += s[threadIdx.x + d];
        __syncthreads();
    }
    if (threadIdx.x == 0) g_bsum[blockIdx.x] = s[0];
}
__global__ void k_scan_bsum() {
    __shared__ int s[256];
    int v = (threadIdx.x < SCAN_BLOCKS) ? g_bsum[threadIdx.x] : 0;
    s[threadIdx.x] = v;
    __syncthreads();
    for (int d = 1; d < 256; d <<= 1) {
        int t = (threadIdx.x >= d) ? s[threadIdx.x - d] : 0;
        __syncthreads();
        s[threadIdx.x] += t;
        __syncthreads();
    }
    if (threadIdx.x < SCAN_BLOCKS) g_bsum[threadIdx.x] = s[threadIdx.x] - v;  // exclusive
}
__global__ void k_scan_final() {
    __shared__ int s[256];
    int i = blockIdx.x * 256 + threadIdx.x;
    int v = (i < N_NODES) ? g_deg[i] : 0;
    s[threadIdx.x] = v;
    __syncthreads();
    for (int d = 1; d < 256; d <<= 1) {
        int t = (threadIdx.x >= d) ? s[threadIdx.x - d] : 0;
        __syncthreads();
        s[threadIdx.x] += t;
        __syncthreads();
    }
    int excl = s[threadIdx.x] - v + g_bsum[blockIdx.x];
    if (i < N_NODES) { g_off[i] = excl; g_fill[i] = excl; }
    if (i == N_NODES - 1) g_off[N_NODES] = excl + v;
}

// phase 1: atomic slot assignment, single 4B random store
__global__ void k_scatter_idx(const int* __restrict__ ei) {
    int e = blockIdx.x * blockDim.x + threadIdx.x;
    if (e < N_EDGES) {
        int dst = ei[N_EDGES + e];
        int p = atomicAdd(&g_fill[dst], 1);
        g_eid[p] = e;
    }
}
// phase 2: coalesced CSR-order writes; random reads served from L2
__global__ void k_gather_attr(const int* __restrict__ ei, const float* __restrict__ attr) {
    int j = blockIdx.x * blockDim.x + threadIdx.x;
    if (j >= N_EDGES) return;
    int e = g_eid[j];
    g_esrc[j] = ei[e];
    const float* a = attr + (size_t)e * 7;
    float4 v0 = make_float4(a[0], a[1], a[2], a[3]);
    float4 v1 = make_float4(a[4], a[5], a[6], 0.0f);
    float4* d = reinterpret_cast<float4*>(g_eattr + (size_t)j * 8);
    d[0] = v0;
    d[1] = v1;
}

// ---------------- edge aggregation, 4-way pipelined, packed f32x2 (layers 1..4) ----------------
// writes (x[dst] + sum msg) as bf16 hi/lo planes
__global__ void __launch_bounds__(256) k_edge_csr(
    const float* __restrict__ eW, const float* __restrict__ eb)
{
    __shared__ ulonglong2 sW[EDIM * 32];   // (w01, w23) packed pairs per (q, lane)
    __shared__ ulonglong2 sB[32];
    int tid = threadIdx.x;
    if (tid < EDIM * 32) sW[tid] = reinterpret_cast<const ulonglong2*>(eW)[tid];
    if (tid < 32)        sB[tid] = reinterpret_cast<const ulonglong2*>(eb)[tid];
    __syncthreads();

    int warp = tid >> 5, lane = tid & 31;
    int dst = blockIdx.x * 8 + warp;
    if (dst >= N_NODES) return;

    const ulonglong2* X2 = reinterpret_cast<const ulonglong2*>(g_x);
    ulonglong2 xd = X2[(size_t)dst * 32 + lane];
    u64 acc01 = xd.x, acc23 = xd.y;
    const u64 b01 = sB[lane].x, b23 = sB[lane].y;
    int j = g_off[dst], end = g_off[dst + 1];

    for (; j + 4 <= end; j += 4) {
        float av = g_eattr[(size_t)j * 8 + lane];   // 4 edges x 8 attrs, coalesced
        int s0 = g_esrc[j + 0], s1 = g_esrc[j + 1];
        int s2 = g_esrc[j + 2], s3 = g_esrc[j + 3];
        ulonglong2 x0 = X2[(size_t)s0 * 32 + lane];
        ulonglong2 x1 = X2[(size_t)s1 * 32 + lane];
        ulonglong2 x2 = X2[(size_t)s2 * 32 + lane];
        ulonglong2 x3 = X2[(size_t)s3 * 32 + lane];
        u64 e01_0 = b01, e23_0 = b23, e01_1 = b01, e23_1 = b23;
        u64 e01_2 = b01, e23_2 = b23, e01_3 = b01, e23_3 = b23;
#pragma unroll
        for (int q = 0; q < EDIM; q++) {
            ulonglong2 w = sW[q * 32 + lane];
            u64 a0 = packdup(__shfl_sync(0xffffffffu, av, q));
            u64 a1 = packdup(__shfl_sync(0xffffffffu, av, 8 + q));
            u64 a2 = packdup(__shfl_sync(0xffffffffu, av, 16 + q));
            u64 a3 = packdup(__shfl_sync(0xffffffffu, av, 24 + q));
            e01_0 = fma2(a0, w.x, e01_0); e23_0 = fma2(a0, w.y, e23_0);
            e01_1 = fma2(a1, w.x, e01_1); e23_1 = fma2(a1, w.y, e23_1);
            e01_2 = fma2(a2, w.x, e01_2); e23_2 = fma2(a2, w.y, e23_2);
            e01_3 = fma2(a3, w.x, e01_3); e23_3 = fma2(a3, w.y, e23_3);
        }
        {
            float2 f01, f23;
            f01 = unpack2(add2(x0.x, e01_0)); f23 = unpack2(add2(x0.y, e23_0));
            acc01 = add2(acc01, pack2(fmaxf(f01.x, 0.f), fmaxf(f01.y, 0.f)));
            acc23 = add2(acc23, pack2(fmaxf(f23.x, 0.f), fmaxf(f23.y, 0.f)));
            f01 = unpack2(add2(x1.x, e01_1)); f23 = unpack2(add2(x1.y, e23_1));
            acc01 = add2(acc01, pack2(fmaxf(f01.x, 0.f), fmaxf(f01.y, 0.f)));
            acc23 = add2(acc23, pack2(fmaxf(f23.x, 0.f), fmaxf(f23.y, 0.f)));
            f01 = unpack2(add2(x2.x, e01_2)); f23 = unpack2(add2(x2.y, e23_2));
            acc01 = add2(acc01, pack2(fmaxf(f01.x, 0.f), fmaxf(f01.y, 0.f)));
            acc23 = add2(acc23, pack2(fmaxf(f23.x, 0.f), fmaxf(f23.y, 0.f)));
            f01 = unpack2(add2(x3.x, e01_3)); f23 = unpack2(add2(x3.y, e23_3));
            acc01 = add2(acc01, pack2(fmaxf(f01.x, 0.f), fmaxf(f01.y, 0.f)));
            acc23 = add2(acc23, pack2(fmaxf(f23.x, 0.f), fmaxf(f23.y, 0.f)));
        }
    }
    for (; j < end; j++) {
        int src = g_esrc[j];
        float v = (lane < EDIM) ? g_eattr[(size_t)j * 8 + lane] : 0.0f;
        u64 e01 = b01, e23 = b23;
#pragma unroll
        for (int q = 0; q < EDIM; q++) {
            ulonglong2 w = sW[q * 32 + lane];
            u64 a = packdup(__shfl_sync(0xffffffffu, v, q));
            e01 = fma2(a, w.x, e01);
            e23 = fma2(a, w.y, e23);
        }
        ulonglong2 xv = X2[(size_t)src * 32 + lane];
        float2 f01 = unpack2(add2(xv.x, e01));
        float2 f23 = unpack2(add2(xv.y, e23));
        acc01 = add2(acc01, pack2(fmaxf(f01.x, 0.f), fmaxf(f01.y, 0.f)));
        acc23 = add2(acc23, pack2(fmaxf(f23.x, 0.f), fmaxf(f23.y, 0.f)));
    }
    float2 a01 = unpack2(acc01), a23 = unpack2(acc23);
    store_split(g_Ah, g_Al, (size_t)dst * 128 + lane * 4,
                make_float4(a01.x, a01.y, a23.x, a23.y));
}

// ---------------- layer-0 edge: x[src] == node_emb for all nodes (no gather) ----------------
__global__ void __launch_bounds__(256) k_edge_l0(
    const float* __restrict__ node_emb,
    const float* __restrict__ eW, const float* __restrict__ eb)
{
    __shared__ ulonglong2 sW[EDIM * 32];
    __shared__ ulonglong2 sB[32];
    __shared__ ulonglong2 sE[32];
    int tid = threadIdx.x;
    if (tid < EDIM * 32) sW[tid] = reinterpret_cast<const ulonglong2*>(eW)[tid];
    if (tid < 32)        sB[tid] = reinterpret_cast<const ulonglong2*>(eb)[tid];
    if (tid >= 32 && tid < 64)
        sE[tid - 32] = reinterpret_cast<const ulonglong2*>(node_emb)[tid - 32];
    __syncthreads();

    int warp = tid >> 5, lane = tid & 31;
    int dst = blockIdx.x * 8 + warp;
    if (dst >= N_NODES) return;

    ulonglong2 em = sE[lane];
    u64 acc01 = em.x, acc23 = em.y;
    const u64 b01 = add2(sB[lane].x, em.x);     // fold emb into bias
    const u64 b23 = add2(sB[lane].y, em.y);
    int j = g_off[dst], end = g_off[dst + 1];

    for (; j + 4 <= end; j += 4) {
        float av = g_eattr[(size_t)j * 8 + lane];
        u64 e01_0 = b01, e23_0 = b23, e01_1 = b01, e23_1 = b23;
        u64 e01_2 = b01, e23_2 = b23, e01_3 = b01, e23_3 = b23;
#pragma unroll
        for (int q = 0; q < EDIM; q++) {
            ulonglong2 w = sW[q * 32 + lane];
            u64 a0 = packdup(__shfl_sync(0xffffffffu, av, q));
            u64 a1 = packdup(__shfl_sync(0xffffffffu, av, 8 + q));
            u64 a2 = packdup(__shfl_sync(0xffffffffu, av, 16 + q));
            u64 a3 = packdup(__shfl_sync(0xffffffffu, av, 24 + q));
            e01_0 = fma2(a0, w.x, e01_0); e23_0 = fma2(a0, w.y, e23_0);
            e01_1 = fma2(a1, w.x, e01_1); e23_1 = fma2(a1, w.y, e23_1);
            e01_2 = fma2(a2, w.x, e01_2); e23_2 = fma2(a2, w.y, e23_2);
            e01_3 = fma2(a3, w.x, e01_3); e23_3 = fma2(a3, w.y, e23_3);
        }
        float2 f01, f23;
        f01 = unpack2(e01_0); f23 = unpack2(e23_0);
        acc01 = add2(acc01, pack2(fmaxf(f01.x, 0.f), fmaxf(f01.y, 0.f)));
        acc23 = add2(acc23, pack2(fmaxf(f23.x, 0.f), fmaxf(f23.y, 0.f)));
        f01 = unpack2(e01_1); f23 = unpack2(e23_1);
        acc01 = add2(acc01, pack2(fmaxf(f01.x, 0.f), fmaxf(f01.y, 0.f)));
        acc23 = add2(acc23, pack2(fmaxf(f23.x, 0.f), fmaxf(f23.y, 0.f)));
        f01 = unpack2(e01_2); f23 = unpack2(e23_2);
        acc01 = add2(acc01, pack2(fmaxf(f01.x, 0.f), fmaxf(f01.y, 0.f)));
        acc23 = add2(acc23, pack2(fmaxf(f23.x, 0.f), fmaxf(f23.y, 0.f)));
        f01 = unpack2(e01_3); f23 = unpack2(e23_3);
        acc01 = add2(acc01, pack2(fmaxf(f01.x, 0.f), fmaxf(f01.y, 0.f)));
        acc23 = add2(acc23, pack2(fmaxf(f23.x, 0.f), fmaxf(f23.y, 0.f)));
    }
    for (; j < end; j++) {
        float v = (lane < EDIM) ? g_eattr[(size_t)j * 8 + lane] : 0.0f;
        u64 e01 = b01, e23 = b23;
#pragma unroll
        for (int q = 0; q < EDIM; q++) {
            ulonglong2 w = sW[q * 32 + lane];
            u64 a = packdup(__shfl_sync(0xffffffffu, v, q));
            e01 = fma2(a, w.x, e01);
            e23 = fma2(a, w.y, e23);
        }
        float2 f01 = unpack2(e01), f23 = unpack2(e23);
        acc01 = add2(acc01, pack2(fmaxf(f01.x, 0.f), fmaxf(f01.y, 0.f)));
        acc23 = add2(acc23, pack2(fmaxf(f23.x, 0.f), fmaxf(f23.y, 0.f)));
    }
    float2 a01 = unpack2(acc01), a23 = unpack2(acc23);
    store_split(g_Ah, g_Al, (size_t)dst * 128 + lane * 4,
                make_float4(a01.x, a01.y, a23.x, a23.y));
}

// ---------------- fused per-layer MLP ----------------
#define PAD 136
#define WIMG (128 * PAD)
#define FUSED_SMEM (6 * WIMG * 2 + 2048)

__device__ __forceinline__ void gemm_128(float (&acc)[2][8][4],
    uint32_t adrAh, uint32_t adrAl, uint32_t adrBh, uint32_t adrBl)
{
#pragma unroll
    for (int mt = 0; mt < 2; mt++)
#pragma unroll
        for (int nt = 0; nt < 8; nt++)
#pragma unroll
            for (int q = 0; q < 4; q++) acc[mt][nt][q] = 0.0f;

#pragma unroll
    for (int ks = 0; ks < 8; ks++) {
        uint32_t k2 = ks * 32;
        uint32_t ah[2][4], al[2][4], bh[4][4], bl[4][4];
        ldm4(ah[0], adrAh + k2);
        ldm4(ah[1], adrAh + 16 * PAD * 2 + k2);
        ldm4(al[0], adrAl + k2);
        ldm4(al[1], adrAl + 16 * PAD * 2 + k2);
#pragma unroll
        for (int p = 0; p < 4; p++) {
            ldm4(bh[p], adrBh + p * 16 * PAD * 2 + k2);
            ldm4(bl[p], adrBl + p * 16 * PAD * 2 + k2);
        }
#pragma unroll
        for (int mt = 0; mt < 2; mt++)
#pragma unroll
            for (int nt = 0; nt < 8; nt++) {
                int p = nt >> 1, q = nt & 1;
                mma_bf16(acc[mt][nt], ah[mt], bh[p][q], bh[p][q + 2]);
                mma_bf16(acc[mt][nt], al[mt], bh[p][q], bh[p][q + 2]);
                mma_bf16(acc[mt][nt], ah[mt], bl[p][q], bl[p][q + 2]);
            }
    }
}

__global__ void __launch_bounds__(256, 1) k_mlp_fused(
    const __nv_bfloat16* __restrict__ Ah, const __nv_bfloat16* __restrict__ Al,
    float* __restrict__ out,
    const int* __restrict__ batch, int last,
    const __nv_bfloat16* __restrict__ W1h, const __nv_bfloat16* __restrict__ W1l,
    const __nv_bfloat16* __restrict__ W2h, const __nv_bfloat16* __restrict__ W2l,
    const float* __restrict__ b1,
    const float* __restrict__ g1, const float* __restrict__ bb1,
    const float* __restrict__ m1, const float* __restrict__ v1,
    const float* __restrict__ b2,
    const float* __restrict__ g2, const float* __restrict__ bb2,
    const float* __restrict__ m2, const float* __restrict__ v2)
{
    extern __shared__ char sm[];
    __nv_bfloat16* sW1h = reinterpret_cast<__nv_bfloat16*>(sm);
    __nv_bfloat16* sW1l = sW1h + WIMG;
    __nv_bfloat16* sW2h = sW1l + WIMG;
    __nv_bfloat16* sW2l = sW2h + WIMG;
    __nv_bfloat16* sAh  = sW2l + WIMG;
    __nv_bfloat16* sAl  = sAh + WIMG;
    float* S1 = reinterpret_cast<float*>(sAl + WIMG);
    float* T1 = S1 + 128;
    float* S2 = T1 + 128;
    float* T2 = S2 + 128;

    int tid = threadIdx.x, wid = tid >> 5, lane = tid & 31;

    for (int i = tid; i < 2048; i += 256) {
        int o = i >> 4, kc = (i & 15) * 8;
        *reinterpret_cast<uint4*>(sW1h + o * PAD + kc) = reinterpret_cast<const uint4*>(W1h)[i];
        *reinterpret_cast<uint4*>(sW1l + o * PAD + kc) = reinterpret_cast<const uint4*>(W1l)[i];
        *reinterpret_cast<uint4*>(sW2h + o * PAD + kc) = reinterpret_cast<const uint4*>(W2h)[i];
        *reinterpret_cast<uint4*>(sW2l + o * PAD + kc) = reinterpret_cast<const uint4*>(W2l)[i];
    }
    if (tid < 128) {
        float s1 = g1[tid] * rsqrtf(v1[tid] + BN_EPS);
        S1[tid] = s1;
        T1[tid] = (b1[tid] - m1[tid]) * s1 + bb1[tid];
        float s2 = g2[tid] * rsqrtf(v2[tid] + BN_EPS);
        S2[tid] = s2;
        T2[tid] = (b2[tid] - m2[tid]) * s2 + bb2[tid];
    }

    int wm = wid & 3, wn = wid >> 2;
    uint32_t aOff = ((uint32_t)(wm * 32 + (lane & 15)) * PAD + (lane >> 4) * 8) * 2;
    uint32_t bOff = ((uint32_t)(wn * 64 + (lane & 7) + ((lane >> 3) & 1) * 8) * PAD + (lane >> 4) * 8) * 2;
    uint32_t adrAh  = smem_u32(sAh)  + aOff;
    uint32_t adrAl  = smem_u32(sAl)  + aOff;
    uint32_t adrB1h = smem_u32(sW1h) + bOff;
    uint32_t adrB1l = smem_u32(sW1l) + bOff;
    uint32_t adrB2h = smem_u32(sW2h) + bOff;
    uint32_t adrB2l = smem_u32(sW2l) + bOff;

    uint32_t sAh_u = smem_u32(sAh);
    uint32_t sAl_u = smem_u32(sAl);

    const int NTILES = (N_NODES + 127) / 128;   // 391

    for (int t = blockIdx.x; t < NTILES; t += gridDim.x) {
        int base = t * 128;
        __syncthreads();   // everyone done with previous tile's sA

        // ---- A: cp.async relayout of bf16 planes into padded smem ----
        for (int i = tid; i < 2048; i += 256) {
            int row = i >> 4, seg = (i & 15) * 8;
            uint32_t d = (uint32_t)((row * PAD + seg) * 2);
            size_t s = (size_t)(base + row) * 128 + seg;
            cp16(sAh_u + d, Ah + s);
            cp16(sAl_u + d, Al + s);
        }
        asm volatile("cp.async.commit_group;" ::: "memory");
        asm volatile("cp.async.wait_group 0;" ::: "memory");
        __syncthreads();

        // ---- GEMM1 ----
        float acc[2][8][4];
        gemm_128(acc, adrAh, adrAl, adrB1h, adrB1l);
        __syncthreads();   // all warps done reading sA

        // ---- epilogue1: BN1 + ReLU -> bf16 split back into sA ----
#pragma unroll
        for (int mt = 0; mt < 2; mt++) {
            int r0 = wm * 32 + mt * 16 + (lane >> 2);
#pragma unroll
            for (int nt = 0; nt < 8; nt++) {
                int col = wn * 64 + nt * 8 + (lane & 3) * 2;
                float Sa = S1[col], Sb2 = S1[col + 1];
                float Ta = T1[col], Tb = T1[col + 1];
                float y0 = fmaxf(acc[mt][nt][0] * Sa + Ta, 0.0f);
                float y1 = fmaxf(acc[mt][nt][1] * Sb2 + Tb, 0.0f);
                float y2 = fmaxf(acc[mt][nt][2] * Sa + Ta, 0.0f);
                float y3 = fmaxf(acc[mt][nt][3] * Sb2 + Tb, 0.0f);
                __nv_bfloat162 h0 = __float22bfloat162_rn(make_float2(y0, y1));
                __nv_bfloat162 h1 = __float22bfloat162_rn(make_float2(y2, y3));
                float2 f0 = __bfloat1622float2(h0);
                float2 f1 = __bfloat1622float2(h1);
                __nv_bfloat162 l0 = __float22bfloat162_rn(make_float2(y0 - f0.x, y1 - f0.y));
                __nv_bfloat162 l1 = __float22bfloat162_rn(make_float2(y2 - f1.x, y3 - f1.y));
                *reinterpret_cast<uint32_t*>(sAh + r0 * PAD + col) = *reinterpret_cast<uint32_t*>(&h0);
                *reinterpret_cast<uint32_t*>(sAl + r0 * PAD + col) = *reinterpret_cast<uint32_t*>(&l0);
                *reinterpret_cast<uint32_t*>(sAh + (r0 + 8) * PAD + col) = *reinterpret_cast<uint32_t*>(&h1);
                *reinterpret_cast<uint32_t*>(sAl + (r0 + 8) * PAD + col) = *reinterpret_cast<uint32_t*>(&l1);
            }
        }
        __syncthreads();

        // ---- GEMM2 ----
        gemm_128(acc, adrAh, adrAl, adrB2h, adrB2l);

        // ---- epilogue2: BN2 + ReLU -> global x, or fused pool atomics on last layer ----
#pragma unroll
        for (int mt = 0; mt < 2; mt++) {
            int r0 = base + wm * 32 + mt * 16 + (lane >> 2);
            int c0 = (last && r0 < N_NODES) ? batch[r0] : 0;
            int c1 = (last && r0 + 8 < N_NODES) ? batch[r0 + 8] : 0;
#pragma unroll
            for (int nt = 0; nt < 8; nt++) {
                int col = wn * 64 + nt * 8 + (lane & 3) * 2;
                float Sa = S2[col], Sb2 = S2[col + 1];
                float Ta = T2[col], Tb = T2[col + 1];
                if (r0 < N_NODES) {
                    float2 v;
                    v.x = fmaxf(acc[mt][nt][0] * Sa + Ta, 0.0f);
                    v.y = fmaxf(acc[mt][nt][1] * Sb2 + Tb, 0.0f);
                    if (last) atomicAdd(reinterpret_cast<float2*>(g_pool + (size_t)c0 * 128 + col), v);
                    else *reinterpret_cast<float2*>(out + (size_t)r0 * 128 + col) = v;
                }
                if (r0 + 8 < N_NODES) {
                    float2 v;
                    v.x = fmaxf(acc[mt][nt][2] * Sa + Ta, 0.0f);
                    v.y = fmaxf(acc[mt][nt][3] * Sb2 + Tb, 0.0f);
                    if (last) atomicAdd(reinterpret_cast<float2*>(g_pool + (size_t)c1 * 128 + col), v);
                    else *reinterpret_cast<float2*>(out + (size_t)(r0 + 8) * 128 + col) = v;
                }
            }
        }
    }
}

// ---------------- head ----------------
__global__ void k_head(const float* __restrict__ W1, const float* __restrict__ b1,
                       const float* __restrict__ W2, const float* __restrict__ b2,
                       float* __restrict__ out)
{
    __shared__ float sg[DIM];
    __shared__ float sh[DIM];
    int c = blockIdx.x;
    int t = threadIdx.x;
    float cnt = fmaxf(g_gcnt[c], 1.0f);
    sg[t] = g_pool[c * DIM + t] / cnt;
    __syncthreads();
    float acc = b1[t];
#pragma unroll 8
    for (int k = 0; k < DIM; k++) acc += sg[k] * W1[k * DIM + t];
    sh[t] = fmaxf(acc, 0.0f);
    __syncthreads();
    if (t < NCLASS) {
        float o2 = b2[t];
#pragma unroll 8
        for (int k = 0; k < DIM; k++) o2 += sh[k] * W2[k * NCLASS + t];
        out[c * NCLASS + t] = o2;
    }
}

// ---------------- launch ----------------
extern "C" void kernel_launch(void* const* d_in, const int* in_sizes, int n_in,
                              void* d_out, int out_size)
{
    const float* edge_attr = (const float*)d_in[0];
    const int*   edge_index= (const int*)  d_in[1];
    const int*   batch     = (const int*)  d_in[2];
    const float* node_emb  = (const float*)d_in[3];
    const float* edge_W    = (const float*)d_in[4];
    const float* edge_b    = (const float*)d_in[5];
    const float* mlp_W1    = (const float*)d_in[6];
    const float* mlp_b1    = (const float*)d_in[7];
    const float* bn1_g     = (const float*)d_in[8];
    const float* bn1_b     = (const float*)d_in[9];
    const float* bn1_m     = (const float*)d_in[10];
    const float* bn1_v     = (const float*)d_in[11];
    const float* mlp_W2    = (const float*)d_in[12];
    const float* mlp_b2    = (const float*)d_in[13];
    const float* bn2_g     = (const float*)d_in[14];
    const float* bn2_b     = (const float*)d_in[15];
    const float* bn2_m     = (const float*)d_in[16];
    const float* bn2_v     = (const float*)d_in[17];
    const float* head_W1   = (const float*)d_in[18];
    const float* head_b1   = (const float*)d_in[19];
    const float* head_W2   = (const float*)d_in[20];
    const float* head_b2   = (const float*)d_in[21];
    float* out = (float*)d_out;

    cudaFuncSetAttribute(k_mlp_fused, cudaFuncAttributeMaxDynamicSharedMemorySize, FUSED_SMEM);

    float *px, *ppool;
    int *pdeg;
    __nv_bfloat16 *pwh, *pwl, *pah, *pal;
    cudaGetSymbolAddress((void**)&px,    g_x);
    cudaGetSymbolAddress((void**)&ppool, g_pool);
    cudaGetSymbolAddress((void**)&pdeg,  g_deg);
    cudaGetSymbolAddress((void**)&pwh,   g_Wh);
    cudaGetSymbolAddress((void**)&pwl,   g_Wl);
    cudaGetSymbolAddress((void**)&pah,   g_Ah);
    cudaGetSymbolAddress((void**)&pal,   g_Al);

    // zeroing via async memsets (graph-capturable)
    cudaMemsetAsync(pdeg,  0, N_NODES * sizeof(int));
    cudaMemsetAsync(ppool, 0, N_GRAPH * DIM * sizeof(float));

    // weight prep + graph sizes + CSR build (deterministic each replay)
    k_prep_w<<<(10 * 16384 + 255) / 256, 256>>>(mlp_W1, mlp_W2);
    k_gcnt<<<2, 256>>>(batch);
    k_hist<<<(N_EDGES + 255) / 256, 256>>>(edge_index);
    k_blocksum<<<SCAN_BLOCKS, 256>>>();
    k_scan_bsum<<<1, 256>>>();
    k_scan_final<<<SCAN_BLOCKS, 256>>>();
    k_scatter_idx<<<(N_EDGES + 255) / 256, 256>>>(edge_index);
    k_gather_attr<<<(N_EDGES + 255) / 256, 256>>>(edge_index, edge_attr);

    const int TC_GRID = 148;
    for (int l = 0; l < LAYERS; l++) {
        if (l == 0)
            k_edge_l0<<<(N_NODES + 7) / 8, 256>>>(node_emb, edge_W, edge_b);
        else
            k_edge_csr<<<(N_NODES + 7) / 8, 256>>>(edge_W + l * EDIM * DIM, edge_b + l * DIM);
        int m1 = l * 2, m2 = l * 2 + 1;
        k_mlp_fused<<<TC_GRID, 256, FUSED_SMEM>>>(
            pah, pal, px,
            batch, (l == LAYERS - 1) ? 1 : 0,
            pwh + m1 * 16384, pwl + m1 * 16384,
            pwh + m2 * 16384, pwl + m2 * 16384,
            mlp_b1 + l * DIM, bn1_g + l * DIM, bn1_b + l * DIM, bn1_m + l * DIM, bn1_v + l * DIM,
            mlp_b2 + l * DIM, bn2_g + l * DIM, bn2_b + l * DIM, bn2_m + l * DIM, bn2_v + l * DIM);
    }

    k_head<<<N_GRAPH, DIM>>>(head_W1, head_b1, head_W2, head_b2, out);
}

// round 15
// speedup vs baseline: 1.0966x; 1.0107x over previous
#include <cuda_runtime.h>
#include <cuda_bf16.h>
#include <cstdint>

#define N_NODES 50000
#define N_EDGES 800000
#define N_GRAPH 500
#define DIM     128
#define EDIM    7
#define LAYERS  5
#define NCLASS  10
#define BN_EPS  1e-5f
#define NROWS_PAD 50048   // NTILES*128

typedef unsigned long long u64;

// ---------------- scratch ----------------
__device__ float g_x  [N_NODES * DIM];
__device__ float g_pool[N_GRAPH * DIM];

// bf16 hi/lo planes of (x + agg): edge-kernel output, MLP A input
__device__ __nv_bfloat16 g_Ah[(size_t)NROWS_PAD * DIM];
__device__ __nv_bfloat16 g_Al[(size_t)NROWS_PAD * DIM];

// CSR scratch
__device__ int   g_deg [N_NODES];
__device__ int   g_off [N_NODES + 1];
__device__ int   g_fill[N_NODES];
__device__ int   g_eid [N_EDGES];
__device__ int   g_esrc[N_EDGES];
__device__ float g_eattr[(size_t)N_EDGES * 8];   // attr in CSR order (padded to 8)

#define SCAN_BLOCKS ((N_NODES + 255) / 256)   // 196
__device__ int g_flag[SCAN_BLOCKS];
__device__ int g_aggr[SCAN_BLOCKS];
__device__ int g_incl[SCAN_BLOCKS];

// transposed + bf16-split weight images, row-major [o][k] (10 mats: l*2 + {W1,W2})
__device__ __nv_bfloat16 g_Wh[10 * 16384];
__device__ __nv_bfloat16 g_Wl[10 * 16384];

// ================= helpers =================
__device__ __forceinline__ uint32_t smem_u32(const void* p) {
    uint32_t a;
    asm("{ .reg .u64 t; cvta.to.shared.u64 t, %1; cvt.u32.u64 %0, t; }" : "=r"(a) : "l"(p));
    return a;
}
__device__ __forceinline__ void ldm4(uint32_t* r, uint32_t addr) {
    asm volatile("ldmatrix.sync.aligned.m8n8.x4.shared.b16 {%0,%1,%2,%3}, [%4];"
                 : "=r"(r[0]), "=r"(r[1]), "=r"(r[2]), "=r"(r[3]) : "r"(addr));
}
__device__ __forceinline__ void mma_bf16(float* c, const uint32_t* a, uint32_t b0, uint32_t b1) {
    asm volatile("mma.sync.aligned.m16n8k16.row.col.f32.bf16.bf16.f32 "
                 "{%0,%1,%2,%3}, {%4,%5,%6,%7}, {%8,%9}, {%0,%1,%2,%3};"
                 : "+f"(c[0]), "+f"(c[1]), "+f"(c[2]), "+f"(c[3])
                 : "r"(a[0]), "r"(a[1]), "r"(a[2]), "r"(a[3]), "r"(b0), "r"(b1));
}
__device__ __forceinline__ void cp16(uint32_t smem_dst, const void* gsrc) {
    asm volatile("cp.async.cg.shared.global [%0], [%1], 16;" :: "r"(smem_dst), "l"(gsrc));
}

// ---- packed f32x2 ----
__device__ __forceinline__ u64 fma2(u64 a, u64 b, u64 c) {
    u64 d;
    asm("fma.rn.f32x2 %0, %1, %2, %3;" : "=l"(d) : "l"(a), "l"(b), "l"(c));
    return d;
}
__device__ __forceinline__ u64 add2(u64 a, u64 b) {
    u64 d;
    asm("add.rn.f32x2 %0, %1, %2;" : "=l"(d) : "l"(a), "l"(b));
    return d;
}
__device__ __forceinline__ u64 packdup(float a) {
    u64 d;
    uint32_t u = __float_as_uint(a);
    asm("mov.b64 %0, {%1, %1};" : "=l"(d) : "r"(u));
    return d;
}
__device__ __forceinline__ u64 pack2(float a, float b) {
    u64 d;
    uint32_t ua = __float_as_uint(a), ub = __float_as_uint(b);
    asm("mov.b64 %0, {%1, %2};" : "=l"(d) : "r"(ua), "r"(ub));
    return d;
}
__device__ __forceinline__ float2 unpack2(u64 v) {
    uint32_t x, y;
    asm("mov.b64 {%0, %1}, %2;" : "=r"(x), "=r"(y) : "l"(v));
    return make_float2(__uint_as_float(x), __uint_as_float(y));
}

// split fp32x4 -> bf16 hi/lo and store 8B to each plane
__device__ __forceinline__ void store_split(__nv_bfloat16* Ah, __nv_bfloat16* Al,
                                            size_t idx, float4 acc) {
    __nv_bfloat162 h01 = __float22bfloat162_rn(make_float2(acc.x, acc.y));
    __nv_bfloat162 h23 = __float22bfloat162_rn(make_float2(acc.z, acc.w));
    float2 f01 = __bfloat1622float2(h01);
    float2 f23 = __bfloat1622float2(h23);
    __nv_bfloat162 l01 = __float22bfloat162_rn(make_float2(acc.x - f01.x, acc.y - f01.y));
    __nv_bfloat162 l23 = __float22bfloat162_rn(make_float2(acc.z - f23.x, acc.w - f23.y));
    uint2 hp = make_uint2(*reinterpret_cast<uint32_t*>(&h01), *reinterpret_cast<uint32_t*>(&h23));
    uint2 lp = make_uint2(*reinterpret_cast<uint32_t*>(&l01), *reinterpret_cast<uint32_t*>(&l23));
    *reinterpret_cast<uint2*>(Ah + idx) = hp;
    *reinterpret_cast<uint2*>(Al + idx) = lp;
}

// ---------------- weight prep ----------------
__global__ void k_prep_w(const float* __restrict__ W1, const float* __restrict__ W2) {
    int idx = blockIdx.x * blockDim.x + threadIdx.x;
    if (idx >= 10 * 16384) return;
    int mat = idx >> 14;
    int r = idx & 16383;
    int o = r >> 7, k = r & 127;
    int l = mat >> 1;
    const float* W = (mat & 1) ? (W2 + l * 16384) : (W1 + l * 16384);
    float x = W[k * 128 + o];
    __nv_bfloat16 h = __float2bfloat16(x);
    __nv_bfloat16 lo = __float2bfloat16(x - __bfloat162float(h));
    g_Wh[mat * 16384 + o * 128 + k] = h;
    g_Wl[mat * 16384 + o * 128 + k] = lo;
}

// ---------------- CSR build ----------------
__global__ void k_hist(const int* __restrict__ ei) {
    int e = blockIdx.x * blockDim.x + threadIdx.x;
    if (e < N_EDGES) atomicAdd(&g_deg[ei[N_EDGES + e]], 1);
}

// single-pass decoupled-lookback scan (integer, deterministic)
__global__ void __launch_bounds__(256) k_scan_lb() {
    __shared__ int sw[8];
    __shared__ int s_excl;
    int tid = threadIdx.x, lane = tid & 31, wid = tid >> 5;
    int bid = blockIdx.x;
    int i = bid * 256 + tid;
    int v = (i < N_NODES) ? g_deg[i] : 0;
    int x = v;
#pragma unroll
    for (int d = 1; d < 32; d <<= 1) {
        int t = __shfl_up_sync(0xffffffffu, x, d);
        if (lane >= d) x += t;
    }
    if (lane == 31) sw[wid] = x;
    __syncthreads();
    if (wid == 0 && lane < 8) {
        int y = sw[lane];
#pragma unroll
        for (int d = 1; d < 8; d <<= 1) {
            int t = __shfl_up_sync(0xffu, y, d);
            if (lane >= d) y += t;
        }
        sw[lane] = y;
    }
    __syncthreads();
    int blk_incl = sw[7];
    int x_blk = x + (wid ? sw[wid - 1] : 0);   // block-inclusive

    if (tid == 0) {
        if (bid == 0) {
            g_incl[0] = blk_incl;
            __threadfence();
            atomicExch(&g_flag[0], 2);
        } else {
            g_aggr[bid] = blk_incl;
            __threadfence();
            atomicExch(&g_flag[bid], 1);
        }
    }

    if (wid == 0) {
        int running = 0;
        if (bid > 0) {
            int idx = bid - 1;
            while (true) {
                int ii = idx - lane;
                int f;
                do {
                    f = (ii >= 0) ? atomicAdd(&g_flag[ii], 0) : 2;
                } while (__any_sync(0xffffffffu, f == 0 && ii >= 0));
                unsigned m2 = __ballot_sync(0xffffffffu, ii >= 0 && f == 2);
                int stop = m2 ? (__ffs(m2) - 1) : 32;
                int own = 0;
                if (ii >= 0 && lane < stop) own = g_aggr[ii];
                else if (m2 && lane == stop) own = g_incl[ii];
#pragma unroll
                for (int d = 16; d > 0; d >>= 1)
                    own += __shfl_down_sync(0xffffffffu, own, d);
                own = __shfl_sync(0xffffffffu, own, 0);
                running += own;
                if (m2) break;
                idx -= 32;
            }
            if (lane == 0) {
                g_incl[bid] = running + blk_incl;
                __threadfence();
                atomicExch(&g_flag[bid], 2);
            }
        }
        if (lane == 0) s_excl = running;
    }
    __syncthreads();
    int excl = s_excl + x_blk - v;
    if (i < N_NODES) { g_off[i] = excl; g_fill[i] = excl; }
    if (i == 0) g_off[N_NODES] = N_EDGES;
}

// phase 1: atomic slot assignment, single 4B random store
__global__ void k_scatter_idx(const int* __restrict__ ei) {
    int e = blockIdx.x * blockDim.x + threadIdx.x;
    if (e < N_EDGES) {
        int dst = ei[N_EDGES + e];
        int p = atomicAdd(&g_fill[dst], 1);
        g_eid[p] = e;
    }
}
// phase 2: coalesced CSR-order writes; random reads served from L2
__global__ void k_gather_attr(const int* __restrict__ ei, const float* __restrict__ attr) {
    int j = blockIdx.x * blockDim.x + threadIdx.x;
    if (j >= N_EDGES) return;
    int e = g_eid[j];
    g_esrc[j] = ei[e];
    const float* a = attr + (size_t)e * 7;
    float4 v0 = make_float4(a[0], a[1], a[2], a[3]);
    float4 v1 = make_float4(a[4], a[5], a[6], 0.0f);
    float4* d = reinterpret_cast<float4*>(g_eattr + (size_t)j * 8);
    d[0] = v0;
    d[1] = v1;
}

// ---------------- edge aggregation, 4-way pipelined, packed f32x2 (layers 1..4) ----------------
__global__ void __launch_bounds__(256) k_edge_csr(
    const float* __restrict__ eW, const float* __restrict__ eb)
{
    __shared__ ulonglong2 sW[EDIM * 32];
    __shared__ ulonglong2 sB[32];
    int tid = threadIdx.x;
    if (tid < EDIM * 32) sW[tid] = reinterpret_cast<const ulonglong2*>(eW)[tid];
    if (tid < 32)        sB[tid] = reinterpret_cast<const ulonglong2*>(eb)[tid];
    __syncthreads();

    int warp = tid >> 5, lane = tid & 31;
    int dst = blockIdx.x * 8 + warp;
    if (dst >= N_NODES) return;

    const ulonglong2* X2 = reinterpret_cast<const ulonglong2*>(g_x);
    ulonglong2 xd = X2[(size_t)dst * 32 + lane];
    u64 acc01 = xd.x, acc23 = xd.y;
    const u64 b01 = sB[lane].x, b23 = sB[lane].y;
    int j = g_off[dst], end = g_off[dst + 1];

    for (; j + 4 <= end; j += 4) {
        float av = g_eattr[(size_t)j * 8 + lane];
        int s0 = g_esrc[j + 0], s1 = g_esrc[j + 1];
        int s2 = g_esrc[j + 2], s3 = g_esrc[j + 3];
        ulonglong2 x0 = X2[(size_t)s0 * 32 + lane];
        ulonglong2 x1 = X2[(size_t)s1 * 32 + lane];
        ulonglong2 x2 = X2[(size_t)s2 * 32 + lane];
        ulonglong2 x3 = X2[(size_t)s3 * 32 + lane];
        u64 e01_0 = b01, e23_0 = b23, e01_1 = b01, e23_1 = b23;
        u64 e01_2 = b01, e23_2 = b23, e01_3 = b01, e23_3 = b23;
#pragma unroll
        for (int q = 0; q < EDIM; q++) {
            ulonglong2 w = sW[q * 32 + lane];
            u64 a0 = packdup(__shfl_sync(0xffffffffu, av, q));
            u64 a1 = packdup(__shfl_sync(0xffffffffu, av, 8 + q));
            u64 a2 = packdup(__shfl_sync(0xffffffffu, av, 16 + q));
            u64 a3 = packdup(__shfl_sync(0xffffffffu, av, 24 + q));
            e01_0 = fma2(a0, w.x, e01_0); e23_0 = fma2(a0, w.y, e23_0);
            e01_1 = fma2(a1, w.x, e01_1); e23_1 = fma2(a1, w.y, e23_1);
            e01_2 = fma2(a2, w.x, e01_2); e23_2 = fma2(a2, w.y, e23_2);
            e01_3 = fma2(a3, w.x, e01_3); e23_3 = fma2(a3, w.y, e23_3);
        }
        {
            float2 f01, f23;
            f01 = unpack2(add2(x0.x, e01_0)); f23 = unpack2(add2(x0.y, e23_0));
            acc01 = add2(acc01, pack2(fmaxf(f01.x, 0.f), fmaxf(f01.y, 0.f)));
            acc23 = add2(acc23, pack2(fmaxf(f23.x, 0.f), fmaxf(f23.y, 0.f)));
            f01 = unpack2(add2(x1.x, e01_1)); f23 = unpack2(add2(x1.y, e23_1));
            acc01 = add2(acc01, pack2(fmaxf(f01.x, 0.f), fmaxf(f01.y, 0.f)));
            acc23 = add2(acc23, pack2(fmaxf(f23.x, 0.f), fmaxf(f23.y, 0.f)));
            f01 = unpack2(add2(x2.x, e01_2)); f23 = unpack2(add2(x2.y, e23_2));
            acc01 = add2(acc01, pack2(fmaxf(f01.x, 0.f), fmaxf(f01.y, 0.f)));
            acc23 = add2(acc23, pack2(fmaxf(f23.x, 0.f), fmaxf(f23.y, 0.f)));
            f01 = unpack2(add2(x3.x, e01_3)); f23 = unpack2(add2(x3.y, e23_3));
            acc01 = add2(acc01, pack2(fmaxf(f01.x, 0.f), fmaxf(f01.y, 0.f)));
            acc23 = add2(acc23, pack2(fmaxf(f23.x, 0.f), fmaxf(f23.y, 0.f)));
        }
    }
    for (; j < end; j++) {
        int src = g_esrc[j];
        float v = (lane < EDIM) ? g_eattr[(size_t)j * 8 + lane] : 0.0f;
        u64 e01 = b01, e23 = b23;
#pragma unroll
        for (int q = 0; q < EDIM; q++) {
            ulonglong2 w = sW[q * 32 + lane];
            u64 a = packdup(__shfl_sync(0xffffffffu, v, q));
            e01 = fma2(a, w.x, e01);
            e23 = fma2(a, w.y, e23);
        }
        ulonglong2 xv = X2[(size_t)src * 32 + lane];
        float2 f01 = unpack2(add2(xv.x, e01));
        float2 f23 = unpack2(add2(xv.y, e23));
        acc01 = add2(acc01, pack2(fmaxf(f01.x, 0.f), fmaxf(f01.y, 0.f)));
        acc23 = add2(acc23, pack2(fmaxf(f23.x, 0.f), fmaxf(f23.y, 0.f)));
    }
    float2 a01 = unpack2(acc01), a23 = unpack2(acc23);
    store_split(g_Ah, g_Al, (size_t)dst * 128 + lane * 4,
                make_float4(a01.x, a01.y, a23.x, a23.y));
}

// ---------------- layer-0 edge ----------------
__global__ void __launch_bounds__(256) k_edge_l0(
    const float* __restrict__ node_emb,
    const float* __restrict__ eW, const float* __restrict__ eb)
{
    __shared__ ulonglong2 sW[EDIM * 32];
    __shared__ ulonglong2 sB[32];
    __shared__ ulonglong2 sE[32];
    int tid = threadIdx.x;
    if (tid < EDIM * 32) sW[tid] = reinterpret_cast<const ulonglong2*>(eW)[tid];
    if (tid < 32)        sB[tid] = reinterpret_cast<const ulonglong2*>(eb)[tid];
    if (tid >= 32 && tid < 64)
        sE[tid - 32] = reinterpret_cast<const ulonglong2*>(node_emb)[tid - 32];
    __syncthreads();

    int warp = tid >> 5, lane = tid & 31;
    int dst = blockIdx.x * 8 + warp;
    if (dst >= N_NODES) return;

    ulonglong2 em = sE[lane];
    u64 acc01 = em.x, acc23 = em.y;
    const u64 b01 = add2(sB[lane].x, em.x);
    const u64 b23 = add2(sB[lane].y, em.y);
    int j = g_off[dst], end = g_off[dst + 1];

    for (; j + 4 <= end; j += 4) {
        float av = g_eattr[(size_t)j * 8 + lane];
        u64 e01_0 = b01, e23_0 = b23, e01_1 = b01, e23_1 = b23;
        u64 e01_2 = b01, e23_2 = b23, e01_3 = b01, e23_3 = b23;
#pragma unroll
        for (int q = 0; q < EDIM; q++) {
            ulonglong2 w = sW[q * 32 + lane];
            u64 a0 = packdup(__shfl_sync(0xffffffffu, av, q));
            u64 a1 = packdup(__shfl_sync(0xffffffffu, av, 8 + q));
            u64 a2 = packdup(__shfl_sync(0xffffffffu, av, 16 + q));
            u64 a3 = packdup(__shfl_sync(0xffffffffu, av, 24 + q));
            e01_0 = fma2(a0, w.x, e01_0); e23_0 = fma2(a0, w.y, e23_0);
            e01_1 = fma2(a1, w.x, e01_1); e23_1 = fma2(a1, w.y, e23_1);
            e01_2 = fma2(a2, w.x, e01_2); e23_2 = fma2(a2, w.y, e23_2);
            e01_3 = fma2(a3, w.x, e01_3); e23_3 = fma2(a3, w.y, e23_3);
        }
        float2 f01, f23;
        f01 = unpack2(e01_0); f23 = unpack2(e23_0);
        acc01 = add2(acc01, pack2(fmaxf(f01.x, 0.f), fmaxf(f01.y, 0.f)));
        acc23 = add2(acc23, pack2(fmaxf(f23.x, 0.f), fmaxf(f23.y, 0.f)));
        f01 = unpack2(e01_1); f23 = unpack2(e23_1);
        acc01 = add2(acc01, pack2(fmaxf(f01.x, 0.f), fmaxf(f01.y, 0.f)));
        acc23 = add2(acc23, pack2(fmaxf(f23.x, 0.f), fmaxf(f23.y, 0.f)));
        f01 = unpack2(e01_2); f23 = unpack2(e23_2);
        acc01 = add2(acc01, pack2(fmaxf(f01.x, 0.f), fmaxf(f01.y, 0.f)));
        acc23 = add2(acc23, pack2(fmaxf(f23.x, 0.f), fmaxf(f23.y, 0.f)));
        f01 = unpack2(e01_3); f23 = unpack2(e23_3);
        acc01 = add2(acc01, pack2(fmaxf(f01.x, 0.f), fmaxf(f01.y, 0.f)));
        acc23 = add2(acc23, pack2(fmaxf(f23.x, 0.f), fmaxf(f23.y, 0.f)));
    }
    for (; j < end; j++) {
        float v = (lane < EDIM) ? g_eattr[(size_t)j * 8 + lane] : 0.0f;
        u64 e01 = b01, e23 = b23;
#pragma unroll
        for (int q = 0; q < EDIM; q++) {
            ulonglong2 w = sW[q * 32 + lane];
            u64 a = packdup(__shfl_sync(0xffffffffu, v, q));
            e01 = fma2(a, w.x, e01);
            e23 = fma2(a, w.y, e23);
        }
        float2 f01 = unpack2(e01), f23 = unpack2(e23);
        acc01 = add2(acc01, pack2(fmaxf(f01.x, 0.f), fmaxf(f01.y, 0.f)));
        acc23 = add2(acc23, pack2(fmaxf(f23.x, 0.f), fmaxf(f23.y, 0.f)));
    }
    float2 a01 = unpack2(acc01), a23 = unpack2(acc23);
    store_split(g_Ah, g_Al, (size_t)dst * 128 + lane * 4,
                make_float4(a01.x, a01.y, a23.x, a23.y));
}

// ---------------- fused per-layer MLP (with next-tile A prefetch) ----------------
#define PAD 136
#define WIMG (128 * PAD)
#define FUSED_SMEM (6 * WIMG * 2 + 2048)

__device__ __forceinline__ void gemm_128(float (&acc)[2][8][4],
    uint32_t adrAh, uint32_t adrAl, uint32_t adrBh, uint32_t adrBl)
{
#pragma unroll
    for (int mt = 0; mt < 2; mt++)
#pragma unroll
        for (int nt = 0; nt < 8; nt++)
#pragma unroll
            for (int q = 0; q < 4; q++) acc[mt][nt][q] = 0.0f;

#pragma unroll
    for (int ks = 0; ks < 8; ks++) {
        uint32_t k2 = ks * 32;
        uint32_t ah[2][4], al[2][4], bh[4][4], bl[4][4];
        ldm4(ah[0], adrAh + k2);
        ldm4(ah[1], adrAh + 16 * PAD * 2 + k2);
        ldm4(al[0], adrAl + k2);
        ldm4(al[1], adrAl + 16 * PAD * 2 + k2);
#pragma unroll
        for (int p = 0; p < 4; p++) {
            ldm4(bh[p], adrBh + p * 16 * PAD * 2 + k2);
            ldm4(bl[p], adrBl + p * 16 * PAD * 2 + k2);
        }
#pragma unroll
        for (int mt = 0; mt < 2; mt++)
#pragma unroll
            for (int nt = 0; nt < 8; nt++) {
                int p = nt >> 1, q = nt & 1;
                mma_bf16(acc[mt][nt], ah[mt], bh[p][q], bh[p][q + 2]);
                mma_bf16(acc[mt][nt], al[mt], bh[p][q], bh[p][q + 2]);
                mma_bf16(acc[mt][nt], ah[mt], bl[p][q], bl[p][q + 2]);
            }
    }
}

__global__ void __launch_bounds__(256, 1) k_mlp_fused(
    const __nv_bfloat16* __restrict__ Ah, const __nv_bfloat16* __restrict__ Al,
    float* __restrict__ out,
    const int* __restrict__ batch, int last,
    const __nv_bfloat16* __restrict__ W1h, const __nv_bfloat16* __restrict__ W1l,
    const __nv_bfloat16* __restrict__ W2h, const __nv_bfloat16* __restrict__ W2l,
    const float* __restrict__ b1,
    const float* __restrict__ g1, const float* __restrict__ bb1,
    const float* __restrict__ m1, const float* __restrict__ v1,
    const float* __restrict__ b2,
    const float* __restrict__ g2, const float* __restrict__ bb2,
    const float* __restrict__ m2, const float* __restrict__ v2)
{
    extern __shared__ char sm[];
    __nv_bfloat16* sW1h = reinterpret_cast<__nv_bfloat16*>(sm);
    __nv_bfloat16* sW1l = sW1h + WIMG;
    __nv_bfloat16* sW2h = sW1l + WIMG;
    __nv_bfloat16* sW2l = sW2h + WIMG;
    __nv_bfloat16* sAh  = sW2l + WIMG;
    __nv_bfloat16* sAl  = sAh + WIMG;
    float* S1 = reinterpret_cast<float*>(sAl + WIMG);
    float* T1 = S1 + 128;
    float* S2 = T1 + 128;
    float* T2 = S2 + 128;

    int tid = threadIdx.x, wid = tid >> 5, lane = tid & 31;
    uint32_t sAh_u = smem_u32(sAh);
    uint32_t sAl_u = smem_u32(sAl);

    const int NTILES = (N_NODES + 127) / 128;   // 391

    // prologue: prefetch first tile's A while loading W images
    {
        int t0 = blockIdx.x;
        int base = t0 * 128;
        for (int i = tid; i < 2048; i += 256) {
            int row = i >> 4, seg = (i & 15) * 8;
            uint32_t d = (uint32_t)((row * PAD + seg) * 2);
            size_t s = (size_t)(base + row) * 128 + seg;
            cp16(sAh_u + d, Ah + s);
            cp16(sAl_u + d, Al + s);
        }
        asm volatile("cp.async.commit_group;" ::: "memory");
    }
    for (int i = tid; i < 2048; i += 256) {
        int o = i >> 4, kc = (i & 15) * 8;
        *reinterpret_cast<uint4*>(sW1h + o * PAD + kc) = reinterpret_cast<const uint4*>(W1h)[i];
        *reinterpret_cast<uint4*>(sW1l + o * PAD + kc) = reinterpret_cast<const uint4*>(W1l)[i];
        *reinterpret_cast<uint4*>(sW2h + o * PAD + kc) = reinterpret_cast<const uint4*>(W2h)[i];
        *reinterpret_cast<uint4*>(sW2l + o * PAD + kc) = reinterpret_cast<const uint4*>(W2l)[i];
    }
    if (tid < 128) {
        float s1 = g1[tid] * rsqrtf(v1[tid] + BN_EPS);
        S1[tid] = s1;
        T1[tid] = (b1[tid] - m1[tid]) * s1 + bb1[tid];
        float s2 = g2[tid] * rsqrtf(v2[tid] + BN_EPS);
        S2[tid] = s2;
        T2[tid] = (b2[tid] - m2[tid]) * s2 + bb2[tid];
    }

    int wm = wid & 3, wn = wid >> 2;
    uint32_t aOff = ((uint32_t)(wm * 32 + (lane & 15)) * PAD + (lane >> 4) * 8) * 2;
    uint32_t bOff = ((uint32_t)(wn * 64 + (lane & 7) + ((lane >> 3) & 1) * 8) * PAD + (lane >> 4) * 8) * 2;
    uint32_t adrAh  = sAh_u + aOff;
    uint32_t adrAl  = sAl_u + aOff;
    uint32_t adrB1h = smem_u32(sW1h) + bOff;
    uint32_t adrB1l = smem_u32(sW1l) + bOff;
    uint32_t adrB2h = smem_u32(sW2h) + bOff;
    uint32_t adrB2l = smem_u32(sW2l) + bOff;

    for (int t = blockIdx.x; t < NTILES; t += gridDim.x) {
        int base = t * 128;
        asm volatile("cp.async.wait_group 0;" ::: "memory");
        __syncthreads();

        // ---- GEMM1 ----
        float acc[2][8][4];
        gemm_128(acc, adrAh, adrAl, adrB1h, adrB1l);
        __syncthreads();   // all warps done reading sA

        // ---- epilogue1: BN1 + ReLU -> bf16 split back into sA ----
#pragma unroll
        for (int mt = 0; mt < 2; mt++) {
            int r0 = wm * 32 + mt * 16 + (lane >> 2);
#pragma unroll
            for (int nt = 0; nt < 8; nt++) {
                int col = wn * 64 + nt * 8 + (lane & 3) * 2;
                float Sa = S1[col], Sb2 = S1[col + 1];
                float Ta = T1[col], Tb = T1[col + 1];
                float y0 = fmaxf(acc[mt][nt][0] * Sa + Ta, 0.0f);
                float y1 = fmaxf(acc[mt][nt][1] * Sb2 + Tb, 0.0f);
                float y2 = fmaxf(acc[mt][nt][2] * Sa + Ta, 0.0f);
                float y3 = fmaxf(acc[mt][nt][3] * Sb2 + Tb, 0.0f);
                __nv_bfloat162 h0 = __float22bfloat162_rn(make_float2(y0, y1));
                __nv_bfloat162 h1 = __float22bfloat162_rn(make_float2(y2, y3));
                float2 f0 = __bfloat1622float2(h0);
                float2 f1 = __bfloat1622float2(h1);
                __nv_bfloat162 l0 = __float22bfloat162_rn(make_float2(y0 - f0.x, y1 - f0.y));
                __nv_bfloat162 l1 = __float22bfloat162_rn(make_float2(y2 - f1.x, y3 - f1.y));
                *reinterpret_cast<uint32_t*>(sAh + r0 * PAD + col) = *reinterpret_cast<uint32_t*>(&h0);
                *reinterpret_cast<uint32_t*>(sAl + r0 * PAD + col) = *reinterpret_cast<uint32_t*>(&l0);
                *reinterpret_cast<uint32_t*>(sAh + (r0 + 8) * PAD + col) = *reinterpret_cast<uint32_t*>(&h1);
                *reinterpret_cast<uint32_t*>(sAl + (r0 + 8) * PAD + col) = *reinterpret_cast<uint32_t*>(&l1);
            }
        }
        __syncthreads();

        // ---- GEMM2 ----
        gemm_128(acc, adrAh, adrAl, adrB2h, adrB2l);
        __syncthreads();   // all warps done reading sA -> safe to prefetch next tile

        // ---- prefetch next tile's A (overlaps epilogue2 stores) ----
        int tn = t + gridDim.x;
        if (tn < NTILES) {
            int nb = tn * 128;
            for (int i = tid; i < 2048; i += 256) {
                int row = i >> 4, seg = (i & 15) * 8;
                uint32_t d = (uint32_t)((row * PAD + seg) * 2);
                size_t s = (size_t)(nb + row) * 128 + seg;
                cp16(sAh_u + d, Ah + s);
                cp16(sAl_u + d, Al + s);
            }
        }
        asm volatile("cp.async.commit_group;" ::: "memory");

        // ---- epilogue2: BN2 + ReLU -> global x, or fused pool atomics on last layer ----
#pragma unroll
        for (int mt = 0; mt < 2; mt++) {
            int r0 = base + wm * 32 + mt * 16 + (lane >> 2);
            int c0 = (last && r0 < N_NODES) ? batch[r0] : 0;
            int c1 = (last && r0 + 8 < N_NODES) ? batch[r0 + 8] : 0;
#pragma unroll
            for (int nt = 0; nt < 8; nt++) {
                int col = wn * 64 + nt * 8 + (lane & 3) * 2;
                float Sa = S2[col], Sb2 = S2[col + 1];
                float Ta = T2[col], Tb = T2[col + 1];
                if (r0 < N_NODES) {
                    float2 v;
                    v.x = fmaxf(acc[mt][nt][0] * Sa + Ta, 0.0f);
                    v.y = fmaxf(acc[mt][nt][1] * Sb2 + Tb, 0.0f);
                    if (last) atomicAdd(reinterpret_cast<float2*>(g_pool + (size_t)c0 * 128 + col), v);
                    else *reinterpret_cast<float2*>(out + (size_t)r0 * 128 + col) = v;
                }
                if (r0 + 8 < N_NODES) {
                    float2 v;
                    v.x = fmaxf(acc[mt][nt][2] * Sa + Ta, 0.0f);
                    v.y = fmaxf(acc[mt][nt][3] * Sb2 + Tb, 0.0f);
                    if (last) atomicAdd(reinterpret_cast<float2*>(g_pool + (size_t)c1 * 128 + col), v);
                    else *reinterpret_cast<float2*>(out + (size_t)(r0 + 8) * 128 + col) = v;
                }
            }
        }
    }
}

// ---------------- head (graph count via binary search on sorted batch) ----------------
__global__ void k_head(const int* __restrict__ batch,
                       const float* __restrict__ W1, const float* __restrict__ b1,
                       const float* __restrict__ W2, const float* __restrict__ b2,
                       float* __restrict__ out)
{
    __shared__ float sg[DIM];
    __shared__ float sh[DIM];
    int c = blockIdx.x;
    int t = threadIdx.x;
    int lo = 0, hi = N_NODES;
    while (lo < hi) { int m = (lo + hi) >> 1; if (batch[m] < c) lo = m + 1; else hi = m; }
    int lo2 = lo, hi2 = N_NODES;
    while (lo2 < hi2) { int m = (lo2 + hi2) >> 1; if (batch[m] < c + 1) lo2 = m + 1; else hi2 = m; }
    float cnt = fmaxf((float)(lo2 - lo), 1.0f);
    sg[t] = g_pool[c * DIM + t] / cnt;
    __syncthreads();
    float acc = b1[t];
#pragma unroll 8
    for (int k = 0; k < DIM; k++) acc += sg[k] * W1[k * DIM + t];
    sh[t] = fmaxf(acc, 0.0f);
    __syncthreads();
    if (t < NCLASS) {
        float o2 = b2[t];
#pragma unroll 8
        for (int k = 0; k < DIM; k++) o2 += sh[k] * W2[k * NCLASS + t];
        out[c * NCLASS + t] = o2;
    }
}

// ---------------- launch ----------------
extern "C" void kernel_launch(void* const* d_in, const int* in_sizes, int n_in,
                              void* d_out, int out_size)
{
    const float* edge_attr = (const float*)d_in[0];
    const int*   edge_index= (const int*)  d_in[1];
    const int*   batch     = (const int*)  d_in[2];
    const float* node_emb  = (const float*)d_in[3];
    const float* edge_W    = (const float*)d_in[4];
    const float* edge_b    = (const float*)d_in[5];
    const float* mlp_W1    = (const float*)d_in[6];
    const float* mlp_b1    = (const float*)d_in[7];
    const float* bn1_g     = (const float*)d_in[8];
    const float* bn1_b     = (const float*)d_in[9];
    const float* bn1_m     = (const float*)d_in[10];
    const float* bn1_v     = (const float*)d_in[11];
    const float* mlp_W2    = (const float*)d_in[12];
    const float* mlp_b2    = (const float*)d_in[13];
    const float* bn2_g     = (const float*)d_in[14];
    const float* bn2_b     = (const float*)d_in[15];
    const float* bn2_m     = (const float*)d_in[16];
    const float* bn2_v     = (const float*)d_in[17];
    const float* head_W1   = (const float*)d_in[18];
    const float* head_b1   = (const float*)d_in[19];
    const float* head_W2   = (const float*)d_in[20];
    const float* head_b2   = (const float*)d_in[21];
    float* out = (float*)d_out;

    cudaFuncSetAttribute(k_mlp_fused, cudaFuncAttributeMaxDynamicSharedMemorySize, FUSED_SMEM);

    float *px, *ppool;
    int *pdeg, *pflag;
    __nv_bfloat16 *pwh, *pwl, *pah, *pal;
    cudaGetSymbolAddress((void**)&px,    g_x);
    cudaGetSymbolAddress((void**)&ppool, g_pool);
    cudaGetSymbolAddress((void**)&pdeg,  g_deg);
    cudaGetSymbolAddress((void**)&pflag, g_flag);
    cudaGetSymbolAddress((void**)&pwh,   g_Wh);
    cudaGetSymbolAddress((void**)&pwl,   g_Wl);
    cudaGetSymbolAddress((void**)&pah,   g_Ah);
    cudaGetSymbolAddress((void**)&pal,   g_Al);

    // zeroing via async memsets (graph-capturable)
    cudaMemsetAsync(pdeg,  0, N_NODES * sizeof(int));
    cudaMemsetAsync(pflag, 0, SCAN_BLOCKS * sizeof(int));
    cudaMemsetAsync(ppool, 0, N_GRAPH * DIM * sizeof(float));

    // weight prep + CSR build (deterministic each replay)
    k_prep_w<<<(10 * 16384 + 255) / 256, 256>>>(mlp_W1, mlp_W2);
    k_hist<<<(N_EDGES + 255) / 256, 256>>>(edge_index);
    k_scan_lb<<<SCAN_BLOCKS, 256>>>();
    k_scatter_idx<<<(N_EDGES + 255) / 256, 256>>>(edge_index);
    k_gather_attr<<<(N_EDGES + 255) / 256, 256>>>(edge_index, edge_attr);

    const int TC_GRID = 148;
    for (int l = 0; l < LAYERS; l++) {
        if (l == 0)
            k_edge_l0<<<(N_NODES + 7) / 8, 256>>>(node_emb, edge_W, edge_b);
        else
            k_edge_csr<<<(N_NODES + 7) / 8, 256>>>(edge_W + l * EDIM * DIM, edge_b + l * DIM);
        int m1 = l * 2, m2 = l * 2 + 1;
        k_mlp_fused<<<TC_GRID, 256, FUSED_SMEM>>>(
            pah, pal, px,
            batch, (l == LAYERS - 1) ? 1 : 0,
            pwh + m1 * 16384, pwl + m1 * 16384,
            pwh + m2 * 16384, pwl + m2 * 16384,
            mlp_b1 + l * DIM, bn1_g + l * DIM, bn1_b + l * DIM, bn1_m + l * DIM, bn1_v + l * DIM,
            mlp_b2 + l * DIM, bn2_g + l * DIM, bn2_b + l * DIM, bn2_m + l * DIM, bn2_v + l * DIM);
    }

    k_head<<<N_GRAPH, DIM>>>(batch, head_W1, head_b1, head_W2, head_b2, out);
}

// round 16
// speedup vs baseline: 1.2221x; 1.1145x over previous
#include <cuda_runtime.h>
#include <cuda_bf16.h>
#include <cstdint>

#define N_NODES 50000
#define N_EDGES 800000
#define N_GRAPH 500
#define DIM     128
#define EDIM    7
#define LAYERS  5
#define NCLASS  10
#define BN_EPS  1e-5f
#define NROWS_PAD 50048   // NTILES*128

typedef unsigned long long u64;

// ---------------- scratch ----------------
__device__ float g_x  [N_NODES * DIM];
__device__ float g_pool[N_GRAPH * DIM];
__device__ int   g_ctr [8];               // work-stealing counters (one per layer)

// bf16 hi/lo planes of (x + agg): edge-kernel output, MLP A input
__device__ __nv_bfloat16 g_Ah[(size_t)NROWS_PAD * DIM];
__device__ __nv_bfloat16 g_Al[(size_t)NROWS_PAD * DIM];

// CSR scratch
__device__ int   g_deg [N_NODES];
__device__ int   g_off [N_NODES + 1];
__device__ int   g_fill[N_NODES];
__device__ int   g_eid [N_EDGES];
__device__ int   g_esrc[N_EDGES];
__device__ float g_eattr[(size_t)N_EDGES * 8];   // attr in CSR order (padded to 8)

#define SCAN_BLOCKS ((N_NODES + 255) / 256)   // 196
__device__ int g_flag[SCAN_BLOCKS];
__device__ int g_aggr[SCAN_BLOCKS];
__device__ int g_incl[SCAN_BLOCKS];

// transposed + bf16-split weight images, row-major [o][k] (10 mats: l*2 + {W1,W2})
__device__ __nv_bfloat16 g_Wh[10 * 16384];
__device__ __nv_bfloat16 g_Wl[10 * 16384];

// ================= helpers =================
__device__ __forceinline__ uint32_t smem_u32(const void* p) {
    uint32_t a;
    asm("{ .reg .u64 t; cvta.to.shared.u64 t, %1; cvt.u32.u64 %0, t; }" : "=r"(a) : "l"(p));
    return a;
}
__device__ __forceinline__ void ldm4(uint32_t* r, uint32_t addr) {
    asm volatile("ldmatrix.sync.aligned.m8n8.x4.shared.b16 {%0,%1,%2,%3}, [%4];"
                 : "=r"(r[0]), "=r"(r[1]), "=r"(r[2]), "=r"(r[3]) : "r"(addr));
}
__device__ __forceinline__ void mma_bf16(float* c, const uint32_t* a, uint32_t b0, uint32_t b1) {
    asm volatile("mma.sync.aligned.m16n8k16.row.col.f32.bf16.bf16.f32 "
                 "{%0,%1,%2,%3}, {%4,%5,%6,%7}, {%8,%9}, {%0,%1,%2,%3};"
                 : "+f"(c[0]), "+f"(c[1]), "+f"(c[2]), "+f"(c[3])
                 : "r"(a[0]), "r"(a[1]), "r"(a[2]), "r"(a[3]), "r"(b0), "r"(b1));
}
__device__ __forceinline__ void cp16(uint32_t smem_dst, const void* gsrc) {
    asm volatile("cp.async.cg.shared.global [%0], [%1], 16;" :: "r"(smem_dst), "l"(gsrc));
}

// ---- packed f32x2 ----
__device__ __forceinline__ u64 fma2(u64 a, u64 b, u64 c) {
    u64 d;
    asm("fma.rn.f32x2 %0, %1, %2, %3;" : "=l"(d) : "l"(a), "l"(b), "l"(c));
    return d;
}
__device__ __forceinline__ u64 add2(u64 a, u64 b) {
    u64 d;
    asm("add.rn.f32x2 %0, %1, %2;" : "=l"(d) : "l"(a), "l"(b));
    return d;
}
__device__ __forceinline__ u64 packdup(float a) {
    u64 d;
    uint32_t u = __float_as_uint(a);
    asm("mov.b64 %0, {%1, %1};" : "=l"(d) : "r"(u));
    return d;
}
__device__ __forceinline__ u64 pack2(float a, float b) {
    u64 d;
    uint32_t ua = __float_as_uint(a), ub = __float_as_uint(b);
    asm("mov.b64 %0, {%1, %2};" : "=l"(d) : "r"(ua), "r"(ub));
    return d;
}
__device__ __forceinline__ float2 unpack2(u64 v) {
    uint32_t x, y;
    asm("mov.b64 {%0, %1}, %2;" : "=r"(x), "=r"(y) : "l"(v));
    return make_float2(__uint_as_float(x), __uint_as_float(y));
}

// split fp32x4 -> bf16 hi/lo and store 8B to each plane
__device__ __forceinline__ void store_split(__nv_bfloat16* Ah, __nv_bfloat16* Al,
                                            size_t idx, float4 acc) {
    __nv_bfloat162 h01 = __float22bfloat162_rn(make_float2(acc.x, acc.y));
    __nv_bfloat162 h23 = __float22bfloat162_rn(make_float2(acc.z, acc.w));
    float2 f01 = __bfloat1622float2(h01);
    float2 f23 = __bfloat1622float2(h23);
    __nv_bfloat162 l01 = __float22bfloat162_rn(make_float2(acc.x - f01.x, acc.y - f01.y));
    __nv_bfloat162 l23 = __float22bfloat162_rn(make_float2(acc.z - f23.x, acc.w - f23.y));
    uint2 hp = make_uint2(*reinterpret_cast<uint32_t*>(&h01), *reinterpret_cast<uint32_t*>(&h23));
    uint2 lp = make_uint2(*reinterpret_cast<uint32_t*>(&l01), *reinterpret_cast<uint32_t*>(&l23));
    *reinterpret_cast<uint2*>(Ah + idx) = hp;
    *reinterpret_cast<uint2*>(Al + idx) = lp;
}

// ---------------- weight prep ----------------
__global__ void k_prep_w(const float* __restrict__ W1, const float* __restrict__ W2) {
    int idx = blockIdx.x * blockDim.x + threadIdx.x;
    if (idx >= 10 * 16384) return;
    int mat = idx >> 14;
    int r = idx & 16383;
    int o = r >> 7, k = r & 127;
    int l = mat >> 1;
    const float* W = (mat & 1) ? (W2 + l * 16384) : (W1 + l * 16384);
    float x = W[k * 128 + o];
    __nv_bfloat16 h = __float2bfloat16(x);
    __nv_bfloat16 lo = __float2bfloat16(x - __bfloat162float(h));
    g_Wh[mat * 16384 + o * 128 + k] = h;
    g_Wl[mat * 16384 + o * 128 + k] = lo;
}

// ---------------- CSR build ----------------
__global__ void k_hist(const int* __restrict__ ei) {
    int e = blockIdx.x * blockDim.x + threadIdx.x;
    if (e < N_EDGES) atomicAdd(&g_deg[ei[N_EDGES + e]], 1);
}

// single-pass decoupled-lookback scan (integer, deterministic)
__global__ void __launch_bounds__(256) k_scan_lb() {
    __shared__ int sw[8];
    __shared__ int s_excl;
    int tid = threadIdx.x, lane = tid & 31, wid = tid >> 5;
    int bid = blockIdx.x;
    int i = bid * 256 + tid;
    int v = (i < N_NODES) ? g_deg[i] : 0;
    int x = v;
#pragma unroll
    for (int d = 1; d < 32; d <<= 1) {
        int t = __shfl_up_sync(0xffffffffu, x, d);
        if (lane >= d) x += t;
    }
    if (lane == 31) sw[wid] = x;
    __syncthreads();
    if (wid == 0 && lane < 8) {
        int y = sw[lane];
#pragma unroll
        for (int d = 1; d < 8; d <<= 1) {
            int t = __shfl_up_sync(0xffu, y, d);
            if (lane >= d) y += t;
        }
        sw[lane] = y;
    }
    __syncthreads();
    int blk_incl = sw[7];
    int x_blk = x + (wid ? sw[wid - 1] : 0);

    if (tid == 0) {
        if (bid == 0) {
            g_incl[0] = blk_incl;
            __threadfence();
            atomicExch(&g_flag[0], 2);
        } else {
            g_aggr[bid] = blk_incl;
            __threadfence();
            atomicExch(&g_flag[bid], 1);
        }
    }

    if (wid == 0) {
        int running = 0;
        if (bid > 0) {
            int idx = bid - 1;
            while (true) {
                int ii = idx - lane;
                int f;
                do {
                    f = (ii >= 0) ? atomicAdd(&g_flag[ii], 0) : 2;
                } while (__any_sync(0xffffffffu, f == 0 && ii >= 0));
                unsigned m2 = __ballot_sync(0xffffffffu, ii >= 0 && f == 2);
                int stop = m2 ? (__ffs(m2) - 1) : 32;
                int own = 0;
                if (ii >= 0 && lane < stop) own = g_aggr[ii];
                else if (m2 && lane == stop) own = g_incl[ii];
#pragma unroll
                for (int d = 16; d > 0; d >>= 1)
                    own += __shfl_down_sync(0xffffffffu, own, d);
                own = __shfl_sync(0xffffffffu, own, 0);
                running += own;
                if (m2) break;
                idx -= 32;
            }
            if (lane == 0) {
                g_incl[bid] = running + blk_incl;
                __threadfence();
                atomicExch(&g_flag[bid], 2);
            }
        }
        if (lane == 0) s_excl = running;
    }
    __syncthreads();
    int excl = s_excl + x_blk - v;
    if (i < N_NODES) { g_off[i] = excl; g_fill[i] = excl; }
    if (i == 0) g_off[N_NODES] = N_EDGES;
}

// phase 1: atomic slot assignment, single 4B random store
__global__ void k_scatter_idx(const int* __restrict__ ei) {
    int e = blockIdx.x * blockDim.x + threadIdx.x;
    if (e < N_EDGES) {
        int dst = ei[N_EDGES + e];
        int p = atomicAdd(&g_fill[dst], 1);
        g_eid[p] = e;
    }
}
// phase 2: coalesced CSR-order writes; random reads served from L2
__global__ void k_gather_attr(const int* __restrict__ ei, const float* __restrict__ attr) {
    int j = blockIdx.x * blockDim.x + threadIdx.x;
    if (j >= N_EDGES) return;
    int e = g_eid[j];
    g_esrc[j] = ei[e];
    const float* a = attr + (size_t)e * 7;
    float4 v0 = make_float4(a[0], a[1], a[2], a[3]);
    float4 v1 = make_float4(a[4], a[5], a[6], 0.0f);
    float4* d = reinterpret_cast<float4*>(g_eattr + (size_t)j * 8);
    d[0] = v0;
    d[1] = v1;
}

// ---------------- per-node edge body (packed f32x2) ----------------
__device__ __forceinline__ void edge_node_body(
    int dst, int lane, const ulonglong2* X2,
    const ulonglong2* sW, u64 b01, u64 b23)
{
    ulonglong2 xd = X2[(size_t)dst * 32 + lane];
    u64 acc01 = xd.x, acc23 = xd.y;
    int j = g_off[dst], end = g_off[dst + 1];

    for (; j + 4 <= end; j += 4) {
        float av = g_eattr[(size_t)j * 8 + lane];
        int s0 = g_esrc[j + 0], s1 = g_esrc[j + 1];
        int s2 = g_esrc[j + 2], s3 = g_esrc[j + 3];
        ulonglong2 x0 = X2[(size_t)s0 * 32 + lane];
        ulonglong2 x1 = X2[(size_t)s1 * 32 + lane];
        ulonglong2 x2 = X2[(size_t)s2 * 32 + lane];
        ulonglong2 x3 = X2[(size_t)s3 * 32 + lane];
        u64 e01_0 = b01, e23_0 = b23, e01_1 = b01, e23_1 = b23;
        u64 e01_2 = b01, e23_2 = b23, e01_3 = b01, e23_3 = b23;
#pragma unroll
        for (int q = 0; q < EDIM; q++) {
            ulonglong2 w = sW[q * 32 + lane];
            u64 a0 = packdup(__shfl_sync(0xffffffffu, av, q));
            u64 a1 = packdup(__shfl_sync(0xffffffffu, av, 8 + q));
            u64 a2 = packdup(__shfl_sync(0xffffffffu, av, 16 + q));
            u64 a3 = packdup(__shfl_sync(0xffffffffu, av, 24 + q));
            e01_0 = fma2(a0, w.x, e01_0); e23_0 = fma2(a0, w.y, e23_0);
            e01_1 = fma2(a1, w.x, e01_1); e23_1 = fma2(a1, w.y, e23_1);
            e01_2 = fma2(a2, w.x, e01_2); e23_2 = fma2(a2, w.y, e23_2);
            e01_3 = fma2(a3, w.x, e01_3); e23_3 = fma2(a3, w.y, e23_3);
        }
        float2 f01, f23;
        f01 = unpack2(add2(x0.x, e01_0)); f23 = unpack2(add2(x0.y, e23_0));
        acc01 = add2(acc01, pack2(fmaxf(f01.x, 0.f), fmaxf(f01.y, 0.f)));
        acc23 = add2(acc23, pack2(fmaxf(f23.x, 0.f), fmaxf(f23.y, 0.f)));
        f01 = unpack2(add2(x1.x, e01_1)); f23 = unpack2(add2(x1.y, e23_1));
        acc01 = add2(acc01, pack2(fmaxf(f01.x, 0.f), fmaxf(f01.y, 0.f)));
        acc23 = add2(acc23, pack2(fmaxf(f23.x, 0.f), fmaxf(f23.y, 0.f)));
        f01 = unpack2(add2(x2.x, e01_2)); f23 = unpack2(add2(x2.y, e23_2));
        acc01 = add2(acc01, pack2(fmaxf(f01.x, 0.f), fmaxf(f01.y, 0.f)));
        acc23 = add2(acc23, pack2(fmaxf(f23.x, 0.f), fmaxf(f23.y, 0.f)));
        f01 = unpack2(add2(x3.x, e01_3)); f23 = unpack2(add2(x3.y, e23_3));
        acc01 = add2(acc01, pack2(fmaxf(f01.x, 0.f), fmaxf(f01.y, 0.f)));
        acc23 = add2(acc23, pack2(fmaxf(f23.x, 0.f), fmaxf(f23.y, 0.f)));
    }
    for (; j < end; j++) {
        int src = g_esrc[j];
        float v = (lane < EDIM) ? g_eattr[(size_t)j * 8 + lane] : 0.0f;
        u64 e01 = b01, e23 = b23;
#pragma unroll
        for (int q = 0; q < EDIM; q++) {
            ulonglong2 w = sW[q * 32 + lane];
            u64 a = packdup(__shfl_sync(0xffffffffu, v, q));
            e01 = fma2(a, w.x, e01);
            e23 = fma2(a, w.y, e23);
        }
        ulonglong2 xv = X2[(size_t)src * 32 + lane];
        float2 f01 = unpack2(add2(xv.x, e01));
        float2 f23 = unpack2(add2(xv.y, e23));
        acc01 = add2(acc01, pack2(fmaxf(f01.x, 0.f), fmaxf(f01.y, 0.f)));
        acc23 = add2(acc23, pack2(fmaxf(f23.x, 0.f), fmaxf(f23.y, 0.f)));
    }
    float2 a01 = unpack2(acc01), a23 = unpack2(acc23);
    store_split(g_Ah, g_Al, (size_t)dst * 128 + lane * 4,
                make_float4(a01.x, a01.y, a23.x, a23.y));
}

// ---------------- edge aggregation, work-stealing (layers 1..4) ----------------
#define STEAL_CHUNK 2
__global__ void __launch_bounds__(256) k_edge_csr(
    const float* __restrict__ eW, const float* __restrict__ eb, int lidx)
{
    __shared__ ulonglong2 sW[EDIM * 32];
    __shared__ ulonglong2 sB[32];
    int tid = threadIdx.x;
    if (tid < EDIM * 32) sW[tid] = reinterpret_cast<const ulonglong2*>(eW)[tid];
    if (tid < 32)        sB[tid] = reinterpret_cast<const ulonglong2*>(eb)[tid];
    __syncthreads();

    int lane = tid & 31;
    const ulonglong2* X2 = reinterpret_cast<const ulonglong2*>(g_x);
    const u64 b01 = sB[lane].x, b23 = sB[lane].y;

    for (;;) {
        int n0;
        if (lane == 0) n0 = atomicAdd(&g_ctr[lidx], STEAL_CHUNK);
        n0 = __shfl_sync(0xffffffffu, n0, 0);
        if (n0 >= N_NODES) break;
#pragma unroll
        for (int k = 0; k < STEAL_CHUNK; k++) {
            int dst = n0 + k;
            if (dst < N_NODES)
                edge_node_body(dst, lane, X2, sW, b01, b23);
        }
    }
}

// ---------------- layer-0 edge: x[src] == node_emb (no gather), work-stealing ----------------
__device__ __forceinline__ void edge_node_body_l0(
    int dst, int lane, const ulonglong2* sW,
    u64 b01, u64 b23, u64 em01, u64 em23)
{
    u64 acc01 = em01, acc23 = em23;
    int j = g_off[dst], end = g_off[dst + 1];

    for (; j + 4 <= end; j += 4) {
        float av = g_eattr[(size_t)j * 8 + lane];
        u64 e01_0 = b01, e23_0 = b23, e01_1 = b01, e23_1 = b23;
        u64 e01_2 = b01, e23_2 = b23, e01_3 = b01, e23_3 = b23;
#pragma unroll
        for (int q = 0; q < EDIM; q++) {
            ulonglong2 w = sW[q * 32 + lane];
            u64 a0 = packdup(__shfl_sync(0xffffffffu, av, q));
            u64 a1 = packdup(__shfl_sync(0xffffffffu, av, 8 + q));
            u64 a2 = packdup(__shfl_sync(0xffffffffu, av, 16 + q));
            u64 a3 = packdup(__shfl_sync(0xffffffffu, av, 24 + q));
            e01_0 = fma2(a0, w.x, e01_0); e23_0 = fma2(a0, w.y, e23_0);
            e01_1 = fma2(a1, w.x, e01_1); e23_1 = fma2(a1, w.y, e23_1);
            e01_2 = fma2(a2, w.x, e01_2); e23_2 = fma2(a2, w.y, e23_2);
            e01_3 = fma2(a3, w.x, e01_3); e23_3 = fma2(a3, w.y, e23_3);
        }
        float2 f01, f23;
        f01 = unpack2(e01_0); f23 = unpack2(e23_0);
        acc01 = add2(acc01, pack2(fmaxf(f01.x, 0.f), fmaxf(f01.y, 0.f)));
        acc23 = add2(acc23, pack2(fmaxf(f23.x, 0.f), fmaxf(f23.y, 0.f)));
        f01 = unpack2(e01_1); f23 = unpack2(e23_1);
        acc01 = add2(acc01, pack2(fmaxf(f01.x, 0.f), fmaxf(f01.y, 0.f)));
        acc23 = add2(acc23, pack2(fmaxf(f23.x, 0.f), fmaxf(f23.y, 0.f)));
        f01 = unpack2(e01_2); f23 = unpack2(e23_2);
        acc01 = add2(acc01, pack2(fmaxf(f01.x, 0.f), fmaxf(f01.y, 0.f)));
        acc23 = add2(acc23, pack2(fmaxf(f23.x, 0.f), fmaxf(f23.y, 0.f)));
        f01 = unpack2(e01_3); f23 = unpack2(e23_3);
        acc01 = add2(acc01, pack2(fmaxf(f01.x, 0.f), fmaxf(f01.y, 0.f)));
        acc23 = add2(acc23, pack2(fmaxf(f23.x, 0.f), fmaxf(f23.y, 0.f)));
    }
    for (; j < end; j++) {
        float v = (lane < EDIM) ? g_eattr[(size_t)j * 8 + lane] : 0.0f;
        u64 e01 = b01, e23 = b23;
#pragma unroll
        for (int q = 0; q < EDIM; q++) {
            ulonglong2 w = sW[q * 32 + lane];
            u64 a = packdup(__shfl_sync(0xffffffffu, v, q));
            e01 = fma2(a, w.x, e01);
            e23 = fma2(a, w.y, e23);
        }
        float2 f01 = unpack2(e01), f23 = unpack2(e23);
        acc01 = add2(acc01, pack2(fmaxf(f01.x, 0.f), fmaxf(f01.y, 0.f)));
        acc23 = add2(acc23, pack2(fmaxf(f23.x, 0.f), fmaxf(f23.y, 0.f)));
    }
    float2 a01 = unpack2(acc01), a23 = unpack2(acc23);
    store_split(g_Ah, g_Al, (size_t)dst * 128 + lane * 4,
                make_float4(a01.x, a01.y, a23.x, a23.y));
}

__global__ void __launch_bounds__(256) k_edge_l0(
    const float* __restrict__ node_emb,
    const float* __restrict__ eW, const float* __restrict__ eb)
{
    __shared__ ulonglong2 sW[EDIM * 32];
    __shared__ ulonglong2 sB[32];
    __shared__ ulonglong2 sE[32];
    int tid = threadIdx.x;
    if (tid < EDIM * 32) sW[tid] = reinterpret_cast<const ulonglong2*>(eW)[tid];
    if (tid < 32)        sB[tid] = reinterpret_cast<const ulonglong2*>(eb)[tid];
    if (tid >= 32 && tid < 64)
        sE[tid - 32] = reinterpret_cast<const ulonglong2*>(node_emb)[tid - 32];
    __syncthreads();

    int lane = tid & 31;
    ulonglong2 em = sE[lane];
    const u64 b01 = add2(sB[lane].x, em.x);
    const u64 b23 = add2(sB[lane].y, em.y);

    for (;;) {
        int n0;
        if (lane == 0) n0 = atomicAdd(&g_ctr[0], STEAL_CHUNK);
        n0 = __shfl_sync(0xffffffffu, n0, 0);
        if (n0 >= N_NODES) break;
#pragma unroll
        for (int k = 0; k < STEAL_CHUNK; k++) {
            int dst = n0 + k;
            if (dst < N_NODES)
                edge_node_body_l0(dst, lane, sW, b01, b23, em.x, em.y);
        }
    }
}

// ---------------- fused per-layer MLP (with next-tile A prefetch) ----------------
#define PAD 136
#define WIMG (128 * PAD)
#define FUSED_SMEM (6 * WIMG * 2 + 2048)

__device__ __forceinline__ void gemm_128(float (&acc)[2][8][4],
    uint32_t adrAh, uint32_t adrAl, uint32_t adrBh, uint32_t adrBl)
{
#pragma unroll
    for (int mt = 0; mt < 2; mt++)
#pragma unroll
        for (int nt = 0; nt < 8; nt++)
#pragma unroll
            for (int q = 0; q < 4; q++) acc[mt][nt][q] = 0.0f;

#pragma unroll
    for (int ks = 0; ks < 8; ks++) {
        uint32_t k2 = ks * 32;
        uint32_t ah[2][4], al[2][4], bh[4][4], bl[4][4];
        ldm4(ah[0], adrAh + k2);
        ldm4(ah[1], adrAh + 16 * PAD * 2 + k2);
        ldm4(al[0], adrAl + k2);
        ldm4(al[1], adrAl + 16 * PAD * 2 + k2);
#pragma unroll
        for (int p = 0; p < 4; p++) {
            ldm4(bh[p], adrBh + p * 16 * PAD * 2 + k2);
            ldm4(bl[p], adrBl + p * 16 * PAD * 2 + k2);
        }
#pragma unroll
        for (int mt = 0; mt < 2; mt++)
#pragma unroll
            for (int nt = 0; nt < 8; nt++) {
                int p = nt >> 1, q = nt & 1;
                mma_bf16(acc[mt][nt], ah[mt], bh[p][q], bh[p][q + 2]);
                mma_bf16(acc[mt][nt], al[mt], bh[p][q], bh[p][q + 2]);
                mma_bf16(acc[mt][nt], ah[mt], bl[p][q], bl[p][q + 2]);
            }
    }
}

__global__ void __launch_bounds__(256, 1) k_mlp_fused(
    const __nv_bfloat16* __restrict__ Ah, const __nv_bfloat16* __restrict__ Al,
    float* __restrict__ out,
    const int* __restrict__ batch, int last,
    const __nv_bfloat16* __restrict__ W1h, const __nv_bfloat16* __restrict__ W1l,
    const __nv_bfloat16* __restrict__ W2h, const __nv_bfloat16* __restrict__ W2l,
    const float* __restrict__ b1,
    const float* __restrict__ g1, const float* __restrict__ bb1,
    const float* __restrict__ m1, const float* __restrict__ v1,
    const float* __restrict__ b2,
    const float* __restrict__ g2, const float* __restrict__ bb2,
    const float* __restrict__ m2, const float* __restrict__ v2)
{
    extern __shared__ char sm[];
    __nv_bfloat16* sW1h = reinterpret_cast<__nv_bfloat16*>(sm);
    __nv_bfloat16* sW1l = sW1h + WIMG;
    __nv_bfloat16* sW2h = sW1l + WIMG;
    __nv_bfloat16* sW2l = sW2h + WIMG;
    __nv_bfloat16* sAh  = sW2l + WIMG;
    __nv_bfloat16* sAl  = sAh + WIMG;
    float* S1 = reinterpret_cast<float*>(sAl + WIMG);
    float* T1 = S1 + 128;
    float* S2 = T1 + 128;
    float* T2 = S2 + 128;

    int tid = threadIdx.x, wid = tid >> 5, lane = tid & 31;
    uint32_t sAh_u = smem_u32(sAh);
    uint32_t sAl_u = smem_u32(sAl);

    const int NTILES = (N_NODES + 127) / 128;   // 391

    // prologue: prefetch first tile's A while loading W images
    {
        int base = blockIdx.x * 128;
        for (int i = tid; i < 2048; i += 256) {
            int row = i >> 4, seg = (i & 15) * 8;
            uint32_t d = (uint32_t)((row * PAD + seg) * 2);
            size_t s = (size_t)(base + row) * 128 + seg;
            cp16(sAh_u + d, Ah + s);
            cp16(sAl_u + d, Al + s);
        }
        asm volatile("cp.async.commit_group;" ::: "memory");
    }
    for (int i = tid; i < 2048; i += 256) {
        int o = i >> 4, kc = (i & 15) * 8;
        *reinterpret_cast<uint4*>(sW1h + o * PAD + kc) = reinterpret_cast<const uint4*>(W1h)[i];
        *reinterpret_cast<uint4*>(sW1l + o * PAD + kc) = reinterpret_cast<const uint4*>(W1l)[i];
        *reinterpret_cast<uint4*>(sW2h + o * PAD + kc) = reinterpret_cast<const uint4*>(W2h)[i];
        *reinterpret_cast<uint4*>(sW2l + o * PAD + kc) = reinterpret_cast<const uint4*>(W2l)[i];
    }
    if (tid < 128) {
        float s1 = g1[tid] * rsqrtf(v1[tid] + BN_EPS);
        S1[tid] = s1;
        T1[tid] = (b1[tid] - m1[tid]) * s1 + bb1[tid];
        float s2 = g2[tid] * rsqrtf(v2[tid] + BN_EPS);
        S2[tid] = s2;
        T2[tid] = (b2[tid] - m2[tid]) * s2 + bb2[tid];
    }

    int wm = wid & 3, wn = wid >> 2;
    uint32_t aOff = ((uint32_t)(wm * 32 + (lane & 15)) * PAD + (lane >> 4) * 8) * 2;
    uint32_t bOff = ((uint32_t)(wn * 64 + (lane & 7) + ((lane >> 3) & 1) * 8) * PAD + (lane >> 4) * 8) * 2;
    uint32_t adrAh  = sAh_u + aOff;
    uint32_t adrAl  = sAl_u + aOff;
    uint32_t adrB1h = smem_u32(sW1h) + bOff;
    uint32_t adrB1l = smem_u32(sW1l) + bOff;
    uint32_t adrB2h = smem_u32(sW2h) + bOff;
    uint32_t adrB2l = smem_u32(sW2l) + bOff;

    for (int t = blockIdx.x; t < NTILES; t += gridDim.x) {
        int base = t * 128;
        asm volatile("cp.async.wait_group 0;" ::: "memory");
        __syncthreads();

        // ---- GEMM1 ----
        float acc[2][8][4];
        gemm_128(acc, adrAh, adrAl, adrB1h, adrB1l);
        __syncthreads();

        // ---- epilogue1: BN1 + ReLU -> bf16 split back into sA ----
#pragma unroll
        for (int mt = 0; mt < 2; mt++) {
            int r0 = wm * 32 + mt * 16 + (lane >> 2);
#pragma unroll
            for (int nt = 0; nt < 8; nt++) {
                int col = wn * 64 + nt * 8 + (lane & 3) * 2;
                float Sa = S1[col], Sb2 = S1[col + 1];
                float Ta = T1[col], Tb = T1[col + 1];
                float y0 = fmaxf(acc[mt][nt][0] * Sa + Ta, 0.0f);
                float y1 = fmaxf(acc[mt][nt][1] * Sb2 + Tb, 0.0f);
                float y2 = fmaxf(acc[mt][nt][2] * Sa + Ta, 0.0f);
                float y3 = fmaxf(acc[mt][nt][3] * Sb2 + Tb, 0.0f);
                __nv_bfloat162 h0 = __float22bfloat162_rn(make_float2(y0, y1));
                __nv_bfloat162 h1 = __float22bfloat162_rn(make_float2(y2, y3));
                float2 f0 = __bfloat1622float2(h0);
                float2 f1 = __bfloat1622float2(h1);
                __nv_bfloat162 l0 = __float22bfloat162_rn(make_float2(y0 - f0.x, y1 - f0.y));
                __nv_bfloat162 l1 = __float22bfloat162_rn(make_float2(y2 - f1.x, y3 - f1.y));
                *reinterpret_cast<uint32_t*>(sAh + r0 * PAD + col) = *reinterpret_cast<uint32_t*>(&h0);
                *reinterpret_cast<uint32_t*>(sAl + r0 * PAD + col) = *reinterpret_cast<uint32_t*>(&l0);
                *reinterpret_cast<uint32_t*>(sAh + (r0 + 8) * PAD + col) = *reinterpret_cast<uint32_t*>(&h1);
                *reinterpret_cast<uint32_t*>(sAl + (r0 + 8) * PAD + col) = *reinterpret_cast<uint32_t*>(&l1);
            }
        }
        __syncthreads();

        // ---- GEMM2 ----
        gemm_128(acc, adrAh, adrAl, adrB2h, adrB2l);
        __syncthreads();

        // ---- prefetch next tile's A (overlaps epilogue2 stores) ----
        int tn = t + gridDim.x;
        if (tn < NTILES) {
            int nb = tn * 128;
            for (int i = tid; i < 2048; i += 256) {
                int row = i >> 4, seg = (i & 15) * 8;
                uint32_t d = (uint32_t)((row * PAD + seg) * 2);
                size_t s = (size_t)(nb + row) * 128 + seg;
                cp16(sAh_u + d, Ah + s);
                cp16(sAl_u + d, Al + s);
            }
        }
        asm volatile("cp.async.commit_group;" ::: "memory");

        // ---- epilogue2: BN2 + ReLU -> global x, or fused pool atomics on last layer ----
#pragma unroll
        for (int mt = 0; mt < 2; mt++) {
            int r0 = base + wm * 32 + mt * 16 + (lane >> 2);
            int c0 = (last && r0 < N_NODES) ? batch[r0] : 0;
            int c1 = (last && r0 + 8 < N_NODES) ? batch[r0 + 8] : 0;
#pragma unroll
            for (int nt = 0; nt < 8; nt++) {
                int col = wn * 64 + nt * 8 + (lane & 3) * 2;
                float Sa = S2[col], Sb2 = S2[col + 1];
                float Ta = T2[col], Tb = T2[col + 1];
                if (r0 < N_NODES) {
                    float2 v;
                    v.x = fmaxf(acc[mt][nt][0] * Sa + Ta, 0.0f);
                    v.y = fmaxf(acc[mt][nt][1] * Sb2 + Tb, 0.0f);
                    if (last) atomicAdd(reinterpret_cast<float2*>(g_pool + (size_t)c0 * 128 + col), v);
                    else *reinterpret_cast<float2*>(out + (size_t)r0 * 128 + col) = v;
                }
                if (r0 + 8 < N_NODES) {
                    float2 v;
                    v.x = fmaxf(acc[mt][nt][2] * Sa + Ta, 0.0f);
                    v.y = fmaxf(acc[mt][nt][3] * Sb2 + Tb, 0.0f);
                    if (last) atomicAdd(reinterpret_cast<float2*>(g_pool + (size_t)c1 * 128 + col), v);
                    else *reinterpret_cast<float2*>(out + (size_t)(r0 + 8) * 128 + col) = v;
                }
            }
        }
    }
}

// ---------------- head (graph count via binary search on sorted batch) ----------------
__global__ void k_head(const int* __restrict__ batch,
                       const float* __restrict__ W1, const float* __restrict__ b1,
                       const float* __restrict__ W2, const float* __restrict__ b2,
                       float* __restrict__ out)
{
    __shared__ float sg[DIM];
    __shared__ float sh[DIM];
    int c = blockIdx.x;
    int t = threadIdx.x;
    int lo = 0, hi = N_NODES;
    while (lo < hi) { int m = (lo + hi) >> 1; if (batch[m] < c) lo = m + 1; else hi = m; }
    int lo2 = lo, hi2 = N_NODES;
    while (lo2 < hi2) { int m = (lo2 + hi2) >> 1; if (batch[m] < c + 1) lo2 = m + 1; else hi2 = m; }
    float cnt = fmaxf((float)(lo2 - lo), 1.0f);
    sg[t] = g_pool[c * DIM + t] / cnt;
    __syncthreads();
    float acc = b1[t];
#pragma unroll 8
    for (int k = 0; k < DIM; k++) acc += sg[k] * W1[k * DIM + t];
    sh[t] = fmaxf(acc, 0.0f);
    __syncthreads();
    if (t < NCLASS) {
        float o2 = b2[t];
#pragma unroll 8
        for (int k = 0; k < DIM; k++) o2 += sh[k] * W2[k * NCLASS + t];
        out[c * NCLASS + t] = o2;
    }
}

// ---------------- launch ----------------
extern "C" void kernel_launch(void* const* d_in, const int* in_sizes, int n_in,
                              void* d_out, int out_size)
{
    const float* edge_attr = (const float*)d_in[0];
    const int*   edge_index= (const int*)  d_in[1];
    const int*   batch     = (const int*)  d_in[2];
    const float* node_emb  = (const float*)d_in[3];
    const float* edge_W    = (const float*)d_in[4];
    const float* edge_b    = (const float*)d_in[5];
    const float* mlp_W1    = (const float*)d_in[6];
    const float* mlp_b1    = (const float*)d_in[7];
    const float* bn1_g     = (const float*)d_in[8];
    const float* bn1_b     = (const float*)d_in[9];
    const float* bn1_m     = (const float*)d_in[10];
    const float* bn1_v     = (const float*)d_in[11];
    const float* mlp_W2    = (const float*)d_in[12];
    const float* mlp_b2    = (const float*)d_in[13];
    const float* bn2_g     = (const float*)d_in[14];
    const float* bn2_b     = (const float*)d_in[15];
    const float* bn2_m     = (const float*)d_in[16];
    const float* bn2_v     = (const float*)d_in[17];
    const float* head_W1   = (const float*)d_in[18];
    const float* head_b1   = (const float*)d_in[19];
    const float* head_W2   = (const float*)d_in[20];
    const float* head_b2   = (const float*)d_in[21];
    float* out = (float*)d_out;

    cudaFuncSetAttribute(k_mlp_fused, cudaFuncAttributeMaxDynamicSharedMemorySize, FUSED_SMEM);

    float *px, *ppool;
    int *pdeg, *pflag, *pctr;
    __nv_bfloat16 *pwh, *pwl, *pah, *pal;
    cudaGetSymbolAddress((void**)&px,    g_x);
    cudaGetSymbolAddress((void**)&ppool, g_pool);
    cudaGetSymbolAddress((void**)&pdeg,  g_deg);
    cudaGetSymbolAddress((void**)&pflag, g_flag);
    cudaGetSymbolAddress((void**)&pctr,  g_ctr);
    cudaGetSymbolAddress((void**)&pwh,   g_Wh);
    cudaGetSymbolAddress((void**)&pwl,   g_Wl);
    cudaGetSymbolAddress((void**)&pah,   g_Ah);
    cudaGetSymbolAddress((void**)&pal,   g_Al);

    // zeroing via async memsets (graph-capturable)
    cudaMemsetAsync(pdeg,  0, N_NODES * sizeof(int));
    cudaMemsetAsync(pflag, 0, SCAN_BLOCKS * sizeof(int));
    cudaMemsetAsync(ppool, 0, N_GRAPH * DIM * sizeof(float));
    cudaMemsetAsync(pctr,  0, 8 * sizeof(int));

    // weight prep + CSR build (deterministic each replay)
    k_prep_w<<<(10 * 16384 + 255) / 256, 256>>>(mlp_W1, mlp_W2);
    k_hist<<<(N_EDGES + 255) / 256, 256>>>(edge_index);
    k_scan_lb<<<SCAN_BLOCKS, 256>>>();
    k_scatter_idx<<<(N_EDGES + 255) / 256, 256>>>(edge_index);
    k_gather_attr<<<(N_EDGES + 255) / 256, 256>>>(edge_index, edge_attr);

    const int TC_GRID = 148;
    const int EDGE_GRID = 148 * 8;   // work-stealing: enough blocks to fill, each steals
    for (int l = 0; l < LAYERS; l++) {
        if (l == 0)
            k_edge_l0<<<EDGE_GRID, 256>>>(node_emb, edge_W, edge_b);
        else
            k_edge_csr<<<EDGE_GRID, 256>>>(edge_W + l * EDIM * DIM, edge_b + l * DIM, l);
        int m1 = l * 2, m2 = l * 2 + 1;
        k_mlp_fused<<<TC_GRID, 256, FUSED_SMEM>>>(
            pah, pal, px,
            batch, (l == LAYERS - 1) ? 1 : 0,
            pwh + m1 * 16384, pwl + m1 * 16384,
            pwh + m2 * 16384, pwl + m2 * 16384,
            mlp_b1 + l * DIM, bn1_g + l * DIM, bn1_b + l * DIM, bn1_m + l * DIM, bn1_v + l * DIM,
            mlp_b2 + l * DIM, bn2_g + l * DIM, bn2_b + l * DIM, bn2_m + l * DIM, bn2_v + l * DIM);
    }

    k_head<<<N_GRAPH, DIM>>>(batch, head_W1, head_b1, head_W2, head_b2, out);
}

// round 17
// speedup vs baseline: 1.2594x; 1.0305x over previous
#include <cuda_runtime.h>
#include <cuda_bf16.h>
#include <cstdint>

#define N_NODES 50000
#define N_EDGES 800000
#define N_GRAPH 500
#define DIM     128
#define EDIM    7
#define LAYERS  5
#define NCLASS  10
#define BN_EPS  1e-5f
#define NROWS_PAD 50048   // NTILES*128

typedef unsigned long long u64;

// ---------------- scratch ----------------
__device__ float g_x  [N_NODES * DIM];
__device__ float g_pool[N_GRAPH * DIM];
__device__ int   g_ctr [8];               // work-stealing counters (one per layer)

// bf16 hi/lo planes of (x + agg): edge-kernel output, MLP A input
__device__ __nv_bfloat16 g_Ah[(size_t)NROWS_PAD * DIM];
__device__ __nv_bfloat16 g_Al[(size_t)NROWS_PAD * DIM];

// CSR scratch
__device__ int   g_deg [N_NODES];
__device__ int   g_off [N_NODES + 1];
__device__ int   g_fill[N_NODES];
__device__ int   g_eid [N_EDGES];
__device__ int   g_esrc[N_EDGES];
__device__ float g_eattr[(size_t)N_EDGES * 8];   // attr in CSR order (padded to 8)

#define SCAN_BLOCKS ((N_NODES + 255) / 256)   // 196
__device__ int g_flag[SCAN_BLOCKS];
__device__ int g_aggr[SCAN_BLOCKS];
__device__ int g_incl[SCAN_BLOCKS];

// transposed + bf16-split weight images, row-major [o][k] (10 mats: l*2 + {W1,W2})
__device__ __nv_bfloat16 g_Wh[10 * 16384];
__device__ __nv_bfloat16 g_Wl[10 * 16384];

// ================= helpers =================
__device__ __forceinline__ uint32_t smem_u32(const void* p) {
    uint32_t a;
    asm("{ .reg .u64 t; cvta.to.shared.u64 t, %1; cvt.u32.u64 %0, t; }" : "=r"(a) : "l"(p));
    return a;
}
__device__ __forceinline__ void ldm4(uint32_t* r, uint32_t addr) {
    asm volatile("ldmatrix.sync.aligned.m8n8.x4.shared.b16 {%0,%1,%2,%3}, [%4];"
                 : "=r"(r[0]), "=r"(r[1]), "=r"(r[2]), "=r"(r[3]) : "r"(addr));
}
__device__ __forceinline__ void mma_bf16(float* c, const uint32_t* a, uint32_t b0, uint32_t b1) {
    asm volatile("mma.sync.aligned.m16n8k16.row.col.f32.bf16.bf16.f32 "
                 "{%0,%1,%2,%3}, {%4,%5,%6,%7}, {%8,%9}, {%0,%1,%2,%3};"
                 : "+f"(c[0]), "+f"(c[1]), "+f"(c[2]), "+f"(c[3])
                 : "r"(a[0]), "r"(a[1]), "r"(a[2]), "r"(a[3]), "r"(b0), "r"(b1));
}
__device__ __forceinline__ void cp16(uint32_t smem_dst, const void* gsrc) {
    asm volatile("cp.async.cg.shared.global [%0], [%1], 16;" :: "r"(smem_dst), "l"(gsrc));
}

// ---- packed f32x2 ----
__device__ __forceinline__ u64 fma2(u64 a, u64 b, u64 c) {
    u64 d;
    asm("fma.rn.f32x2 %0, %1, %2, %3;" : "=l"(d) : "l"(a), "l"(b), "l"(c));
    return d;
}
__device__ __forceinline__ u64 add2(u64 a, u64 b) {
    u64 d;
    asm("add.rn.f32x2 %0, %1, %2;" : "=l"(d) : "l"(a), "l"(b));
    return d;
}
__device__ __forceinline__ u64 packdup(float a) {
    u64 d;
    uint32_t u = __float_as_uint(a);
    asm("mov.b64 %0, {%1, %1};" : "=l"(d) : "r"(u));
    return d;
}
__device__ __forceinline__ u64 pack2(float a, float b) {
    u64 d;
    uint32_t ua = __float_as_uint(a), ub = __float_as_uint(b);
    asm("mov.b64 %0, {%1, %2};" : "=l"(d) : "r"(ua), "r"(ub));
    return d;
}
__device__ __forceinline__ float2 unpack2(u64 v) {
    uint32_t x, y;
    asm("mov.b64 {%0, %1}, %2;" : "=r"(x), "=r"(y) : "l"(v));
    return make_float2(__uint_as_float(x), __uint_as_float(y));
}

// split fp32x4 -> bf16 hi/lo and store 8B to each plane
__device__ __forceinline__ void store_split(__nv_bfloat16* Ah, __nv_bfloat16* Al,
                                            size_t idx, float4 acc) {
    __nv_bfloat162 h01 = __float22bfloat162_rn(make_float2(acc.x, acc.y));
    __nv_bfloat162 h23 = __float22bfloat162_rn(make_float2(acc.z, acc.w));
    float2 f01 = __bfloat1622float2(h01);
    float2 f23 = __bfloat1622float2(h23);
    __nv_bfloat162 l01 = __float22bfloat162_rn(make_float2(acc.x - f01.x, acc.y - f01.y));
    __nv_bfloat162 l23 = __float22bfloat162_rn(make_float2(acc.z - f23.x, acc.w - f23.y));
    uint2 hp = make_uint2(*reinterpret_cast<uint32_t*>(&h01), *reinterpret_cast<uint32_t*>(&h23));
    uint2 lp = make_uint2(*reinterpret_cast<uint32_t*>(&l01), *reinterpret_cast<uint32_t*>(&l23));
    *reinterpret_cast<uint2*>(Ah + idx) = hp;
    *reinterpret_cast<uint2*>(Al + idx) = lp;
}

// ---------------- weight prep + all scratch zeroing (replaces 4 memsets) ----------------
__global__ void k_prep_w(const float* __restrict__ W1, const float* __restrict__ W2) {
    int idx = blockIdx.x * blockDim.x + threadIdx.x;
    // fold zeroing of scratch used downstream (this kernel runs first, same stream)
    if (idx < N_NODES) g_deg[idx] = 0;
    if (idx < SCAN_BLOCKS) g_flag[idx] = 0;
    if (idx < N_GRAPH * DIM) g_pool[idx] = 0.0f;
    if (idx < 8) g_ctr[idx] = 0;
    if (idx >= 10 * 16384) return;
    int mat = idx >> 14;
    int r = idx & 16383;
    int o = r >> 7, k = r & 127;
    int l = mat >> 1;
    const float* W = (mat & 1) ? (W2 + l * 16384) : (W1 + l * 16384);
    float x = W[k * 128 + o];
    __nv_bfloat16 h = __float2bfloat16(x);
    __nv_bfloat16 lo = __float2bfloat16(x - __bfloat162float(h));
    g_Wh[mat * 16384 + o * 128 + k] = h;
    g_Wl[mat * 16384 + o * 128 + k] = lo;
}

// ---------------- CSR build ----------------
__global__ void k_hist(const int* __restrict__ ei) {
    int e = blockIdx.x * blockDim.x + threadIdx.x;
    if (e < N_EDGES) atomicAdd(&g_deg[ei[N_EDGES + e]], 1);
}

// single-pass decoupled-lookback scan (integer, deterministic)
__global__ void __launch_bounds__(256) k_scan_lb() {
    __shared__ int sw[8];
    __shared__ int s_excl;
    int tid = threadIdx.x, lane = tid & 31, wid = tid >> 5;
    int bid = blockIdx.x;
    int i = bid * 256 + tid;
    int v = (i < N_NODES) ? g_deg[i] : 0;
    int x = v;
#pragma unroll
    for (int d = 1; d < 32; d <<= 1) {
        int t = __shfl_up_sync(0xffffffffu, x, d);
        if (lane >= d) x += t;
    }
    if (lane == 31) sw[wid] = x;
    __syncthreads();
    if (wid == 0 && lane < 8) {
        int y = sw[lane];
#pragma unroll
        for (int d = 1; d < 8; d <<= 1) {
            int t = __shfl_up_sync(0xffu, y, d);
            if (lane >= d) y += t;
        }
        sw[lane] = y;
    }
    __syncthreads();
    int blk_incl = sw[7];
    int x_blk = x + (wid ? sw[wid - 1] : 0);

    if (tid == 0) {
        if (bid == 0) {
            g_incl[0] = blk_incl;
            __threadfence();
            atomicExch(&g_flag[0], 2);
        } else {
            g_aggr[bid] = blk_incl;
            __threadfence();
            atomicExch(&g_flag[bid], 1);
        }
    }

    if (wid == 0) {
        int running = 0;
        if (bid > 0) {
            int idx = bid - 1;
            while (true) {
                int ii = idx - lane;
                int f;
                do {
                    f = (ii >= 0) ? atomicAdd(&g_flag[ii], 0) : 2;
                } while (__any_sync(0xffffffffu, f == 0 && ii >= 0));
                unsigned m2 = __ballot_sync(0xffffffffu, ii >= 0 && f == 2);
                int stop = m2 ? (__ffs(m2) - 1) : 32;
                int own = 0;
                if (ii >= 0 && lane < stop) own = g_aggr[ii];
                else if (m2 && lane == stop) own = g_incl[ii];
#pragma unroll
                for (int d = 16; d > 0; d >>= 1)
                    own += __shfl_down_sync(0xffffffffu, own, d);
                own = __shfl_sync(0xffffffffu, own, 0);
                running += own;
                if (m2) break;
                idx -= 32;
            }
            if (lane == 0) {
                g_incl[bid] = running + blk_incl;
                __threadfence();
                atomicExch(&g_flag[bid], 2);
            }
        }
        if (lane == 0) s_excl = running;
    }
    __syncthreads();
    int excl = s_excl + x_blk - v;
    if (i < N_NODES) { g_off[i] = excl; g_fill[i] = excl; }
    if (i == 0) g_off[N_NODES] = N_EDGES;
}

// atomic slot assignment, single 4B random store
__global__ void k_scatter_idx(const int* __restrict__ ei) {
    int e = blockIdx.x * blockDim.x + threadIdx.x;
    if (e < N_EDGES) {
        int dst = ei[N_EDGES + e];
        int p = atomicAdd(&g_fill[dst], 1);
        g_eid[p] = e;
    }
}

// ---------------- per-node edge body (packed f32x2) ----------------
__device__ __forceinline__ void edge_node_body(
    int dst, int lane, const ulonglong2* X2,
    const ulonglong2* sW, u64 b01, u64 b23)
{
    ulonglong2 xd = X2[(size_t)dst * 32 + lane];
    u64 acc01 = xd.x, acc23 = xd.y;
    int j = g_off[dst], end = g_off[dst + 1];

    for (; j + 4 <= end; j += 4) {
        float av = g_eattr[(size_t)j * 8 + lane];
        int s0 = g_esrc[j + 0], s1 = g_esrc[j + 1];
        int s2 = g_esrc[j + 2], s3 = g_esrc[j + 3];
        ulonglong2 x0 = X2[(size_t)s0 * 32 + lane];
        ulonglong2 x1 = X2[(size_t)s1 * 32 + lane];
        ulonglong2 x2 = X2[(size_t)s2 * 32 + lane];
        ulonglong2 x3 = X2[(size_t)s3 * 32 + lane];
        u64 e01_0 = b01, e23_0 = b23, e01_1 = b01, e23_1 = b23;
        u64 e01_2 = b01, e23_2 = b23, e01_3 = b01, e23_3 = b23;
#pragma unroll
        for (int q = 0; q < EDIM; q++) {
            ulonglong2 w = sW[q * 32 + lane];
            u64 a0 = packdup(__shfl_sync(0xffffffffu, av, q));
            u64 a1 = packdup(__shfl_sync(0xffffffffu, av, 8 + q));
            u64 a2 = packdup(__shfl_sync(0xffffffffu, av, 16 + q));
            u64 a3 = packdup(__shfl_sync(0xffffffffu, av, 24 + q));
            e01_0 = fma2(a0, w.x, e01_0); e23_0 = fma2(a0, w.y, e23_0);
            e01_1 = fma2(a1, w.x, e01_1); e23_1 = fma2(a1, w.y, e23_1);
            e01_2 = fma2(a2, w.x, e01_2); e23_2 = fma2(a2, w.y, e23_2);
            e01_3 = fma2(a3, w.x, e01_3); e23_3 = fma2(a3, w.y, e23_3);
        }
        float2 f01, f23;
        f01 = unpack2(add2(x0.x, e01_0)); f23 = unpack2(add2(x0.y, e23_0));
        acc01 = add2(acc01, pack2(fmaxf(f01.x, 0.f), fmaxf(f01.y, 0.f)));
        acc23 = add2(acc23, pack2(fmaxf(f23.x, 0.f), fmaxf(f23.y, 0.f)));
        f01 = unpack2(add2(x1.x, e01_1)); f23 = unpack2(add2(x1.y, e23_1));
        acc01 = add2(acc01, pack2(fmaxf(f01.x, 0.f), fmaxf(f01.y, 0.f)));
        acc23 = add2(acc23, pack2(fmaxf(f23.x, 0.f), fmaxf(f23.y, 0.f)));
        f01 = unpack2(add2(x2.x, e01_2)); f23 = unpack2(add2(x2.y, e23_2));
        acc01 = add2(acc01, pack2(fmaxf(f01.x, 0.f), fmaxf(f01.y, 0.f)));
        acc23 = add2(acc23, pack2(fmaxf(f23.x, 0.f), fmaxf(f23.y, 0.f)));
        f01 = unpack2(add2(x3.x, e01_3)); f23 = unpack2(add2(x3.y, e23_3));
        acc01 = add2(acc01, pack2(fmaxf(f01.x, 0.f), fmaxf(f01.y, 0.f)));
        acc23 = add2(acc23, pack2(fmaxf(f23.x, 0.f), fmaxf(f23.y, 0.f)));
    }
    for (; j < end; j++) {
        int src = g_esrc[j];
        float v = (lane < EDIM) ? g_eattr[(size_t)j * 8 + lane] : 0.0f;
        u64 e01 = b01, e23 = b23;
#pragma unroll
        for (int q = 0; q < EDIM; q++) {
            ulonglong2 w = sW[q * 32 + lane];
            u64 a = packdup(__shfl_sync(0xffffffffu, v, q));
            e01 = fma2(a, w.x, e01);
            e23 = fma2(a, w.y, e23);
        }
        ulonglong2 xv = X2[(size_t)src * 32 + lane];
        float2 f01 = unpack2(add2(xv.x, e01));
        float2 f23 = unpack2(add2(xv.y, e23));
        acc01 = add2(acc01, pack2(fmaxf(f01.x, 0.f), fmaxf(f01.y, 0.f)));
        acc23 = add2(acc23, pack2(fmaxf(f23.x, 0.f), fmaxf(f23.y, 0.f)));
    }
    float2 a01 = unpack2(acc01), a23 = unpack2(acc23);
    store_split(g_Ah, g_Al, (size_t)dst * 128 + lane * 4,
                make_float4(a01.x, a01.y, a23.x, a23.y));
}

// ---------------- edge aggregation, work-stealing (layers 1..4) ----------------
#define STEAL_CHUNK 2
__global__ void __launch_bounds__(256) k_edge_csr(
    const float* __restrict__ eW, const float* __restrict__ eb, int lidx)
{
    __shared__ ulonglong2 sW[EDIM * 32];
    __shared__ ulonglong2 sB[32];
    int tid = threadIdx.x;
    if (tid < EDIM * 32) sW[tid] = reinterpret_cast<const ulonglong2*>(eW)[tid];
    if (tid < 32)        sB[tid] = reinterpret_cast<const ulonglong2*>(eb)[tid];
    __syncthreads();

    int lane = tid & 31;
    const ulonglong2* X2 = reinterpret_cast<const ulonglong2*>(g_x);
    const u64 b01 = sB[lane].x, b23 = sB[lane].y;

    for (;;) {
        int n0;
        if (lane == 0) n0 = atomicAdd(&g_ctr[lidx], STEAL_CHUNK);
        n0 = __shfl_sync(0xffffffffu, n0, 0);
        if (n0 >= N_NODES) break;
#pragma unroll
        for (int k = 0; k < STEAL_CHUNK; k++) {
            int dst = n0 + k;
            if (dst < N_NODES)
                edge_node_body(dst, lane, X2, sW, b01, b23);
        }
    }
}

// ---------------- layer-0 edge: no x gather; ALSO materializes esrc/eattr in CSR order ----------------
// lanes 8k..8k+7 own edge k of each 4-edge chunk: lanes 0..6 of group read attr,
// lane 7 of group reads src. eattr write index = j*8+lane (fully coalesced).
__device__ __forceinline__ void edge_node_body_l0(
    int dst, int lane, const int* __restrict__ ei, const float* __restrict__ attr,
    const ulonglong2* sW, u64 b01, u64 b23, u64 em01, u64 em23)
{
    u64 acc01 = em01, acc23 = em23;
    int j = g_off[dst], end = g_off[dst + 1];

    for (; j + 4 <= end; j += 4) {
        int e_k = g_eid[j + (lane >> 3)];
        int sub = lane & 7;
        float av = (sub < EDIM) ? attr[(size_t)e_k * EDIM + sub] : 0.0f;
        if (sub == 7) g_esrc[j + (lane >> 3)] = ei[e_k];
        g_eattr[(size_t)j * 8 + lane] = av;

        u64 e01_0 = b01, e23_0 = b23, e01_1 = b01, e23_1 = b23;
        u64 e01_2 = b01, e23_2 = b23, e01_3 = b01, e23_3 = b23;
#pragma unroll
        for (int q = 0; q < EDIM; q++) {
            ulonglong2 w = sW[q * 32 + lane];
            u64 a0 = packdup(__shfl_sync(0xffffffffu, av, q));
            u64 a1 = packdup(__shfl_sync(0xffffffffu, av, 8 + q));
            u64 a2 = packdup(__shfl_sync(0xffffffffu, av, 16 + q));
            u64 a3 = packdup(__shfl_sync(0xffffffffu, av, 24 + q));
            e01_0 = fma2(a0, w.x, e01_0); e23_0 = fma2(a0, w.y, e23_0);
            e01_1 = fma2(a1, w.x, e01_1); e23_1 = fma2(a1, w.y, e23_1);
            e01_2 = fma2(a2, w.x, e01_2); e23_2 = fma2(a2, w.y, e23_2);
            e01_3 = fma2(a3, w.x, e01_3); e23_3 = fma2(a3, w.y, e23_3);
        }
        float2 f01, f23;
        f01 = unpack2(e01_0); f23 = unpack2(e23_0);
        acc01 = add2(acc01, pack2(fmaxf(f01.x, 0.f), fmaxf(f01.y, 0.f)));
        acc23 = add2(acc23, pack2(fmaxf(f23.x, 0.f), fmaxf(f23.y, 0.f)));
        f01 = unpack2(e01_1); f23 = unpack2(e23_1);
        acc01 = add2(acc01, pack2(fmaxf(f01.x, 0.f), fmaxf(f01.y, 0.f)));
        acc23 = add2(acc23, pack2(fmaxf(f23.x, 0.f), fmaxf(f23.y, 0.f)));
        f01 = unpack2(e01_2); f23 = unpack2(e23_2);
        acc01 = add2(acc01, pack2(fmaxf(f01.x, 0.f), fmaxf(f01.y, 0.f)));
        acc23 = add2(acc23, pack2(fmaxf(f23.x, 0.f), fmaxf(f23.y, 0.f)));
        f01 = unpack2(e01_3); f23 = unpack2(e23_3);
        acc01 = add2(acc01, pack2(fmaxf(f01.x, 0.f), fmaxf(f01.y, 0.f)));
        acc23 = add2(acc23, pack2(fmaxf(f23.x, 0.f), fmaxf(f23.y, 0.f)));
    }
    for (; j < end; j++) {
        int e = g_eid[j];
        float v = (lane < EDIM) ? attr[(size_t)e * EDIM + lane] : 0.0f;
        if (lane == 7) g_esrc[j] = ei[e];
        if (lane < 8) g_eattr[(size_t)j * 8 + lane] = (lane < EDIM) ? v : 0.0f;

        u64 e01 = b01, e23 = b23;
#pragma unroll
        for (int q = 0; q < EDIM; q++) {
            ulonglong2 w = sW[q * 32 + lane];
            u64 a = packdup(__shfl_sync(0xffffffffu, v, q));
            e01 = fma2(a, w.x, e01);
            e23 = fma2(a, w.y, e23);
        }
        float2 f01 = unpack2(e01), f23 = unpack2(e23);
        acc01 = add2(acc01, pack2(fmaxf(f01.x, 0.f), fmaxf(f01.y, 0.f)));
        acc23 = add2(acc23, pack2(fmaxf(f23.x, 0.f), fmaxf(f23.y, 0.f)));
    }
    float2 a01 = unpack2(acc01), a23 = unpack2(acc23);
    store_split(g_Ah, g_Al, (size_t)dst * 128 + lane * 4,
                make_float4(a01.x, a01.y, a23.x, a23.y));
}

__global__ void __launch_bounds__(256) k_edge_l0(
    const int* __restrict__ ei, const float* __restrict__ attr,
    const float* __restrict__ node_emb,
    const float* __restrict__ eW, const float* __restrict__ eb)
{
    __shared__ ulonglong2 sW[EDIM * 32];
    __shared__ ulonglong2 sB[32];
    __shared__ ulonglong2 sE[32];
    int tid = threadIdx.x;
    if (tid < EDIM * 32) sW[tid] = reinterpret_cast<const ulonglong2*>(eW)[tid];
    if (tid < 32)        sB[tid] = reinterpret_cast<const ulonglong2*>(eb)[tid];
    if (tid >= 32 && tid < 64)
        sE[tid - 32] = reinterpret_cast<const ulonglong2*>(node_emb)[tid - 32];
    __syncthreads();

    int lane = tid & 31;
    ulonglong2 em = sE[lane];
    const u64 b01 = add2(sB[lane].x, em.x);
    const u64 b23 = add2(sB[lane].y, em.y);

    for (;;) {
        int n0;
        if (lane == 0) n0 = atomicAdd(&g_ctr[0], STEAL_CHUNK);
        n0 = __shfl_sync(0xffffffffu, n0, 0);
        if (n0 >= N_NODES) break;
#pragma unroll
        for (int k = 0; k < STEAL_CHUNK; k++) {
            int dst = n0 + k;
            if (dst < N_NODES)
                edge_node_body_l0(dst, lane, ei, attr, sW, b01, b23, em.x, em.y);
        }
    }
}

// ---------------- fused per-layer MLP (with next-tile A prefetch) ----------------
#define PAD 136
#define WIMG (128 * PAD)
#define FUSED_SMEM (6 * WIMG * 2 + 2048)

__device__ __forceinline__ void gemm_128(float (&acc)[2][8][4],
    uint32_t adrAh, uint32_t adrAl, uint32_t adrBh, uint32_t adrBl)
{
#pragma unroll
    for (int mt = 0; mt < 2; mt++)
#pragma unroll
        for (int nt = 0; nt < 8; nt++)
#pragma unroll
            for (int q = 0; q < 4; q++) acc[mt][nt][q] = 0.0f;

#pragma unroll
    for (int ks = 0; ks < 8; ks++) {
        uint32_t k2 = ks * 32;
        uint32_t ah[2][4], al[2][4], bh[4][4], bl[4][4];
        ldm4(ah[0], adrAh + k2);
        ldm4(ah[1], adrAh + 16 * PAD * 2 + k2);
        ldm4(al[0], adrAl + k2);
        ldm4(al[1], adrAl + 16 * PAD * 2 + k2);
#pragma unroll
        for (int p = 0; p < 4; p++) {
            ldm4(bh[p], adrBh + p * 16 * PAD * 2 + k2);
            ldm4(bl[p], adrBl + p * 16 * PAD * 2 + k2);
        }
#pragma unroll
        for (int mt = 0; mt < 2; mt++)
#pragma unroll
            for (int nt = 0; nt < 8; nt++) {
                int p = nt >> 1, q = nt & 1;
                mma_bf16(acc[mt][nt], ah[mt], bh[p][q], bh[p][q + 2]);
                mma_bf16(acc[mt][nt], al[mt], bh[p][q], bh[p][q + 2]);
                mma_bf16(acc[mt][nt], ah[mt], bl[p][q], bl[p][q + 2]);
            }
    }
}

__global__ void __launch_bounds__(256, 1) k_mlp_fused(
    const __nv_bfloat16* __restrict__ Ah, const __nv_bfloat16* __restrict__ Al,
    float* __restrict__ out,
    const int* __restrict__ batch, int last,
    const __nv_bfloat16* __restrict__ W1h, const __nv_bfloat16* __restrict__ W1l,
    const __nv_bfloat16* __restrict__ W2h, const __nv_bfloat16* __restrict__ W2l,
    const float* __restrict__ b1,
    const float* __restrict__ g1, const float* __restrict__ bb1,
    const float* __restrict__ m1, const float* __restrict__ v1,
    const float* __restrict__ b2,
    const float* __restrict__ g2, const float* __restrict__ bb2,
    const float* __restrict__ m2, const float* __restrict__ v2)
{
    extern __shared__ char sm[];
    __nv_bfloat16* sW1h = reinterpret_cast<__nv_bfloat16*>(sm);
    __nv_bfloat16* sW1l = sW1h + WIMG;
    __nv_bfloat16* sW2h = sW1l + WIMG;
    __nv_bfloat16* sW2l = sW2h + WIMG;
    __nv_bfloat16* sAh  = sW2l + WIMG;
    __nv_bfloat16* sAl  = sAh + WIMG;
    float* S1 = reinterpret_cast<float*>(sAl + WIMG);
    float* T1 = S1 + 128;
    float* S2 = T1 + 128;
    float* T2 = S2 + 128;

    int tid = threadIdx.x, wid = tid >> 5, lane = tid & 31;
    uint32_t sAh_u = smem_u32(sAh);
    uint32_t sAl_u = smem_u32(sAl);

    const int NTILES = (N_NODES + 127) / 128;   // 391

    // prologue: prefetch first tile's A while loading W images
    {
        int base = blockIdx.x * 128;
        for (int i = tid; i < 2048; i += 256) {
            int row = i >> 4, seg = (i & 15) * 8;
            uint32_t d = (uint32_t)((row * PAD + seg) * 2);
            size_t s = (size_t)(base + row) * 128 + seg;
            cp16(sAh_u + d, Ah + s);
            cp16(sAl_u + d, Al + s);
        }
        asm volatile("cp.async.commit_group;" ::: "memory");
    }
    for (int i = tid; i < 2048; i += 256) {
        int o = i >> 4, kc = (i & 15) * 8;
        *reinterpret_cast<uint4*>(sW1h + o * PAD + kc) = reinterpret_cast<const uint4*>(W1h)[i];
        *reinterpret_cast<uint4*>(sW1l + o * PAD + kc) = reinterpret_cast<const uint4*>(W1l)[i];
        *reinterpret_cast<uint4*>(sW2h + o * PAD + kc) = reinterpret_cast<const uint4*>(W2h)[i];
        *reinterpret_cast<uint4*>(sW2l + o * PAD + kc) = reinterpret_cast<const uint4*>(W2l)[i];
    }
    if (tid < 128) {
        float s1 = g1[tid] * rsqrtf(v1[tid] + BN_EPS);
        S1[tid] = s1;
        T1[tid] = (b1[tid] - m1[tid]) * s1 + bb1[tid];
        float s2 = g2[tid] * rsqrtf(v2[tid] + BN_EPS);
        S2[tid] = s2;
        T2[tid] = (b2[tid] - m2[tid]) * s2 + bb2[tid];
    }

    int wm = wid & 3, wn = wid >> 2;
    uint32_t aOff = ((uint32_t)(wm * 32 + (lane & 15)) * PAD + (lane >> 4) * 8) * 2;
    uint32_t bOff = ((uint32_t)(wn * 64 + (lane & 7) + ((lane >> 3) & 1) * 8) * PAD + (lane >> 4) * 8) * 2;
    uint32_t adrAh  = sAh_u + aOff;
    uint32_t adrAl  = sAl_u + aOff;
    uint32_t adrB1h = smem_u32(sW1h) + bOff;
    uint32_t adrB1l = smem_u32(sW1l) + bOff;
    uint32_t adrB2h = smem_u32(sW2h) + bOff;
    uint32_t adrB2l = smem_u32(sW2l) + bOff;

    for (int t = blockIdx.x; t < NTILES; t += gridDim.x) {
        int base = t * 128;
        asm volatile("cp.async.wait_group 0;" ::: "memory");
        __syncthreads();

        // ---- GEMM1 ----
        float acc[2][8][4];
        gemm_128(acc, adrAh, adrAl, adrB1h, adrB1l);
        __syncthreads();

        // ---- epilogue1: BN1 + ReLU -> bf16 split back into sA ----
#pragma unroll
        for (int mt = 0; mt < 2; mt++) {
            int r0 = wm * 32 + mt * 16 + (lane >> 2);
#pragma unroll
            for (int nt = 0; nt < 8; nt++) {
                int col = wn * 64 + nt * 8 + (lane & 3) * 2;
                float Sa = S1[col], Sb2 = S1[col + 1];
                float Ta = T1[col], Tb = T1[col + 1];
                float y0 = fmaxf(acc[mt][nt][0] * Sa + Ta, 0.0f);
                float y1 = fmaxf(acc[mt][nt][1] * Sb2 + Tb, 0.0f);
                float y2 = fmaxf(acc[mt][nt][2] * Sa + Ta, 0.0f);
                float y3 = fmaxf(acc[mt][nt][3] * Sb2 + Tb, 0.0f);
                __nv_bfloat162 h0 = __float22bfloat162_rn(make_float2(y0, y1));
                __nv_bfloat162 h1 = __float22bfloat162_rn(make_float2(y2, y3));
                float2 f0 = __bfloat1622float2(h0);
                float2 f1 = __bfloat1622float2(h1);
                __nv_bfloat162 l0 = __float22bfloat162_rn(make_float2(y0 - f0.x, y1 - f0.y));
                __nv_bfloat162 l1 = __float22bfloat162_rn(make_float2(y2 - f1.x, y3 - f1.y));
                *reinterpret_cast<uint32_t*>(sAh + r0 * PAD + col) = *reinterpret_cast<uint32_t*>(&h0);
                *reinterpret_cast<uint32_t*>(sAl + r0 * PAD + col) = *reinterpret_cast<uint32_t*>(&l0);
                *reinterpret_cast<uint32_t*>(sAh + (r0 + 8) * PAD + col) = *reinterpret_cast<uint32_t*>(&h1);
                *reinterpret_cast<uint32_t*>(sAl + (r0 + 8) * PAD + col) = *reinterpret_cast<uint32_t*>(&l1);
            }
        }
        __syncthreads();

        // ---- GEMM2 ----
        gemm_128(acc, adrAh, adrAl, adrB2h, adrB2l);
        __syncthreads();

        // ---- prefetch next tile's A (overlaps epilogue2 stores) ----
        int tn = t + gridDim.x;
        if (tn < NTILES) {
            int nb = tn * 128;
            for (int i = tid; i < 2048; i += 256) {
                int row = i >> 4, seg = (i & 15) * 8;
                uint32_t d = (uint32_t)((row * PAD + seg) * 2);
                size_t s = (size_t)(nb + row) * 128 + seg;
                cp16(sAh_u + d, Ah + s);
                cp16(sAl_u + d, Al + s);
            }
        }
        asm volatile("cp.async.commit_group;" ::: "memory");

        // ---- epilogue2: BN2 + ReLU -> global x, or fused pool atomics on last layer ----
#pragma unroll
        for (int mt = 0; mt < 2; mt++) {
            int r0 = base + wm * 32 + mt * 16 + (lane >> 2);
            int c0 = (last && r0 < N_NODES) ? batch[r0] : 0;
            int c1 = (last && r0 + 8 < N_NODES) ? batch[r0 + 8] : 0;
#pragma unroll
            for (int nt = 0; nt < 8; nt++) {
                int col = wn * 64 + nt * 8 + (lane & 3) * 2;
                float Sa = S2[col], Sb2 = S2[col + 1];
                float Ta = T2[col], Tb = T2[col + 1];
                if (r0 < N_NODES) {
                    float2 v;
                    v.x = fmaxf(acc[mt][nt][0] * Sa + Ta, 0.0f);
                    v.y = fmaxf(acc[mt][nt][1] * Sb2 + Tb, 0.0f);
                    if (last) atomicAdd(reinterpret_cast<float2*>(g_pool + (size_t)c0 * 128 + col), v);
                    else *reinterpret_cast<float2*>(out + (size_t)r0 * 128 + col) = v;
                }
                if (r0 + 8 < N_NODES) {
                    float2 v;
                    v.x = fmaxf(acc[mt][nt][2] * Sa + Ta, 0.0f);
                    v.y = fmaxf(acc[mt][nt][3] * Sb2 + Tb, 0.0f);
                    if (last) atomicAdd(reinterpret_cast<float2*>(g_pool + (size_t)c1 * 128 + col), v);
                    else *reinterpret_cast<float2*>(out + (size_t)(r0 + 8) * 128 + col) = v;
                }
            }
        }
    }
}

// ---------------- head (graph count via binary search on sorted batch) ----------------
__global__ void k_head(const int* __restrict__ batch,
                       const float* __restrict__ W1, const float* __restrict__ b1,
                       const float* __restrict__ W2, const float* __restrict__ b2,
                       float* __restrict__ out)
{
    __shared__ float sg[DIM];
    __shared__ float sh[DIM];
    int c = blockIdx.x;
    int t = threadIdx.x;
    int lo = 0, hi = N_NODES;
    while (lo < hi) { int m = (lo + hi) >> 1; if (batch[m] < c) lo = m + 1; else hi = m; }
    int lo2 = lo, hi2 = N_NODES;
    while (lo2 < hi2) { int m = (lo2 + hi2) >> 1; if (batch[m] < c + 1) lo2 = m + 1; else hi2 = m; }
    float cnt = fmaxf((float)(lo2 - lo), 1.0f);
    sg[t] = g_pool[c * DIM + t] / cnt;
    __syncthreads();
    float acc = b1[t];
#pragma unroll 8
    for (int k = 0; k < DIM; k++) acc += sg[k] * W1[k * DIM + t];
    sh[t] = fmaxf(acc, 0.0f);
    __syncthreads();
    if (t < NCLASS) {
        float o2 = b2[t];
#pragma unroll 8
        for (int k = 0; k < DIM; k++) o2 += sh[k] * W2[k * NCLASS + t];
        out[c * NCLASS + t] = o2;
    }
}

// ---------------- launch ----------------
extern "C" void kernel_launch(void* const* d_in, const int* in_sizes, int n_in,
                              void* d_out, int out_size)
{
    const float* edge_attr = (const float*)d_in[0];
    const int*   edge_index= (const int*)  d_in[1];
    const int*   batch     = (const int*)  d_in[2];
    const float* node_emb  = (const float*)d_in[3];
    const float* edge_W    = (const float*)d_in[4];
    const float* edge_b    = (const float*)d_in[5];
    const float* mlp_W1    = (const float*)d_in[6];
    const float* mlp_b1    = (const float*)d_in[7];
    const float* bn1_g     = (const float*)d_in[8];
    const float* bn1_b     = (const float*)d_in[9];
    const float* bn1_m     = (const float*)d_in[10];
    const float* bn1_v     = (const float*)d_in[11];
    const float* mlp_W2    = (const float*)d_in[12];
    const float* mlp_b2    = (const float*)d_in[13];
    const float* bn2_g     = (const float*)d_in[14];
    const float* bn2_b     = (const float*)d_in[15];
    const float* bn2_m     = (const float*)d_in[16];
    const float* bn2_v     = (const float*)d_in[17];
    const float* head_W1   = (const float*)d_in[18];
    const float* head_b1   = (const float*)d_in[19];
    const float* head_W2   = (const float*)d_in[20];
    const float* head_b2   = (const float*)d_in[21];
    float* out = (float*)d_out;

    cudaFuncSetAttribute(k_mlp_fused, cudaFuncAttributeMaxDynamicSharedMemorySize, FUSED_SMEM);

    float *px;
    __nv_bfloat16 *pwh, *pwl, *pah, *pal;
    cudaGetSymbolAddress((void**)&px,  g_x);
    cudaGetSymbolAddress((void**)&pwh, g_Wh);
    cudaGetSymbolAddress((void**)&pwl, g_Wl);
    cudaGetSymbolAddress((void**)&pah, g_Ah);
    cudaGetSymbolAddress((void**)&pal, g_Al);

    // prep_w also zeroes g_deg / g_flag / g_pool / g_ctr (runs first, same stream)
    k_prep_w<<<(10 * 16384 + 255) / 256, 256>>>(mlp_W1, mlp_W2);
    k_hist<<<(N_EDGES + 255) / 256, 256>>>(edge_index);
    k_scan_lb<<<SCAN_BLOCKS, 256>>>();
    k_scatter_idx<<<(N_EDGES + 255) / 256, 256>>>(edge_index);

    const int TC_GRID = 148;
    const int EDGE_GRID = 148 * 8;
    for (int l = 0; l < LAYERS; l++) {
        if (l == 0)
            k_edge_l0<<<EDGE_GRID, 256>>>(edge_index, edge_attr, node_emb, edge_W, edge_b);
        else
            k_edge_csr<<<EDGE_GRID, 256>>>(edge_W + l * EDIM * DIM, edge_b + l * DIM, l);
        int m1 = l * 2, m2 = l * 2 + 1;
        k_mlp_fused<<<TC_GRID, 256, FUSED_SMEM>>>(
            pah, pal, px,
            batch, (l == LAYERS - 1) ? 1 : 0,
            pwh + m1 * 16384, pwl + m1 * 16384,
            pwh + m2 * 16384, pwl + m2 * 16384,
            mlp_b1 + l * DIM, bn1_g + l * DIM, bn1_b + l * DIM, bn1_m + l * DIM, bn1_v + l * DIM,
            mlp_b2 + l * DIM, bn2_g + l * DIM, bn2_b + l * DIM, bn2_m + l * DIM, bn2_v + l * DIM);
    }

    k_head<<<N_GRAPH, DIM>>>(batch, head_W1, head_b1, head_W2, head_b2, out);
}